// round 7
// baseline (speedup 1.0000x reference)
#include <cuda_runtime.h>
#include <cuda_bf16.h>
#include <math.h>
#include <stdint.h>

#define SEQ 2048
#define DM 1024
#define NH 16
#define NKV 4
#define HDIM 64
#define NE 8
#define NI 3584
#define QKVN 1536
#define NSLOTS (2*SEQ)

typedef __nv_bfloat16 bf16;

// ---------------- scratch (device globals; no allocations) ----------------
__device__ bf16  g_wqkv_bf[QKVN*DM];
__device__ bf16  g_wo_bf[DM*DM];
__device__ bf16  g_w1_bf[(size_t)NE*NI*DM];
__device__ bf16  g_w3_bf[(size_t)NE*NI*DM];
__device__ bf16  g_w2_bf[(size_t)NE*DM*NI];
__device__ bf16  g_hn_bf[SEQ*DM];
__device__ float g_qkv[SEQ*QKVN];
__device__ float g_q[NH*SEQ*HDIM];
__device__ float g_k[NKV*SEQ*HDIM];
__device__ float g_v[NKV*SEQ*HDIM];
__device__ bf16  g_y_bf[SEQ*DM];
__device__ float g_h[SEQ*DM];
__device__ float g_hf[SEQ*DM];
__device__ bf16  g_hf_bf[SEQ*DM];
__device__ int   g_cnt[NE];
__device__ int   g_slot[NE*SEQ];
__device__ float g_wslot[NSLOTS];
__device__ bf16  g_gb[(size_t)NSLOTS*NI];
__device__ float g_os[(size_t)NSLOTS*DM];

// ---------------- helpers ---------------------------------------------------
__device__ __forceinline__ uint32_t f2tf32(float f) {
    uint32_t r;
    asm("cvt.rna.tf32.f32 %0, %1;" : "=r"(r) : "f"(f));
    return r;
}
__device__ __forceinline__ void mma_tf32(float c[4],
    uint32_t a0, uint32_t a1, uint32_t a2, uint32_t a3,
    uint32_t b0, uint32_t b1)
{
    asm volatile(
        "mma.sync.aligned.m16n8k8.row.col.f32.tf32.tf32.f32 "
        "{%0,%1,%2,%3}, {%4,%5,%6,%7}, {%8,%9}, {%0,%1,%2,%3};"
        : "+f"(c[0]), "+f"(c[1]), "+f"(c[2]), "+f"(c[3])
        : "r"(a0), "r"(a1), "r"(a2), "r"(a3), "r"(b0), "r"(b1));
}
__device__ __forceinline__ void mma_bf16(float c[4],
    uint32_t a0, uint32_t a1, uint32_t a2, uint32_t a3,
    uint32_t b0, uint32_t b1)
{
    asm volatile(
        "mma.sync.aligned.m16n8k16.row.col.f32.bf16.bf16.f32 "
        "{%0,%1,%2,%3}, {%4,%5,%6,%7}, {%8,%9}, {%0,%1,%2,%3};"
        : "+f"(c[0]), "+f"(c[1]), "+f"(c[2]), "+f"(c[3])
        : "r"(a0), "r"(a1), "r"(a2), "r"(a3), "r"(b0), "r"(b1));
}
__device__ __forceinline__ void ldsm4(uint32_t r[4], uint32_t addr) {
    asm volatile("ldmatrix.sync.aligned.m8n8.x4.shared.b16 {%0,%1,%2,%3}, [%4];"
                 : "=r"(r[0]), "=r"(r[1]), "=r"(r[2]), "=r"(r[3]) : "r"(addr));
}
__device__ __forceinline__ void cpa(uint32_t dst, const void* src, int sz) {
    asm volatile("cp.async.cg.shared.global [%0], [%1], 16, %2;"
                 :: "r"(dst), "l"(src), "r"(sz));
}
// wait for chunk c when chunks up to min(c+3,CC)-1 have been committed
__device__ __forceinline__ void wait_for(int c, int CC) {
    int rem = CC - c - 1;
    if (rem >= 2)      asm volatile("cp.async.wait_group 2;" ::: "memory");
    else if (rem == 1) asm volatile("cp.async.wait_group 1;" ::: "memory");
    else               asm volatile("cp.async.wait_group 0;" ::: "memory");
}

// ---------------- fp32 -> bf16 convert --------------------------------------
__global__ void f2bf_kernel(const float4* __restrict__ s, uint2* __restrict__ d, int n4)
{
    int i = blockIdx.x * blockDim.x + threadIdx.x;
    if (i >= n4) return;
    float4 v = s[i];
    __nv_bfloat162 lo = __floats2bfloat162_rn(v.x, v.y);
    __nv_bfloat162 hi = __floats2bfloat162_rn(v.z, v.w);
    uint2 o;
    o.x = *(uint32_t*)&lo;
    o.y = *(uint32_t*)&hi;
    d[i] = o;
}

// ---------------- rmsnorm (bf16 out + optional fp32 out) -------------------
__global__ __launch_bounds__(256) void rmsnorm_kernel(
    const float* __restrict__ x, const float* __restrict__ w,
    bf16* __restrict__ obf, float* __restrict__ ofp)
{
    int row = blockIdx.x;
    int tid = threadIdx.x;
    const float4* xr = (const float4*)(x + (size_t)row*DM);
    float4 v = xr[tid];
    float ss = v.x*v.x + v.y*v.y + v.z*v.z + v.w*v.w;
    __shared__ float red[8];
    #pragma unroll
    for (int ofs = 16; ofs > 0; ofs >>= 1) ss += __shfl_down_sync(0xffffffffu, ss, ofs);
    if ((tid & 31) == 0) red[tid >> 5] = ss;
    __syncthreads();
    __shared__ float sr;
    if (tid == 0) {
        float t = 0.f;
        #pragma unroll
        for (int i = 0; i < 8; i++) t += red[i];
        sr = rsqrtf(t / (float)DM + 1e-5f);
    }
    __syncthreads();
    float r = sr;
    float4 wv = ((const float4*)w)[tid];
    float4 o;
    o.x = v.x*r*wv.x; o.y = v.y*r*wv.y; o.z = v.z*r*wv.z; o.w = v.w*r*wv.w;
    __nv_bfloat162 lo = __floats2bfloat162_rn(o.x, o.y);
    __nv_bfloat162 hi = __floats2bfloat162_rn(o.z, o.w);
    uint2 ob; ob.x = *(uint32_t*)&lo; ob.y = *(uint32_t*)&hi;
    *(uint2*)(obf + (size_t)row*DM + tid*4) = ob;
    if (ofp) ((float4*)(ofp + (size_t)row*DM))[tid] = o;
}

// ---------------- bf16 HMMA GEMM: C[M,N] = A @ B^T (+resid) ----------------
// 128x128x64 tiles, 256 threads (8 warps, 2x4), 4-stage cp.async pipeline,
// ONE __syncthreads per chunk (4-stage: buffer re-written at c was last read
// at c-2; two barriers in between guarantee safety).
#define GSTG 16384
template<bool GATHER>
__global__ __launch_bounds__(256) void gemm_bf(
    const bf16* __restrict__ A, const bf16* __restrict__ B,
    const float* __restrict__ resid, float* __restrict__ C,
    int M, int N, int K, int shiftA)
{
    extern __shared__ char smem[];
    const int* sl = nullptr;
    if (GATHER) {
        int e = blockIdx.z;
        M = g_cnt[e];
        if ((int)blockIdx.y * 128 >= M) return;
        sl = g_slot + e * SEQ;
        B += (size_t)e * N * K;
    }
    int m0 = blockIdx.y * 128, n0 = blockIdx.x * 128;
    int tid = threadIdx.x, warp = tid >> 5, lane = tid & 31;
    int wm = (warp >> 2) * 64, wn = (warp & 3) * 32;
    uint32_t sbase = (uint32_t)__cvta_generic_to_shared(smem);
    uint32_t aoff[4], boff[4];
    #pragma unroll
    for (int s = 0; s < 4; s++) {
        aoff[s] = sbase + s*GSTG;
        boff[s] = sbase + 4*GSTG + s*GSTG;
    }

    int lrow = tid >> 1;
    int lsg  = (tid & 1) * 4;
    const bf16* Arow; int szA = 16;
    if (GATHER) {
        int gm = m0 + lrow;
        if (gm < M) Arow = A + (size_t)(sl[gm] >> shiftA) * K;
        else { Arow = A; szA = 0; }
    } else {
        Arow = A + (size_t)(m0 + lrow) * K;
    }
    const bf16* Brow = B + (size_t)(n0 + lrow) * K;
    uint32_t dsw = (uint32_t)lrow * 128u;
    int rxor = lrow & 7;

    float acc[4][4][4];
    #pragma unroll
    for (int i = 0; i < 4; i++)
        #pragma unroll
        for (int j = 0; j < 4; j++)
            #pragma unroll
            for (int q = 0; q < 4; q++) acc[i][j][q] = 0.f;

    int CC = K / 64;
    auto loadChunk = [&](int c) {
        int s = c & 3;
        const char* pa = (const char*)(Arow + c*64);
        const char* pb = (const char*)(Brow + c*64);
        #pragma unroll
        for (int i = 0; i < 4; i++) {
            int seg = lsg + i;
            uint32_t o = dsw + (uint32_t)((seg ^ rxor) * 16);
            cpa(aoff[s] + o, pa + seg*16, szA);
            cpa(boff[s] + o, pb + seg*16, 16);
        }
        asm volatile("cp.async.commit_group;" ::: "memory");
    };
    loadChunk(0);
    loadChunk(1);
    loadChunk(2);

    int lt = lane >> 3;
    int rl = lane & 7;
    int th = (lt & 1) * 8;
    int ts = lane >> 4;

    for (int c = 0; c < CC; c++) {
        wait_for(c, CC);
        __syncthreads();
        if (c + 3 < CC) loadChunk(c + 3);

        uint32_t Ab = aoff[c & 3], Bb = boff[c & 3];
        #pragma unroll
        for (int kk = 0; kk < 4; kk++) {
            uint32_t af[4][4], bf[2][4];
            #pragma unroll
            for (int i = 0; i < 4; i++) {
                int row = wm + i*16 + th + rl;
                int seg = 2*kk + ts;
                ldsm4(af[i], Ab + row*128 + ((seg ^ (row & 7)) << 4));
            }
            #pragma unroll
            for (int j = 0; j < 2; j++) {
                int nr = wn + j*16 + th + rl;
                int seg = 2*kk + ts;
                ldsm4(bf[j], Bb + nr*128 + ((seg ^ (nr & 7)) << 4));
            }
            #pragma unroll
            for (int i = 0; i < 4; i++)
                #pragma unroll
                for (int jn = 0; jn < 4; jn++) {
                    int jj = jn >> 1, hi = jn & 1;
                    mma_bf16(acc[i][jn], af[i][0], af[i][1], af[i][2], af[i][3],
                             bf[jj][hi], bf[jj][hi+2]);
                }
        }
    }

    int g = lane >> 2, tg = lane & 3;
    #pragma unroll
    for (int i = 0; i < 4; i++) {
        int r0 = m0 + wm + i*16 + g;
        int r1 = r0 + 8;
        bool v0, v1;
        int row0, row1;
        if (GATHER) {
            v0 = r0 < M; v1 = r1 < M;
            row0 = v0 ? sl[r0] : 0;
            row1 = v1 ? sl[r1] : 0;
        } else {
            v0 = v1 = true; row0 = r0; row1 = r1;
        }
        #pragma unroll
        for (int j = 0; j < 4; j++) {
            int c0 = n0 + wn + j*8 + tg*2;
            if (v0) {
                float2 v; v.x = acc[i][j][0]; v.y = acc[i][j][1];
                if (resid) {
                    v.x += resid[(size_t)row0*N + c0];
                    v.y += resid[(size_t)row0*N + c0 + 1];
                }
                *(float2*)(C + (size_t)row0*N + c0) = v;
            }
            if (v1) {
                float2 v; v.x = acc[i][j][2]; v.y = acc[i][j][3];
                if (resid) {
                    v.x += resid[(size_t)row1*N + c0];
                    v.y += resid[(size_t)row1*N + c0 + 1];
                }
                *(float2*)(C + (size_t)row1*N + c0) = v;
            }
        }
    }
}

// ---------------- fused MoE w1/w3 GEMM + silu*mul (bf16 out) ---------------
__global__ __launch_bounds__(256) void gemm_w13(
    const bf16* __restrict__ A, const bf16* __restrict__ B1,
    const bf16* __restrict__ B3)
{
    extern __shared__ char smem[];
    int e = blockIdx.z;
    int M = g_cnt[e];
    if ((int)blockIdx.y * 128 >= M) return;
    const int* sl = g_slot + e * SEQ;
    B1 += (size_t)e * NI * DM;
    B3 += (size_t)e * NI * DM;

    int m0 = blockIdx.y * 128, n0 = blockIdx.x * 128;
    int tid = threadIdx.x, warp = tid >> 5, lane = tid & 31;
    int wm = (warp >> 2) * 64, wn = (warp & 3) * 32;
    uint32_t sbase = (uint32_t)__cvta_generic_to_shared(smem);
    uint32_t aoff[4], b1off[4], b3off[4];
    #pragma unroll
    for (int s = 0; s < 4; s++) {
        aoff[s]  = sbase + s*GSTG;
        b1off[s] = sbase + 4*GSTG + s*GSTG;
        b3off[s] = sbase + 8*GSTG + s*GSTG;
    }

    int lrow = tid >> 1;
    int lsg  = (tid & 1) * 4;
    const bf16* Arow; int szA = 16;
    {
        int gm = m0 + lrow;
        if (gm < M) Arow = A + (size_t)(sl[gm] >> 1) * DM;
        else { Arow = A; szA = 0; }
    }
    const bf16* B1row = B1 + (size_t)(n0 + lrow) * DM;
    const bf16* B3row = B3 + (size_t)(n0 + lrow) * DM;
    uint32_t dsw = (uint32_t)lrow * 128u;
    int rxor = lrow & 7;

    float ac1[4][4][4], ac3[4][4][4];
    #pragma unroll
    for (int i = 0; i < 4; i++)
        #pragma unroll
        for (int j = 0; j < 4; j++)
            #pragma unroll
            for (int q = 0; q < 4; q++) { ac1[i][j][q] = 0.f; ac3[i][j][q] = 0.f; }

    const int CC = DM / 64;
    auto loadChunk = [&](int c) {
        int s = c & 3;
        const char* pa  = (const char*)(Arow  + c*64);
        const char* pb1 = (const char*)(B1row + c*64);
        const char* pb3 = (const char*)(B3row + c*64);
        #pragma unroll
        for (int i = 0; i < 4; i++) {
            int seg = lsg + i;
            uint32_t o = dsw + (uint32_t)((seg ^ rxor) * 16);
            cpa(aoff[s]  + o, pa  + seg*16, szA);
            cpa(b1off[s] + o, pb1 + seg*16, 16);
            cpa(b3off[s] + o, pb3 + seg*16, 16);
        }
        asm volatile("cp.async.commit_group;" ::: "memory");
    };
    loadChunk(0);
    loadChunk(1);
    loadChunk(2);

    int lt = lane >> 3, rl = lane & 7;
    int th = (lt & 1) * 8;
    int ts = lane >> 4;

    for (int c = 0; c < CC; c++) {
        wait_for(c, CC);
        __syncthreads();
        if (c + 3 < CC) loadChunk(c + 3);

        uint32_t Ab = aoff[c & 3], B1b = b1off[c & 3], B3b = b3off[c & 3];
        #pragma unroll
        for (int kk = 0; kk < 4; kk++) {
            uint32_t af[4][4], f1[2][4], f3[2][4];
            #pragma unroll
            for (int i = 0; i < 4; i++) {
                int row = wm + i*16 + th + rl;
                int seg = 2*kk + ts;
                ldsm4(af[i], Ab + row*128 + ((seg ^ (row & 7)) << 4));
            }
            #pragma unroll
            for (int j = 0; j < 2; j++) {
                int nr = wn + j*16 + th + rl;
                int seg = 2*kk + ts;
                ldsm4(f1[j], B1b + nr*128 + ((seg ^ (nr & 7)) << 4));
                ldsm4(f3[j], B3b + nr*128 + ((seg ^ (nr & 7)) << 4));
            }
            #pragma unroll
            for (int i = 0; i < 4; i++)
                #pragma unroll
                for (int jn = 0; jn < 4; jn++) {
                    int jj = jn >> 1, hi = jn & 1;
                    mma_bf16(ac1[i][jn], af[i][0], af[i][1], af[i][2], af[i][3],
                             f1[jj][hi], f1[jj][hi+2]);
                    mma_bf16(ac3[i][jn], af[i][0], af[i][1], af[i][2], af[i][3],
                             f3[jj][hi], f3[jj][hi+2]);
                }
        }
    }

    int g = lane >> 2, tg = lane & 3;
    #pragma unroll
    for (int i = 0; i < 4; i++) {
        int r0 = m0 + wm + i*16 + g;
        int r1 = r0 + 8;
        bool v0 = r0 < M, v1 = r1 < M;
        int row0 = v0 ? sl[r0] : 0;
        int row1 = v1 ? sl[r1] : 0;
        #pragma unroll
        for (int j = 0; j < 4; j++) {
            int c0 = n0 + wn + j*8 + tg*2;
            if (v0) {
                float a0 = ac1[i][j][0], a1 = ac1[i][j][1];
                float u0 = a0 / (1.f + __expf(-a0)) * ac3[i][j][0];
                float u1 = a1 / (1.f + __expf(-a1)) * ac3[i][j][1];
                *(__nv_bfloat162*)(g_gb + (size_t)row0*NI + c0) = __floats2bfloat162_rn(u0, u1);
            }
            if (v1) {
                float a0 = ac1[i][j][2], a1 = ac1[i][j][3];
                float u0 = a0 / (1.f + __expf(-a0)) * ac3[i][j][2];
                float u1 = a1 / (1.f + __expf(-a1)) * ac3[i][j][3];
                *(__nv_bfloat162*)(g_gb + (size_t)row1*NI + c0) = __floats2bfloat162_rn(u0, u1);
            }
        }
    }
}

// ---------------- RoPE + QKV split (tf32 pre-rounded, Q pre-scaled) --------
__global__ void rope_split_kernel(const float* __restrict__ freqs)
{
    int idx = blockIdx.x * blockDim.x + threadIdx.x;
    if (idx >= SEQ * (QKVN/2)) return;
    int t = idx / (QKVN/2);
    int col = (idx % (QKVN/2)) * 2;
    float x0 = g_qkv[(size_t)t*QKVN + col];
    float x1 = g_qkv[(size_t)t*QKVN + col + 1];
    if (col < DM) {
        int h = col >> 6, d = col & 63, p = d >> 1;
        float cs = freqs[((size_t)t*32 + p)*2 + 0];
        float sn = freqs[((size_t)t*32 + p)*2 + 1];
        float o0 = (x0*cs - x1*sn) * 0.125f;
        float o1 = (x1*cs + x0*sn) * 0.125f;
        size_t base = ((size_t)h*SEQ + t)*HDIM + d;
        g_q[base]   = __uint_as_float(f2tf32(o0));
        g_q[base+1] = __uint_as_float(f2tf32(o1));
    } else if (col < DM + NKV*HDIM) {
        int c = col - DM;
        int kh = c >> 6, d = c & 63, p = d >> 1;
        float cs = freqs[((size_t)t*32 + p)*2 + 0];
        float sn = freqs[((size_t)t*32 + p)*2 + 1];
        float o0 = x0*cs - x1*sn;
        float o1 = x1*cs + x0*sn;
        size_t base = ((size_t)kh*SEQ + t)*HDIM + d;
        g_k[base]   = __uint_as_float(f2tf32(o0));
        g_k[base+1] = __uint_as_float(f2tf32(o1));
    } else {
        int c = col - DM - NKV*HDIM;
        int vh = c >> 6, d = c & 63;
        size_t base = ((size_t)vh*SEQ + t)*HDIM + d;
        g_v[base]   = __uint_as_float(f2tf32(x0));
        g_v[base+1] = __uint_as_float(f2tf32(x1));
    }
}

// ---------------- tf32 flash attention v3 (R5 structure + cp.async) --------
// 128 threads (4 warps), grid (32, NH). K/V double-buffered via cp.async;
// all inputs pre-rounded tf32 (staging = raw copy).
#define ASTR 68
#define ATILE (64*ASTR)
__global__ __launch_bounds__(128) void attn3_kernel()
{
    extern __shared__ float sm[];
    float* QP = sm + 4*ATILE;   // Q frags then P scratch

    int qt = blockIdx.x, h = blockIdx.y;
    int kvh = h >> 2;
    int tid = threadIdx.x, warp = tid >> 5, lane = tid & 31;
    int g = lane >> 2, tg = lane & 3;
    int wq = warp * 16;
    int q0 = qt * 64;
    uint32_t sbase = (uint32_t)__cvta_generic_to_shared(sm);

    // stage Q (pre-scaled + tf32-rounded): raw copy
    for (int i = tid; i < 64*16; i += 128) {
        int row = i >> 4, c4 = (i & 15) * 4;
        *(float4*)&QP[row*ASTR + c4] =
            *(const float4*)(g_q + ((size_t)h*SEQ + q0 + row)*HDIM + c4);
    }
    __syncthreads();
    uint32_t aq[8][4];
    #pragma unroll
    for (int kk = 0; kk < 8; kk++) {
        aq[kk][0] = __float_as_uint(QP[(wq+g)*ASTR + kk*8 + tg]);
        aq[kk][1] = __float_as_uint(QP[(wq+g+8)*ASTR + kk*8 + tg]);
        aq[kk][2] = __float_as_uint(QP[(wq+g)*ASTR + kk*8 + tg + 4]);
        aq[kk][3] = __float_as_uint(QP[(wq+g+8)*ASTR + kk*8 + tg + 4]);
    }

    float oc[8][4];
    #pragma unroll
    for (int j = 0; j < 8; j++)
        #pragma unroll
        for (int q = 0; q < 4; q++) oc[j][q] = 0.f;
    float mrow[2] = {-1e30f, -1e30f};
    float lrow[2] = {0.f, 0.f};

    // cp.async K/V staging: thread -> row tid>>1, 8 x 16B segs
    int srow = tid >> 1, ssg = (tid & 1) * 8;
    auto issue = [&](int kt) {
        int b = kt & 1;
        const float* kb = g_k + ((size_t)kvh*SEQ + kt*64 + srow)*HDIM;
        const float* vb = g_v + ((size_t)kvh*SEQ + kt*64 + srow)*HDIM;
        uint32_t kd = sbase + (uint32_t)(b*ATILE + srow*ASTR)*4u + (uint32_t)ssg*16u;
        uint32_t vd = sbase + (uint32_t)((2+b)*ATILE + srow*ASTR)*4u + (uint32_t)ssg*16u;
        #pragma unroll
        for (int i = 0; i < 8; i++) {
            cpa(kd + i*16, kb + (ssg + i)*4, 16);
            cpa(vd + i*16, vb + (ssg + i)*4, 16);
        }
        asm volatile("cp.async.commit_group;" ::: "memory");
    };
    issue(0);

    for (int kt = 0; kt <= qt; kt++) {
        __syncthreads();   // prior compute done before overwriting buffer kt-1
        if (kt < qt) {
            issue(kt + 1);
            asm volatile("cp.async.wait_group 1;" ::: "memory");
        } else {
            asm volatile("cp.async.wait_group 0;" ::: "memory");
        }
        __syncthreads();

        const float* Ks = sm + (kt & 1)*ATILE;
        const float* Vs = sm + (2 + (kt & 1))*ATILE;

        float sc[8][4];
        #pragma unroll
        for (int j = 0; j < 8; j++)
            #pragma unroll
            for (int q = 0; q < 4; q++) sc[j][q] = 0.f;
        #pragma unroll
        for (int kk = 0; kk < 8; kk++) {
            #pragma unroll
            for (int j = 0; j < 8; j++) {
                uint32_t b0 = __float_as_uint(Ks[(j*8+g)*ASTR + kk*8 + tg]);
                uint32_t b1 = __float_as_uint(Ks[(j*8+g)*ASTR + kk*8 + tg + 4]);
                mma_tf32(sc[j], aq[kk][0], aq[kk][1], aq[kk][2], aq[kk][3], b0, b1);
            }
        }

        if (kt == qt) {
            int r0g = q0 + wq + g, r1g = r0g + 8;
            #pragma unroll
            for (int j = 0; j < 8; j++) {
                int c0 = kt*64 + j*8 + tg*2;
                if (c0     > r0g) sc[j][0] = -1e30f;
                if (c0 + 1 > r0g) sc[j][1] = -1e30f;
                if (c0     > r1g) sc[j][2] = -1e30f;
                if (c0 + 1 > r1g) sc[j][3] = -1e30f;
            }
        }

        float mx0 = -1e30f, mx1 = -1e30f;
        #pragma unroll
        for (int j = 0; j < 8; j++) {
            mx0 = fmaxf(mx0, fmaxf(sc[j][0], sc[j][1]));
            mx1 = fmaxf(mx1, fmaxf(sc[j][2], sc[j][3]));
        }
        mx0 = fmaxf(mx0, __shfl_xor_sync(0xffffffffu, mx0, 1));
        mx0 = fmaxf(mx0, __shfl_xor_sync(0xffffffffu, mx0, 2));
        mx1 = fmaxf(mx1, __shfl_xor_sync(0xffffffffu, mx1, 1));
        mx1 = fmaxf(mx1, __shfl_xor_sync(0xffffffffu, mx1, 2));
        float mn0 = fmaxf(mrow[0], mx0), mn1 = fmaxf(mrow[1], mx1);
        float s0 = __expf(mrow[0] - mn0), s1 = __expf(mrow[1] - mn1);
        float ls0 = 0.f, ls1 = 0.f;
        #pragma unroll
        for (int j = 0; j < 8; j++) {
            sc[j][0] = __expf(sc[j][0] - mn0);
            sc[j][1] = __expf(sc[j][1] - mn0);
            sc[j][2] = __expf(sc[j][2] - mn1);
            sc[j][3] = __expf(sc[j][3] - mn1);
            ls0 += sc[j][0] + sc[j][1];
            ls1 += sc[j][2] + sc[j][3];
        }
        ls0 += __shfl_xor_sync(0xffffffffu, ls0, 1);
        ls0 += __shfl_xor_sync(0xffffffffu, ls0, 2);
        ls1 += __shfl_xor_sync(0xffffffffu, ls1, 1);
        ls1 += __shfl_xor_sync(0xffffffffu, ls1, 2);
        lrow[0] = lrow[0]*s0 + ls0;
        lrow[1] = lrow[1]*s1 + ls1;
        mrow[0] = mn0; mrow[1] = mn1;
        #pragma unroll
        for (int j = 0; j < 8; j++) {
            oc[j][0] *= s0; oc[j][1] *= s0;
            oc[j][2] *= s1; oc[j][3] *= s1;
        }

        // write P (tf32-rounded) to warp-private QP rows
        #pragma unroll
        for (int j = 0; j < 8; j++) {
            float2 p0, p1;
            p0.x = __uint_as_float(f2tf32(sc[j][0]));
            p0.y = __uint_as_float(f2tf32(sc[j][1]));
            p1.x = __uint_as_float(f2tf32(sc[j][2]));
            p1.y = __uint_as_float(f2tf32(sc[j][3]));
            *(float2*)&QP[(wq+g)*ASTR + j*8 + tg*2]   = p0;
            *(float2*)&QP[(wq+g+8)*ASTR + j*8 + tg*2] = p1;
        }
        __syncwarp();

        #pragma unroll
        for (int kk = 0; kk < 8; kk++) {
            uint32_t a0 = __float_as_uint(QP[(wq+g)*ASTR + kk*8 + tg]);
            uint32_t a1 = __float_as_uint(QP[(wq+g+8)*ASTR + kk*8 + tg]);
            uint32_t a2 = __float_as_uint(QP[(wq+g)*ASTR + kk*8 + tg + 4]);
            uint32_t a3 = __float_as_uint(QP[(wq+g+8)*ASTR + kk*8 + tg + 4]);
            #pragma unroll
            for (int j = 0; j < 8; j++) {
                uint32_t b0 = __float_as_uint(Vs[(kk*8+tg)*ASTR + j*8 + g]);
                uint32_t b1 = __float_as_uint(Vs[(kk*8+tg+4)*ASTR + j*8 + g]);
                mma_tf32(oc[j], a0, a1, a2, a3, b0, b1);
            }
        }
    }

    float inv0 = 1.f / lrow[0], inv1 = 1.f / lrow[1];
    #pragma unroll
    for (int j = 0; j < 8; j++) {
        int col = h*HDIM + j*8 + tg*2;
        __nv_bfloat162 b0 = __floats2bfloat162_rn(oc[j][0]*inv0, oc[j][1]*inv0);
        __nv_bfloat162 b1 = __floats2bfloat162_rn(oc[j][2]*inv1, oc[j][3]*inv1);
        *(__nv_bfloat162*)(g_y_bf + (size_t)(q0+wq+g)*DM + col)   = b0;
        *(__nv_bfloat162*)(g_y_bf + (size_t)(q0+wq+g+8)*DM + col) = b1;
    }
}

// ---------------- gating ----------------------------------------------------
__global__ __launch_bounds__(256) void gating_kernel(const float* __restrict__ gw)
{
    int t = blockIdx.x;
    int tid = threadIdx.x;
    int e = tid >> 5, lane = tid & 31;
    float s = 0.f;
    const float* hr = g_hf + (size_t)t*DM;
    const float* wr = gw + (size_t)e*DM;
    for (int d = lane; d < DM; d += 32) s += hr[d]*wr[d];
    #pragma unroll
    for (int ofs = 16; ofs > 0; ofs >>= 1) s += __shfl_down_sync(0xffffffffu, s, ofs);
    __shared__ float lg[NE];
    if (lane == 0) lg[e] = s;
    __syncthreads();
    if (tid == 0) {
        float mx = lg[0];
        #pragma unroll
        for (int i = 1; i < NE; i++) mx = fmaxf(mx, lg[i]);
        float p[NE]; float den = 0.f;
        #pragma unroll
        for (int i = 0; i < NE; i++) { p[i] = expf(lg[i]-mx); den += p[i]; }
        #pragma unroll
        for (int i = 0; i < NE; i++) p[i] /= den;
        int i1 = 0;
        #pragma unroll
        for (int i = 1; i < NE; i++) if (p[i] > p[i1]) i1 = i;
        int i2 = (i1 == 0) ? 1 : 0;
        #pragma unroll
        for (int i = 0; i < NE; i++) if (i != i1 && p[i] > p[i2]) i2 = i;
        float w1 = p[i1], w2 = p[i2];
        float sw2 = w1 + w2;
        w1 /= sw2; w2 /= sw2;
        int pos1 = atomicAdd(&g_cnt[i1], 1);
        g_slot[i1*SEQ + pos1] = 2*t;
        g_wslot[2*t] = w1;
        int pos2 = atomicAdd(&g_cnt[i2], 1);
        g_slot[i2*SEQ + pos2] = 2*t + 1;
        g_wslot[2*t+1] = w2;
    }
}

// ---------------- final combine ---------------------------------------------
__global__ __launch_bounds__(256) void combine_kernel(float* __restrict__ out)
{
    int t = blockIdx.x;
    int tid = threadIdx.x;
    float w0 = g_wslot[2*t], w1 = g_wslot[2*t+1];
    float4 hv = ((const float4*)(g_h + (size_t)t*DM))[tid];
    float4 a = ((const float4*)(g_os + (size_t)(2*t)*DM))[tid];
    float4 b = ((const float4*)(g_os + (size_t)(2*t+1)*DM))[tid];
    float4 o;
    o.x = hv.x + w0*a.x + w1*b.x;
    o.y = hv.y + w0*a.y + w1*b.y;
    o.z = hv.z + w0*a.z + w1*b.z;
    o.w = hv.w + w0*a.w + w1*b.w;
    ((float4*)(out + (size_t)t*DM))[tid] = o;
}

// ---------------- host launch ----------------------------------------------
#define GEMM_SMEM (8*GSTG)
#define W13_SMEM  (12*GSTG)
#define ATTN_SMEM (5*ATILE*(int)sizeof(float))

extern "C" void kernel_launch(void* const* d_in, const int* in_sizes, int n_in,
                              void* d_out, int out_size)
{
    const float* x      = (const float*)d_in[0];
    const float* wqkv   = (const float*)d_in[1];
    const float* wo     = (const float*)d_in[2];
    const float* gate_w = (const float*)d_in[3];
    const float* w1     = (const float*)d_in[4];
    const float* w2     = (const float*)d_in[5];
    const float* w3     = (const float*)d_in[6];
    const float* anw    = (const float*)d_in[7];
    const float* fnw    = (const float*)d_in[8];
    const float* freqs  = (const float*)d_in[9];
    float* out = (float*)d_out;

    bf16 *p_wqkv_bf, *p_wo_bf, *p_w1_bf, *p_w3_bf, *p_w2_bf;
    bf16 *p_hn_bf, *p_hf_bf, *p_y_bf, *p_gb;
    float *p_qkv, *p_h, *p_hf, *p_os;
    int *p_cnt;
    cudaGetSymbolAddress((void**)&p_wqkv_bf, g_wqkv_bf);
    cudaGetSymbolAddress((void**)&p_wo_bf,   g_wo_bf);
    cudaGetSymbolAddress((void**)&p_w1_bf,   g_w1_bf);
    cudaGetSymbolAddress((void**)&p_w3_bf,   g_w3_bf);
    cudaGetSymbolAddress((void**)&p_w2_bf,   g_w2_bf);
    cudaGetSymbolAddress((void**)&p_hn_bf,   g_hn_bf);
    cudaGetSymbolAddress((void**)&p_hf_bf,   g_hf_bf);
    cudaGetSymbolAddress((void**)&p_y_bf,    g_y_bf);
    cudaGetSymbolAddress((void**)&p_gb,      g_gb);
    cudaGetSymbolAddress((void**)&p_qkv,     g_qkv);
    cudaGetSymbolAddress((void**)&p_h,       g_h);
    cudaGetSymbolAddress((void**)&p_hf,      g_hf);
    cudaGetSymbolAddress((void**)&p_os,      g_os);
    cudaGetSymbolAddress((void**)&p_cnt,     g_cnt);

    static bool attr_set = false;
    if (!attr_set) {
        cudaFuncSetAttribute(attn3_kernel,
            cudaFuncAttributeMaxDynamicSharedMemorySize, ATTN_SMEM);
        cudaFuncSetAttribute(gemm_bf<false>,
            cudaFuncAttributeMaxDynamicSharedMemorySize, GEMM_SMEM);
        cudaFuncSetAttribute(gemm_bf<true>,
            cudaFuncAttributeMaxDynamicSharedMemorySize, GEMM_SMEM);
        cudaFuncSetAttribute(gemm_w13,
            cudaFuncAttributeMaxDynamicSharedMemorySize, W13_SMEM);
        attr_set = true;
    }

    // 0. convert weights fp32 -> bf16
    {
        int n4;
        n4 = QKVN*DM/4;
        f2bf_kernel<<<(n4+255)/256, 256>>>((const float4*)wqkv, (uint2*)p_wqkv_bf, n4);
        n4 = DM*DM/4;
        f2bf_kernel<<<(n4+255)/256, 256>>>((const float4*)wo, (uint2*)p_wo_bf, n4);
        n4 = (int)((size_t)NE*NI*DM/4);
        f2bf_kernel<<<(n4+255)/256, 256>>>((const float4*)w1, (uint2*)p_w1_bf, n4);
        f2bf_kernel<<<(n4+255)/256, 256>>>((const float4*)w3, (uint2*)p_w3_bf, n4);
        f2bf_kernel<<<(n4+255)/256, 256>>>((const float4*)w2, (uint2*)p_w2_bf, n4);
    }
    // 1. attn rmsnorm (bf16 only)
    rmsnorm_kernel<<<SEQ, 256>>>(x, anw, p_hn_bf, nullptr);
    // 2. qkv = hn @ wqkv^T (bf16 HMMA)
    gemm_bf<false><<<dim3(QKVN/128, SEQ/128), 256, GEMM_SMEM>>>(
        p_hn_bf, p_wqkv_bf, nullptr, p_qkv, SEQ, QKVN, DM, 0);
    // 3. rope + split (tf32 pre-round)
    {
        int total = SEQ * (QKVN/2);
        rope_split_kernel<<<(total + 255)/256, 256>>>(freqs);
    }
    // 4. attention v3
    attn3_kernel<<<dim3(SEQ/64, NH), 128, ATTN_SMEM>>>();
    // 5. h = x + y @ wo^T
    gemm_bf<false><<<dim3(DM/128, SEQ/128), 256, GEMM_SMEM>>>(
        p_y_bf, p_wo_bf, x, p_h, SEQ, DM, DM, 0);
    // 6. ffn rmsnorm (bf16 + fp32 for gating)
    rmsnorm_kernel<<<SEQ, 256>>>(p_h, fnw, p_hf_bf, p_hf);
    // 7. gating
    cudaMemsetAsync(p_cnt, 0, NE*sizeof(int), 0);
    gating_kernel<<<SEQ, 256>>>(gate_w);
    // 8. fused MoE w1/w3 + silu*mul -> g_gb (bf16)
    gemm_w13<<<dim3(NI/128, SEQ/128, NE), 256, W13_SMEM>>>(
        p_hf_bf, p_w1_bf, p_w3_bf);
    // 9. out_slot = g @ w2^T (bf16 HMMA, gathered)
    gemm_bf<true><<<dim3(DM/128, SEQ/128, NE), 256, GEMM_SMEM>>>(
        p_gb, p_w2_bf, nullptr, p_os, 0, DM, NI, 0);
    // 10. combine
    combine_kernel<<<SEQ, 256>>>(out);
}

// round 8
// speedup vs baseline: 1.1288x; 1.1288x over previous
#include <cuda_runtime.h>
#include <cuda_bf16.h>
#include <math.h>
#include <stdint.h>

#define SEQ 2048
#define DM 1024
#define NH 16
#define NKV 4
#define HDIM 64
#define NE 8
#define NI 3584
#define QKVN 1536
#define NSLOTS (2*SEQ)

typedef __nv_bfloat16 bf16;

// ---------------- scratch (device globals; no allocations) ----------------
__device__ bf16  g_wqkv_bf[QKVN*DM];
__device__ bf16  g_wo_bf[DM*DM];
__device__ bf16  g_w1_bf[(size_t)NE*NI*DM];
__device__ bf16  g_w3_bf[(size_t)NE*NI*DM];
__device__ bf16  g_w2_bf[(size_t)NE*DM*NI];
__device__ bf16  g_hn_bf[SEQ*DM];
__device__ float g_qkv[SEQ*QKVN];
__device__ float g_q[NH*SEQ*HDIM];
__device__ float g_k[NKV*SEQ*HDIM];
__device__ float g_v[NKV*SEQ*HDIM];
__device__ bf16  g_y_bf[SEQ*DM];
__device__ float g_h[SEQ*DM];
__device__ float g_hf[SEQ*DM];
__device__ bf16  g_hf_bf[SEQ*DM];
__device__ int   g_cnt[NE];
__device__ int   g_slot[NE*SEQ];
__device__ float g_wslot[NSLOTS];
__device__ bf16  g_gb[(size_t)NSLOTS*NI];
__device__ float g_os[(size_t)NSLOTS*DM];

// ---------------- helpers ---------------------------------------------------
__device__ __forceinline__ uint32_t f2tf32(float f) {
    uint32_t r;
    asm("cvt.rna.tf32.f32 %0, %1;" : "=r"(r) : "f"(f));
    return r;
}
__device__ __forceinline__ void mma_tf32(float c[4],
    uint32_t a0, uint32_t a1, uint32_t a2, uint32_t a3,
    uint32_t b0, uint32_t b1)
{
    asm volatile(
        "mma.sync.aligned.m16n8k8.row.col.f32.tf32.tf32.f32 "
        "{%0,%1,%2,%3}, {%4,%5,%6,%7}, {%8,%9}, {%0,%1,%2,%3};"
        : "+f"(c[0]), "+f"(c[1]), "+f"(c[2]), "+f"(c[3])
        : "r"(a0), "r"(a1), "r"(a2), "r"(a3), "r"(b0), "r"(b1));
}
__device__ __forceinline__ void mma_bf16(float c[4],
    uint32_t a0, uint32_t a1, uint32_t a2, uint32_t a3,
    uint32_t b0, uint32_t b1)
{
    asm volatile(
        "mma.sync.aligned.m16n8k16.row.col.f32.bf16.bf16.f32 "
        "{%0,%1,%2,%3}, {%4,%5,%6,%7}, {%8,%9}, {%0,%1,%2,%3};"
        : "+f"(c[0]), "+f"(c[1]), "+f"(c[2]), "+f"(c[3])
        : "r"(a0), "r"(a1), "r"(a2), "r"(a3), "r"(b0), "r"(b1));
}
__device__ __forceinline__ void ldsm4(uint32_t r[4], uint32_t addr) {
    asm volatile("ldmatrix.sync.aligned.m8n8.x4.shared.b16 {%0,%1,%2,%3}, [%4];"
                 : "=r"(r[0]), "=r"(r[1]), "=r"(r[2]), "=r"(r[3]) : "r"(addr));
}
__device__ __forceinline__ void cpa(uint32_t dst, const void* src, int sz) {
    asm volatile("cp.async.cg.shared.global [%0], [%1], 16, %2;"
                 :: "r"(dst), "l"(src), "r"(sz));
}

// ---------------- fp32 -> bf16 convert --------------------------------------
__global__ void f2bf_kernel(const float4* __restrict__ s, uint2* __restrict__ d, int n4)
{
    int i = blockIdx.x * blockDim.x + threadIdx.x;
    if (i >= n4) return;
    float4 v = s[i];
    __nv_bfloat162 lo = __floats2bfloat162_rn(v.x, v.y);
    __nv_bfloat162 hi = __floats2bfloat162_rn(v.z, v.w);
    uint2 o;
    o.x = *(uint32_t*)&lo;
    o.y = *(uint32_t*)&hi;
    d[i] = o;
}

// ---------------- rmsnorm (bf16 out + optional fp32 out) -------------------
__global__ __launch_bounds__(256) void rmsnorm_kernel(
    const float* __restrict__ x, const float* __restrict__ w,
    bf16* __restrict__ obf, float* __restrict__ ofp)
{
    int row = blockIdx.x;
    int tid = threadIdx.x;
    const float4* xr = (const float4*)(x + (size_t)row*DM);
    float4 v = xr[tid];
    float ss = v.x*v.x + v.y*v.y + v.z*v.z + v.w*v.w;
    __shared__ float red[8];
    #pragma unroll
    for (int ofs = 16; ofs > 0; ofs >>= 1) ss += __shfl_down_sync(0xffffffffu, ss, ofs);
    if ((tid & 31) == 0) red[tid >> 5] = ss;
    __syncthreads();
    __shared__ float sr;
    if (tid == 0) {
        float t = 0.f;
        #pragma unroll
        for (int i = 0; i < 8; i++) t += red[i];
        sr = rsqrtf(t / (float)DM + 1e-5f);
    }
    __syncthreads();
    float r = sr;
    float4 wv = ((const float4*)w)[tid];
    float4 o;
    o.x = v.x*r*wv.x; o.y = v.y*r*wv.y; o.z = v.z*r*wv.z; o.w = v.w*r*wv.w;
    __nv_bfloat162 lo = __floats2bfloat162_rn(o.x, o.y);
    __nv_bfloat162 hi = __floats2bfloat162_rn(o.z, o.w);
    uint2 ob; ob.x = *(uint32_t*)&lo; ob.y = *(uint32_t*)&hi;
    *(uint2*)(obf + (size_t)row*DM + tid*4) = ob;
    if (ofp) ((float4*)(ofp + (size_t)row*DM))[tid] = o;
}

// ---------------- bf16 HMMA GEMM: C[M,N] = A @ B^T (+resid) ----------------
// 128x128x64 tiles, 256 threads (8 warps, 2x4), warp tile 64x32,
// mma m16n8k16 bf16, 3-stage cp.async, XOR-swizzled smem + ldmatrix.
// (96KB smem -> 2 CTAs/SM; do not deepen the pipeline.)
#define GSTG 16384
template<bool GATHER>
__global__ __launch_bounds__(256) void gemm_bf(
    const bf16* __restrict__ A, const bf16* __restrict__ B,
    const float* __restrict__ resid, float* __restrict__ C,
    int M, int N, int K, int shiftA)
{
    extern __shared__ char smem[];
    const int* sl = nullptr;
    if (GATHER) {
        int e = blockIdx.z;
        M = g_cnt[e];
        if ((int)blockIdx.y * 128 >= M) return;
        sl = g_slot + e * SEQ;
        B += (size_t)e * N * K;
    }
    int m0 = blockIdx.y * 128, n0 = blockIdx.x * 128;
    int tid = threadIdx.x, warp = tid >> 5, lane = tid & 31;
    int wm = (warp >> 2) * 64, wn = (warp & 3) * 32;
    uint32_t sbase = (uint32_t)__cvta_generic_to_shared(smem);
    uint32_t aoff[3], boff[3];
    #pragma unroll
    for (int s = 0; s < 3; s++) {
        aoff[s] = sbase + s*GSTG;
        boff[s] = sbase + 3*GSTG + s*GSTG;
    }

    int lrow = tid >> 1;
    int lsg  = (tid & 1) * 4;
    const bf16* Arow; int szA = 16;
    if (GATHER) {
        int gm = m0 + lrow;
        if (gm < M) Arow = A + (size_t)(sl[gm] >> shiftA) * K;
        else { Arow = A; szA = 0; }
    } else {
        Arow = A + (size_t)(m0 + lrow) * K;
    }
    const bf16* Brow = B + (size_t)(n0 + lrow) * K;
    uint32_t dsw = (uint32_t)lrow * 128u;
    int rxor = lrow & 7;

    float acc[4][4][4];
    #pragma unroll
    for (int i = 0; i < 4; i++)
        #pragma unroll
        for (int j = 0; j < 4; j++)
            #pragma unroll
            for (int q = 0; q < 4; q++) acc[i][j][q] = 0.f;

    int CC = K / 64;
    auto loadChunk = [&](int c) {
        int s = c % 3;
        const char* pa = (const char*)(Arow + c*64);
        const char* pb = (const char*)(Brow + c*64);
        #pragma unroll
        for (int i = 0; i < 4; i++) {
            int seg = lsg + i;
            uint32_t o = dsw + (uint32_t)((seg ^ rxor) * 16);
            cpa(aoff[s] + o, pa + seg*16, szA);
            cpa(boff[s] + o, pb + seg*16, 16);
        }
        asm volatile("cp.async.commit_group;" ::: "memory");
    };
    loadChunk(0);
    if (CC > 1) loadChunk(1);

    int lt = lane >> 3;
    int rl = lane & 7;
    int th = (lt & 1) * 8;
    int ts = lane >> 4;

    for (int c = 0; c < CC; c++) {
        if (c + 1 < CC) asm volatile("cp.async.wait_group 1;" ::: "memory");
        else            asm volatile("cp.async.wait_group 0;" ::: "memory");
        __syncthreads();
        if (c + 2 < CC) loadChunk(c + 2);

        uint32_t Ab = aoff[c % 3], Bb = boff[c % 3];
        #pragma unroll
        for (int kk = 0; kk < 4; kk++) {
            uint32_t af[4][4], bf[2][4];
            #pragma unroll
            for (int i = 0; i < 4; i++) {
                int row = wm + i*16 + th + rl;
                int seg = 2*kk + ts;
                ldsm4(af[i], Ab + row*128 + ((seg ^ (row & 7)) << 4));
            }
            #pragma unroll
            for (int j = 0; j < 2; j++) {
                int nr = wn + j*16 + th + rl;
                int seg = 2*kk + ts;
                ldsm4(bf[j], Bb + nr*128 + ((seg ^ (nr & 7)) << 4));
            }
            #pragma unroll
            for (int i = 0; i < 4; i++)
                #pragma unroll
                for (int jn = 0; jn < 4; jn++) {
                    int jj = jn >> 1, hi = jn & 1;
                    mma_bf16(acc[i][jn], af[i][0], af[i][1], af[i][2], af[i][3],
                             bf[jj][hi], bf[jj][hi+2]);
                }
        }
        __syncthreads();
    }

    int g = lane >> 2, tg = lane & 3;
    #pragma unroll
    for (int i = 0; i < 4; i++) {
        int r0 = m0 + wm + i*16 + g;
        int r1 = r0 + 8;
        bool v0, v1;
        int row0, row1;
        if (GATHER) {
            v0 = r0 < M; v1 = r1 < M;
            row0 = v0 ? sl[r0] : 0;
            row1 = v1 ? sl[r1] : 0;
        } else {
            v0 = v1 = true; row0 = r0; row1 = r1;
        }
        #pragma unroll
        for (int j = 0; j < 4; j++) {
            int c0 = n0 + wn + j*8 + tg*2;
            if (v0) {
                float2 v; v.x = acc[i][j][0]; v.y = acc[i][j][1];
                if (resid) {
                    v.x += resid[(size_t)row0*N + c0];
                    v.y += resid[(size_t)row0*N + c0 + 1];
                }
                *(float2*)(C + (size_t)row0*N + c0) = v;
            }
            if (v1) {
                float2 v; v.x = acc[i][j][2]; v.y = acc[i][j][3];
                if (resid) {
                    v.x += resid[(size_t)row1*N + c0];
                    v.y += resid[(size_t)row1*N + c0 + 1];
                }
                *(float2*)(C + (size_t)row1*N + c0) = v;
            }
        }
    }
}

// ---------------- fused MoE w1/w3 GEMM + silu*mul (bf16 out) ---------------
__global__ __launch_bounds__(256) void gemm_w13(
    const bf16* __restrict__ A, const bf16* __restrict__ B1,
    const bf16* __restrict__ B3)
{
    extern __shared__ char smem[];
    int e = blockIdx.z;
    int M = g_cnt[e];
    if ((int)blockIdx.y * 128 >= M) return;
    const int* sl = g_slot + e * SEQ;
    B1 += (size_t)e * NI * DM;
    B3 += (size_t)e * NI * DM;

    int m0 = blockIdx.y * 128, n0 = blockIdx.x * 128;
    int tid = threadIdx.x, warp = tid >> 5, lane = tid & 31;
    int wm = (warp >> 2) * 64, wn = (warp & 3) * 32;
    uint32_t sbase = (uint32_t)__cvta_generic_to_shared(smem);
    uint32_t aoff[3], b1off[3], b3off[3];
    #pragma unroll
    for (int s = 0; s < 3; s++) {
        aoff[s]  = sbase + s*GSTG;
        b1off[s] = sbase + 3*GSTG + s*GSTG;
        b3off[s] = sbase + 6*GSTG + s*GSTG;
    }

    int lrow = tid >> 1;
    int lsg  = (tid & 1) * 4;
    const bf16* Arow; int szA = 16;
    {
        int gm = m0 + lrow;
        if (gm < M) Arow = A + (size_t)(sl[gm] >> 1) * DM;
        else { Arow = A; szA = 0; }
    }
    const bf16* B1row = B1 + (size_t)(n0 + lrow) * DM;
    const bf16* B3row = B3 + (size_t)(n0 + lrow) * DM;
    uint32_t dsw = (uint32_t)lrow * 128u;
    int rxor = lrow & 7;

    float ac1[4][4][4], ac3[4][4][4];
    #pragma unroll
    for (int i = 0; i < 4; i++)
        #pragma unroll
        for (int j = 0; j < 4; j++)
            #pragma unroll
            for (int q = 0; q < 4; q++) { ac1[i][j][q] = 0.f; ac3[i][j][q] = 0.f; }

    const int CC = DM / 64;
    auto loadChunk = [&](int c) {
        int s = c % 3;
        const char* pa  = (const char*)(Arow  + c*64);
        const char* pb1 = (const char*)(B1row + c*64);
        const char* pb3 = (const char*)(B3row + c*64);
        #pragma unroll
        for (int i = 0; i < 4; i++) {
            int seg = lsg + i;
            uint32_t o = dsw + (uint32_t)((seg ^ rxor) * 16);
            cpa(aoff[s]  + o, pa  + seg*16, szA);
            cpa(b1off[s] + o, pb1 + seg*16, 16);
            cpa(b3off[s] + o, pb3 + seg*16, 16);
        }
        asm volatile("cp.async.commit_group;" ::: "memory");
    };
    loadChunk(0);
    loadChunk(1);

    int lt = lane >> 3, rl = lane & 7;
    int th = (lt & 1) * 8;
    int ts = lane >> 4;

    for (int c = 0; c < CC; c++) {
        if (c + 1 < CC) asm volatile("cp.async.wait_group 1;" ::: "memory");
        else            asm volatile("cp.async.wait_group 0;" ::: "memory");
        __syncthreads();
        if (c + 2 < CC) loadChunk(c + 2);

        uint32_t Ab = aoff[c % 3], B1b = b1off[c % 3], B3b = b3off[c % 3];
        #pragma unroll
        for (int kk = 0; kk < 4; kk++) {
            uint32_t af[4][4], f1[2][4], f3[2][4];
            #pragma unroll
            for (int i = 0; i < 4; i++) {
                int row = wm + i*16 + th + rl;
                int seg = 2*kk + ts;
                ldsm4(af[i], Ab + row*128 + ((seg ^ (row & 7)) << 4));
            }
            #pragma unroll
            for (int j = 0; j < 2; j++) {
                int nr = wn + j*16 + th + rl;
                int seg = 2*kk + ts;
                ldsm4(f1[j], B1b + nr*128 + ((seg ^ (nr & 7)) << 4));
                ldsm4(f3[j], B3b + nr*128 + ((seg ^ (nr & 7)) << 4));
            }
            #pragma unroll
            for (int i = 0; i < 4; i++)
                #pragma unroll
                for (int jn = 0; jn < 4; jn++) {
                    int jj = jn >> 1, hi = jn & 1;
                    mma_bf16(ac1[i][jn], af[i][0], af[i][1], af[i][2], af[i][3],
                             f1[jj][hi], f1[jj][hi+2]);
                    mma_bf16(ac3[i][jn], af[i][0], af[i][1], af[i][2], af[i][3],
                             f3[jj][hi], f3[jj][hi+2]);
                }
        }
        __syncthreads();
    }

    int g = lane >> 2, tg = lane & 3;
    #pragma unroll
    for (int i = 0; i < 4; i++) {
        int r0 = m0 + wm + i*16 + g;
        int r1 = r0 + 8;
        bool v0 = r0 < M, v1 = r1 < M;
        int row0 = v0 ? sl[r0] : 0;
        int row1 = v1 ? sl[r1] : 0;
        #pragma unroll
        for (int j = 0; j < 4; j++) {
            int c0 = n0 + wn + j*8 + tg*2;
            if (v0) {
                float a0 = ac1[i][j][0], a1 = ac1[i][j][1];
                float u0 = a0 / (1.f + __expf(-a0)) * ac3[i][j][0];
                float u1 = a1 / (1.f + __expf(-a1)) * ac3[i][j][1];
                *(__nv_bfloat162*)(g_gb + (size_t)row0*NI + c0) = __floats2bfloat162_rn(u0, u1);
            }
            if (v1) {
                float a0 = ac1[i][j][2], a1 = ac1[i][j][3];
                float u0 = a0 / (1.f + __expf(-a0)) * ac3[i][j][2];
                float u1 = a1 / (1.f + __expf(-a1)) * ac3[i][j][3];
                *(__nv_bfloat162*)(g_gb + (size_t)row1*NI + c0) = __floats2bfloat162_rn(u0, u1);
            }
        }
    }
}

// ---------------- RoPE + QKV split ----------------------------------------
__global__ void rope_split_kernel(const float* __restrict__ freqs)
{
    int idx = blockIdx.x * blockDim.x + threadIdx.x;
    if (idx >= SEQ * (QKVN/2)) return;
    int t = idx / (QKVN/2);
    int col = (idx % (QKVN/2)) * 2;
    float x0 = g_qkv[(size_t)t*QKVN + col];
    float x1 = g_qkv[(size_t)t*QKVN + col + 1];
    if (col < DM) {
        int h = col >> 6, d = col & 63, p = d >> 1;
        float cs = freqs[((size_t)t*32 + p)*2 + 0];
        float sn = freqs[((size_t)t*32 + p)*2 + 1];
        float o0 = x0*cs - x1*sn;
        float o1 = x1*cs + x0*sn;
        size_t base = ((size_t)h*SEQ + t)*HDIM + d;
        g_q[base] = o0; g_q[base+1] = o1;
    } else if (col < DM + NKV*HDIM) {
        int c = col - DM;
        int kh = c >> 6, d = c & 63, p = d >> 1;
        float cs = freqs[((size_t)t*32 + p)*2 + 0];
        float sn = freqs[((size_t)t*32 + p)*2 + 1];
        float o0 = x0*cs - x1*sn;
        float o1 = x1*cs + x0*sn;
        size_t base = ((size_t)kh*SEQ + t)*HDIM + d;
        g_k[base] = o0; g_k[base+1] = o1;
    } else {
        int c = col - DM - NKV*HDIM;
        int vh = c >> 6, d = c & 63;
        size_t base = ((size_t)vh*SEQ + t)*HDIM + d;
        g_v[base] = x0; g_v[base+1] = x1;
    }
}

// ---------------- TF32 tensor-core flash attention (causal, GQA) -----------
#define ASTR 68
__global__ __launch_bounds__(128) void attn_tf32_kernel()
{
    extern __shared__ float sm[];
    float* Ks = sm;
    float* Vs = sm + 64*ASTR;
    float* QP = sm + 2*64*ASTR;

    int qt = blockIdx.x, h = blockIdx.y;
    int kvh = h >> 2;
    int tid = threadIdx.x, warp = tid >> 5, lane = tid & 31;
    int g = lane >> 2, tg = lane & 3;
    int wq = warp * 16;
    int q0 = qt * 64;

    for (int i = tid; i < 64*16; i += 128) {
        int row = i >> 4, c4 = (i & 15) * 4;
        float4 v = *(const float4*)(g_q + ((size_t)h*SEQ + q0 + row)*HDIM + c4);
        QP[row*ASTR + c4 + 0] = __uint_as_float(f2tf32(v.x * 0.125f));
        QP[row*ASTR + c4 + 1] = __uint_as_float(f2tf32(v.y * 0.125f));
        QP[row*ASTR + c4 + 2] = __uint_as_float(f2tf32(v.z * 0.125f));
        QP[row*ASTR + c4 + 3] = __uint_as_float(f2tf32(v.w * 0.125f));
    }
    __syncthreads();
    uint32_t aq[8][4];
    #pragma unroll
    for (int kk = 0; kk < 8; kk++) {
        aq[kk][0] = __float_as_uint(QP[(wq+g)*ASTR + kk*8 + tg]);
        aq[kk][1] = __float_as_uint(QP[(wq+g+8)*ASTR + kk*8 + tg]);
        aq[kk][2] = __float_as_uint(QP[(wq+g)*ASTR + kk*8 + tg + 4]);
        aq[kk][3] = __float_as_uint(QP[(wq+g+8)*ASTR + kk*8 + tg + 4]);
    }
    __syncthreads();

    float oc[8][4];
    #pragma unroll
    for (int j = 0; j < 8; j++)
        #pragma unroll
        for (int q = 0; q < 4; q++) oc[j][q] = 0.f;
    float mrow[2] = {-1e30f, -1e30f};
    float lrow[2] = {0.f, 0.f};

    for (int kt = 0; kt <= qt; kt++) {
        for (int i = tid; i < 64*16; i += 128) {
            int row = i >> 4, c4 = (i & 15) * 4;
            size_t base = ((size_t)kvh*SEQ + kt*64 + row)*HDIM + c4;
            float4 kv = *(const float4*)(g_k + base);
            float4 vv = *(const float4*)(g_v + base);
            Ks[row*ASTR + c4 + 0] = __uint_as_float(f2tf32(kv.x));
            Ks[row*ASTR + c4 + 1] = __uint_as_float(f2tf32(kv.y));
            Ks[row*ASTR + c4 + 2] = __uint_as_float(f2tf32(kv.z));
            Ks[row*ASTR + c4 + 3] = __uint_as_float(f2tf32(kv.w));
            Vs[row*ASTR + c4 + 0] = __uint_as_float(f2tf32(vv.x));
            Vs[row*ASTR + c4 + 1] = __uint_as_float(f2tf32(vv.y));
            Vs[row*ASTR + c4 + 2] = __uint_as_float(f2tf32(vv.z));
            Vs[row*ASTR + c4 + 3] = __uint_as_float(f2tf32(vv.w));
        }
        __syncthreads();

        float sc[8][4];
        #pragma unroll
        for (int j = 0; j < 8; j++)
            #pragma unroll
            for (int q = 0; q < 4; q++) sc[j][q] = 0.f;
        #pragma unroll
        for (int kk = 0; kk < 8; kk++) {
            #pragma unroll
            for (int j = 0; j < 8; j++) {
                uint32_t b0 = __float_as_uint(Ks[(j*8+g)*ASTR + kk*8 + tg]);
                uint32_t b1 = __float_as_uint(Ks[(j*8+g)*ASTR + kk*8 + tg + 4]);
                mma_tf32(sc[j], aq[kk][0], aq[kk][1], aq[kk][2], aq[kk][3], b0, b1);
            }
        }

        if (kt == qt) {
            int r0g = q0 + wq + g, r1g = r0g + 8;
            #pragma unroll
            for (int j = 0; j < 8; j++) {
                int c0 = kt*64 + j*8 + tg*2;
                if (c0     > r0g) sc[j][0] = -1e30f;
                if (c0 + 1 > r0g) sc[j][1] = -1e30f;
                if (c0     > r1g) sc[j][2] = -1e30f;
                if (c0 + 1 > r1g) sc[j][3] = -1e30f;
            }
        }

        float mx0 = -1e30f, mx1 = -1e30f;
        #pragma unroll
        for (int j = 0; j < 8; j++) {
            mx0 = fmaxf(mx0, fmaxf(sc[j][0], sc[j][1]));
            mx1 = fmaxf(mx1, fmaxf(sc[j][2], sc[j][3]));
        }
        mx0 = fmaxf(mx0, __shfl_xor_sync(0xffffffffu, mx0, 1));
        mx0 = fmaxf(mx0, __shfl_xor_sync(0xffffffffu, mx0, 2));
        mx1 = fmaxf(mx1, __shfl_xor_sync(0xffffffffu, mx1, 1));
        mx1 = fmaxf(mx1, __shfl_xor_sync(0xffffffffu, mx1, 2));
        float mn0 = fmaxf(mrow[0], mx0), mn1 = fmaxf(mrow[1], mx1);
        float s0 = __expf(mrow[0] - mn0), s1 = __expf(mrow[1] - mn1);
        float ls0 = 0.f, ls1 = 0.f;
        #pragma unroll
        for (int j = 0; j < 8; j++) {
            sc[j][0] = __expf(sc[j][0] - mn0);
            sc[j][1] = __expf(sc[j][1] - mn0);
            sc[j][2] = __expf(sc[j][2] - mn1);
            sc[j][3] = __expf(sc[j][3] - mn1);
            ls0 += sc[j][0] + sc[j][1];
            ls1 += sc[j][2] + sc[j][3];
        }
        ls0 += __shfl_xor_sync(0xffffffffu, ls0, 1);
        ls0 += __shfl_xor_sync(0xffffffffu, ls0, 2);
        ls1 += __shfl_xor_sync(0xffffffffu, ls1, 1);
        ls1 += __shfl_xor_sync(0xffffffffu, ls1, 2);
        lrow[0] = lrow[0]*s0 + ls0;
        lrow[1] = lrow[1]*s1 + ls1;
        mrow[0] = mn0; mrow[1] = mn1;
        #pragma unroll
        for (int j = 0; j < 8; j++) {
            oc[j][0] *= s0; oc[j][1] *= s0;
            oc[j][2] *= s1; oc[j][3] *= s1;
        }

        #pragma unroll
        for (int j = 0; j < 8; j++) {
            float2 p0, p1;
            p0.x = __uint_as_float(f2tf32(sc[j][0]));
            p0.y = __uint_as_float(f2tf32(sc[j][1]));
            p1.x = __uint_as_float(f2tf32(sc[j][2]));
            p1.y = __uint_as_float(f2tf32(sc[j][3]));
            *(float2*)&QP[(wq+g)*ASTR + j*8 + tg*2]   = p0;
            *(float2*)&QP[(wq+g+8)*ASTR + j*8 + tg*2] = p1;
        }
        __syncwarp();

        #pragma unroll
        for (int kk = 0; kk < 8; kk++) {
            uint32_t a0 = __float_as_uint(QP[(wq+g)*ASTR + kk*8 + tg]);
            uint32_t a1 = __float_as_uint(QP[(wq+g+8)*ASTR + kk*8 + tg]);
            uint32_t a2 = __float_as_uint(QP[(wq+g)*ASTR + kk*8 + tg + 4]);
            uint32_t a3 = __float_as_uint(QP[(wq+g+8)*ASTR + kk*8 + tg + 4]);
            #pragma unroll
            for (int j = 0; j < 8; j++) {
                uint32_t b0 = __float_as_uint(Vs[(kk*8+tg)*ASTR + j*8 + g]);
                uint32_t b1 = __float_as_uint(Vs[(kk*8+tg+4)*ASTR + j*8 + g]);
                mma_tf32(oc[j], a0, a1, a2, a3, b0, b1);
            }
        }
        __syncthreads();
    }

    float inv0 = 1.f / lrow[0], inv1 = 1.f / lrow[1];
    #pragma unroll
    for (int j = 0; j < 8; j++) {
        int col = h*HDIM + j*8 + tg*2;
        __nv_bfloat162 b0 = __floats2bfloat162_rn(oc[j][0]*inv0, oc[j][1]*inv0);
        __nv_bfloat162 b1 = __floats2bfloat162_rn(oc[j][2]*inv1, oc[j][3]*inv1);
        *(__nv_bfloat162*)(g_y_bf + (size_t)(q0+wq+g)*DM + col)   = b0;
        *(__nv_bfloat162*)(g_y_bf + (size_t)(q0+wq+g+8)*DM + col) = b1;
    }
}

// ---------------- gating ----------------------------------------------------
__global__ __launch_bounds__(256) void gating_kernel(const float* __restrict__ gw)
{
    int t = blockIdx.x;
    int tid = threadIdx.x;
    int e = tid >> 5, lane = tid & 31;
    float s = 0.f;
    const float* hr = g_hf + (size_t)t*DM;
    const float* wr = gw + (size_t)e*DM;
    for (int d = lane; d < DM; d += 32) s += hr[d]*wr[d];
    #pragma unroll
    for (int ofs = 16; ofs > 0; ofs >>= 1) s += __shfl_down_sync(0xffffffffu, s, ofs);
    __shared__ float lg[NE];
    if (lane == 0) lg[e] = s;
    __syncthreads();
    if (tid == 0) {
        float mx = lg[0];
        #pragma unroll
        for (int i = 1; i < NE; i++) mx = fmaxf(mx, lg[i]);
        float p[NE]; float den = 0.f;
        #pragma unroll
        for (int i = 0; i < NE; i++) { p[i] = expf(lg[i]-mx); den += p[i]; }
        #pragma unroll
        for (int i = 0; i < NE; i++) p[i] /= den;
        int i1 = 0;
        #pragma unroll
        for (int i = 1; i < NE; i++) if (p[i] > p[i1]) i1 = i;
        int i2 = (i1 == 0) ? 1 : 0;
        #pragma unroll
        for (int i = 0; i < NE; i++) if (i != i1 && p[i] > p[i2]) i2 = i;
        float w1 = p[i1], w2 = p[i2];
        float sw2 = w1 + w2;
        w1 /= sw2; w2 /= sw2;
        int pos1 = atomicAdd(&g_cnt[i1], 1);
        g_slot[i1*SEQ + pos1] = 2*t;
        g_wslot[2*t] = w1;
        int pos2 = atomicAdd(&g_cnt[i2], 1);
        g_slot[i2*SEQ + pos2] = 2*t + 1;
        g_wslot[2*t+1] = w2;
    }
}

// ---------------- final combine ---------------------------------------------
__global__ __launch_bounds__(256) void combine_kernel(float* __restrict__ out)
{
    int t = blockIdx.x;
    int tid = threadIdx.x;
    float w0 = g_wslot[2*t], w1 = g_wslot[2*t+1];
    float4 hv = ((const float4*)(g_h + (size_t)t*DM))[tid];
    float4 a = ((const float4*)(g_os + (size_t)(2*t)*DM))[tid];
    float4 b = ((const float4*)(g_os + (size_t)(2*t+1)*DM))[tid];
    float4 o;
    o.x = hv.x + w0*a.x + w1*b.x;
    o.y = hv.y + w0*a.y + w1*b.y;
    o.z = hv.z + w0*a.z + w1*b.z;
    o.w = hv.w + w0*a.w + w1*b.w;
    ((float4*)(out + (size_t)t*DM))[tid] = o;
}

// ---------------- host launch ----------------------------------------------
#define GEMM_SMEM (6*GSTG)
#define W13_SMEM  (9*GSTG)
#define ATTN_SMEM (3*64*ASTR*(int)sizeof(float))

extern "C" void kernel_launch(void* const* d_in, const int* in_sizes, int n_in,
                              void* d_out, int out_size)
{
    const float* x      = (const float*)d_in[0];
    const float* wqkv   = (const float*)d_in[1];
    const float* wo     = (const float*)d_in[2];
    const float* gate_w = (const float*)d_in[3];
    const float* w1     = (const float*)d_in[4];
    const float* w2     = (const float*)d_in[5];
    const float* w3     = (const float*)d_in[6];
    const float* anw    = (const float*)d_in[7];
    const float* fnw    = (const float*)d_in[8];
    const float* freqs  = (const float*)d_in[9];
    float* out = (float*)d_out;

    bf16 *p_wqkv_bf, *p_wo_bf, *p_w1_bf, *p_w3_bf, *p_w2_bf;
    bf16 *p_hn_bf, *p_hf_bf, *p_y_bf, *p_gb;
    float *p_qkv, *p_h, *p_hf, *p_os;
    int *p_cnt;
    cudaGetSymbolAddress((void**)&p_wqkv_bf, g_wqkv_bf);
    cudaGetSymbolAddress((void**)&p_wo_bf,   g_wo_bf);
    cudaGetSymbolAddress((void**)&p_w1_bf,   g_w1_bf);
    cudaGetSymbolAddress((void**)&p_w3_bf,   g_w3_bf);
    cudaGetSymbolAddress((void**)&p_w2_bf,   g_w2_bf);
    cudaGetSymbolAddress((void**)&p_hn_bf,   g_hn_bf);
    cudaGetSymbolAddress((void**)&p_hf_bf,   g_hf_bf);
    cudaGetSymbolAddress((void**)&p_y_bf,    g_y_bf);
    cudaGetSymbolAddress((void**)&p_gb,      g_gb);
    cudaGetSymbolAddress((void**)&p_qkv,     g_qkv);
    cudaGetSymbolAddress((void**)&p_h,       g_h);
    cudaGetSymbolAddress((void**)&p_hf,      g_hf);
    cudaGetSymbolAddress((void**)&p_os,      g_os);
    cudaGetSymbolAddress((void**)&p_cnt,     g_cnt);

    static cudaStream_t s2 = nullptr;
    static cudaEvent_t ev0 = nullptr, ev1 = nullptr;
    static bool attr_set = false;
    if (!attr_set) {
        cudaFuncSetAttribute(attn_tf32_kernel,
            cudaFuncAttributeMaxDynamicSharedMemorySize, ATTN_SMEM);
        cudaFuncSetAttribute(gemm_bf<false>,
            cudaFuncAttributeMaxDynamicSharedMemorySize, GEMM_SMEM);
        cudaFuncSetAttribute(gemm_bf<true>,
            cudaFuncAttributeMaxDynamicSharedMemorySize, GEMM_SMEM);
        cudaFuncSetAttribute(gemm_w13,
            cudaFuncAttributeMaxDynamicSharedMemorySize, W13_SMEM);
        cudaStreamCreateWithFlags(&s2, cudaStreamNonBlocking);
        cudaEventCreateWithFlags(&ev0, cudaEventDisableTiming);
        cudaEventCreateWithFlags(&ev1, cudaEventDisableTiming);
        attr_set = true;
    }

    // ---- fork: big MoE weight converts on side stream (overlap with attn path)
    cudaEventRecord(ev0, 0);
    cudaStreamWaitEvent(s2, ev0, 0);
    {
        int n4 = (int)((size_t)NE*NI*DM/4);
        f2bf_kernel<<<(n4+255)/256, 256, 0, s2>>>((const float4*)w1, (uint2*)p_w1_bf, n4);
        f2bf_kernel<<<(n4+255)/256, 256, 0, s2>>>((const float4*)w3, (uint2*)p_w3_bf, n4);
        f2bf_kernel<<<(n4+255)/256, 256, 0, s2>>>((const float4*)w2, (uint2*)p_w2_bf, n4);
    }
    cudaEventRecord(ev1, s2);

    // ---- main stream: attention path
    {
        int n4 = QKVN*DM/4;
        f2bf_kernel<<<(n4+255)/256, 256>>>((const float4*)wqkv, (uint2*)p_wqkv_bf, n4);
        n4 = DM*DM/4;
        f2bf_kernel<<<(n4+255)/256, 256>>>((const float4*)wo, (uint2*)p_wo_bf, n4);
    }
    rmsnorm_kernel<<<SEQ, 256>>>(x, anw, p_hn_bf, nullptr);
    gemm_bf<false><<<dim3(QKVN/128, SEQ/128), 256, GEMM_SMEM>>>(
        p_hn_bf, p_wqkv_bf, nullptr, p_qkv, SEQ, QKVN, DM, 0);
    {
        int total = SEQ * (QKVN/2);
        rope_split_kernel<<<(total + 255)/256, 256>>>(freqs);
    }
    attn_tf32_kernel<<<dim3(SEQ/64, NH), 128, ATTN_SMEM>>>();
    gemm_bf<false><<<dim3(DM/128, SEQ/128), 256, GEMM_SMEM>>>(
        p_y_bf, p_wo_bf, x, p_h, SEQ, DM, DM, 0);
    rmsnorm_kernel<<<SEQ, 256>>>(p_h, fnw, p_hf_bf, p_hf);
    cudaMemsetAsync(p_cnt, 0, NE*sizeof(int), 0);
    gating_kernel<<<SEQ, 256>>>(gate_w);

    // ---- join: MoE phase needs converted w1/w3/w2
    cudaStreamWaitEvent(0, ev1, 0);
    gemm_w13<<<dim3(NI/128, SEQ/128, NE), 256, W13_SMEM>>>(
        p_hf_bf, p_w1_bf, p_w3_bf);
    gemm_bf<true><<<dim3(DM/128, SEQ/128, NE), 256, GEMM_SMEM>>>(
        p_gb, p_w2_bf, nullptr, p_os, 0, DM, NI, 0);
    combine_kernel<<<SEQ, 256>>>(out);
}

// round 9
// speedup vs baseline: 1.1474x; 1.0165x over previous
#include <cuda_runtime.h>
#include <cuda_bf16.h>
#include <math.h>
#include <stdint.h>

#define SEQ 2048
#define DM 1024
#define NH 16
#define NKV 4
#define HDIM 64
#define NE 8
#define NI 3584
#define QKVN 1536
#define NSLOTS (2*SEQ)

typedef __nv_bfloat16 bf16;

// ---------------- scratch (device globals; no allocations) ----------------
__device__ bf16  g_wqkv_bf[QKVN*DM];
__device__ bf16  g_wo_bf[DM*DM];
__device__ bf16  g_w1_bf[(size_t)NE*NI*DM];
__device__ bf16  g_w3_bf[(size_t)NE*NI*DM];
__device__ bf16  g_w2_bf[(size_t)NE*DM*NI];
__device__ bf16  g_hn_bf[SEQ*DM];
__device__ float g_q[NH*SEQ*HDIM];      // tf32-rounded, pre-scaled 0.125
__device__ float g_k[NKV*SEQ*HDIM];     // tf32-rounded
__device__ bf16  g_vt[NKV*HDIM*SEQ];    // bf16, transposed [kvh][d][t]
__device__ bf16  g_y_bf[SEQ*DM];
__device__ float g_h[SEQ*DM];
__device__ float g_hf[SEQ*DM];
__device__ bf16  g_hf_bf[SEQ*DM];
__device__ int   g_cnt[NE];
__device__ int   g_slot[NE*SEQ];
__device__ float g_wslot[NSLOTS];
__device__ bf16  g_gb[(size_t)NSLOTS*NI];
__device__ float g_os[(size_t)NSLOTS*DM];

// ---------------- helpers ---------------------------------------------------
__device__ __forceinline__ uint32_t f2tf32(float f) {
    uint32_t r;
    asm("cvt.rna.tf32.f32 %0, %1;" : "=r"(r) : "f"(f));
    return r;
}
__device__ __forceinline__ void mma_tf32(float c[4],
    uint32_t a0, uint32_t a1, uint32_t a2, uint32_t a3,
    uint32_t b0, uint32_t b1)
{
    asm volatile(
        "mma.sync.aligned.m16n8k8.row.col.f32.tf32.tf32.f32 "
        "{%0,%1,%2,%3}, {%4,%5,%6,%7}, {%8,%9}, {%0,%1,%2,%3};"
        : "+f"(c[0]), "+f"(c[1]), "+f"(c[2]), "+f"(c[3])
        : "r"(a0), "r"(a1), "r"(a2), "r"(a3), "r"(b0), "r"(b1));
}
__device__ __forceinline__ void mma_bf16(float c[4],
    uint32_t a0, uint32_t a1, uint32_t a2, uint32_t a3,
    uint32_t b0, uint32_t b1)
{
    asm volatile(
        "mma.sync.aligned.m16n8k16.row.col.f32.bf16.bf16.f32 "
        "{%0,%1,%2,%3}, {%4,%5,%6,%7}, {%8,%9}, {%0,%1,%2,%3};"
        : "+f"(c[0]), "+f"(c[1]), "+f"(c[2]), "+f"(c[3])
        : "r"(a0), "r"(a1), "r"(a2), "r"(a3), "r"(b0), "r"(b1));
}
__device__ __forceinline__ void ldsm4(uint32_t r[4], uint32_t addr) {
    asm volatile("ldmatrix.sync.aligned.m8n8.x4.shared.b16 {%0,%1,%2,%3}, [%4];"
                 : "=r"(r[0]), "=r"(r[1]), "=r"(r[2]), "=r"(r[3]) : "r"(addr));
}
__device__ __forceinline__ void cpa(uint32_t dst, const void* src, int sz) {
    asm volatile("cp.async.cg.shared.global [%0], [%1], 16, %2;"
                 :: "r"(dst), "l"(src), "r"(sz));
}
__device__ __forceinline__ uint32_t packbf(float a, float b) {
    __nv_bfloat162 p = __floats2bfloat162_rn(a, b);
    return *(uint32_t*)&p;
}

// ---------------- fp32 -> bf16 convert --------------------------------------
__global__ void f2bf_kernel(const float4* __restrict__ s, uint2* __restrict__ d, int n4)
{
    int i = blockIdx.x * blockDim.x + threadIdx.x;
    if (i >= n4) return;
    float4 v = s[i];
    __nv_bfloat162 lo = __floats2bfloat162_rn(v.x, v.y);
    __nv_bfloat162 hi = __floats2bfloat162_rn(v.z, v.w);
    uint2 o;
    o.x = *(uint32_t*)&lo;
    o.y = *(uint32_t*)&hi;
    d[i] = o;
}

// ---------------- rmsnorm (bf16 out + optional fp32 out) -------------------
__global__ __launch_bounds__(256) void rmsnorm_kernel(
    const float* __restrict__ x, const float* __restrict__ w,
    bf16* __restrict__ obf, float* __restrict__ ofp)
{
    int row = blockIdx.x;
    int tid = threadIdx.x;
    const float4* xr = (const float4*)(x + (size_t)row*DM);
    float4 v = xr[tid];
    float ss = v.x*v.x + v.y*v.y + v.z*v.z + v.w*v.w;
    __shared__ float red[8];
    #pragma unroll
    for (int ofs = 16; ofs > 0; ofs >>= 1) ss += __shfl_down_sync(0xffffffffu, ss, ofs);
    if ((tid & 31) == 0) red[tid >> 5] = ss;
    __syncthreads();
    __shared__ float sr;
    if (tid == 0) {
        float t = 0.f;
        #pragma unroll
        for (int i = 0; i < 8; i++) t += red[i];
        sr = rsqrtf(t / (float)DM + 1e-5f);
    }
    __syncthreads();
    float r = sr;
    float4 wv = ((const float4*)w)[tid];
    float4 o;
    o.x = v.x*r*wv.x; o.y = v.y*r*wv.y; o.z = v.z*r*wv.z; o.w = v.w*r*wv.w;
    __nv_bfloat162 lo = __floats2bfloat162_rn(o.x, o.y);
    __nv_bfloat162 hi = __floats2bfloat162_rn(o.z, o.w);
    uint2 ob; ob.x = *(uint32_t*)&lo; ob.y = *(uint32_t*)&hi;
    *(uint2*)(obf + (size_t)row*DM + tid*4) = ob;
    if (ofp) ((float4*)(ofp + (size_t)row*DM))[tid] = o;
}

// ---------------- bf16 HMMA GEMM: C[M,N] = A @ B^T (+resid) ----------------
// 128x128x64 tiles, 256 threads, 3-stage cp.async (96KB smem -> 2 CTAs/SM).
#define GSTG 16384
template<bool GATHER>
__global__ __launch_bounds__(256) void gemm_bf(
    const bf16* __restrict__ A, const bf16* __restrict__ B,
    const float* __restrict__ resid, float* __restrict__ C,
    int M, int N, int K, int shiftA)
{
    extern __shared__ char smem[];
    const int* sl = nullptr;
    if (GATHER) {
        int e = blockIdx.z;
        M = g_cnt[e];
        if ((int)blockIdx.y * 128 >= M) return;
        sl = g_slot + e * SEQ;
        B += (size_t)e * N * K;
    }
    int m0 = blockIdx.y * 128, n0 = blockIdx.x * 128;
    int tid = threadIdx.x, warp = tid >> 5, lane = tid & 31;
    int wm = (warp >> 2) * 64, wn = (warp & 3) * 32;
    uint32_t sbase = (uint32_t)__cvta_generic_to_shared(smem);
    uint32_t aoff[3], boff[3];
    #pragma unroll
    for (int s = 0; s < 3; s++) {
        aoff[s] = sbase + s*GSTG;
        boff[s] = sbase + 3*GSTG + s*GSTG;
    }

    int lrow = tid >> 1;
    int lsg  = (tid & 1) * 4;
    const bf16* Arow; int szA = 16;
    if (GATHER) {
        int gm = m0 + lrow;
        if (gm < M) Arow = A + (size_t)(sl[gm] >> shiftA) * K;
        else { Arow = A; szA = 0; }
    } else {
        Arow = A + (size_t)(m0 + lrow) * K;
    }
    const bf16* Brow = B + (size_t)(n0 + lrow) * K;
    uint32_t dsw = (uint32_t)lrow * 128u;
    int rxor = lrow & 7;

    float acc[4][4][4];
    #pragma unroll
    for (int i = 0; i < 4; i++)
        #pragma unroll
        for (int j = 0; j < 4; j++)
            #pragma unroll
            for (int q = 0; q < 4; q++) acc[i][j][q] = 0.f;

    int CC = K / 64;
    auto loadChunk = [&](int c) {
        int s = c % 3;
        const char* pa = (const char*)(Arow + c*64);
        const char* pb = (const char*)(Brow + c*64);
        #pragma unroll
        for (int i = 0; i < 4; i++) {
            int seg = lsg + i;
            uint32_t o = dsw + (uint32_t)((seg ^ rxor) * 16);
            cpa(aoff[s] + o, pa + seg*16, szA);
            cpa(boff[s] + o, pb + seg*16, 16);
        }
        asm volatile("cp.async.commit_group;" ::: "memory");
    };
    loadChunk(0);
    if (CC > 1) loadChunk(1);

    int lt = lane >> 3;
    int rl = lane & 7;
    int th = (lt & 1) * 8;
    int ts = lane >> 4;

    for (int c = 0; c < CC; c++) {
        if (c + 1 < CC) asm volatile("cp.async.wait_group 1;" ::: "memory");
        else            asm volatile("cp.async.wait_group 0;" ::: "memory");
        __syncthreads();
        if (c + 2 < CC) loadChunk(c + 2);

        uint32_t Ab = aoff[c % 3], Bb = boff[c % 3];
        #pragma unroll
        for (int kk = 0; kk < 4; kk++) {
            uint32_t af[4][4], bfm[2][4];
            #pragma unroll
            for (int i = 0; i < 4; i++) {
                int row = wm + i*16 + th + rl;
                int seg = 2*kk + ts;
                ldsm4(af[i], Ab + row*128 + ((seg ^ (row & 7)) << 4));
            }
            #pragma unroll
            for (int j = 0; j < 2; j++) {
                int nr = wn + j*16 + th + rl;
                int seg = 2*kk + ts;
                ldsm4(bfm[j], Bb + nr*128 + ((seg ^ (nr & 7)) << 4));
            }
            #pragma unroll
            for (int i = 0; i < 4; i++)
                #pragma unroll
                for (int jn = 0; jn < 4; jn++) {
                    int jj = jn >> 1, hi = jn & 1;
                    mma_bf16(acc[i][jn], af[i][0], af[i][1], af[i][2], af[i][3],
                             bfm[jj][hi], bfm[jj][hi+2]);
                }
        }
        __syncthreads();
    }

    int g = lane >> 2, tg = lane & 3;
    #pragma unroll
    for (int i = 0; i < 4; i++) {
        int r0 = m0 + wm + i*16 + g;
        int r1 = r0 + 8;
        bool v0, v1;
        int row0, row1;
        if (GATHER) {
            v0 = r0 < M; v1 = r1 < M;
            row0 = v0 ? sl[r0] : 0;
            row1 = v1 ? sl[r1] : 0;
        } else {
            v0 = v1 = true; row0 = r0; row1 = r1;
        }
        #pragma unroll
        for (int j = 0; j < 4; j++) {
            int c0 = n0 + wn + j*8 + tg*2;
            if (v0) {
                float2 v; v.x = acc[i][j][0]; v.y = acc[i][j][1];
                if (resid) {
                    v.x += resid[(size_t)row0*N + c0];
                    v.y += resid[(size_t)row0*N + c0 + 1];
                }
                *(float2*)(C + (size_t)row0*N + c0) = v;
            }
            if (v1) {
                float2 v; v.x = acc[i][j][2]; v.y = acc[i][j][3];
                if (resid) {
                    v.x += resid[(size_t)row1*N + c0];
                    v.y += resid[(size_t)row1*N + c0 + 1];
                }
                *(float2*)(C + (size_t)row1*N + c0) = v;
            }
        }
    }
}

// ---------------- QKV GEMM with fused RoPE/split epilogue -------------------
// Same mainloop as gemm_bf<false>; epilogue applies RoPE (pairs are the
// adjacent even/odd accumulators) and scatters to g_q/g_k (tf32-rounded,
// Q pre-scaled 0.125) and g_vt (bf16, transposed [kvh][d][t]).
__device__ __forceinline__ void rope_write(
    int t, int c0, float vx, float vy, const float* __restrict__ freqs)
{
    if (c0 < DM) {
        int h = c0 >> 6, d = c0 & 63, p = d >> 1;
        float cs = freqs[((size_t)t*32 + p)*2 + 0];
        float sn = freqs[((size_t)t*32 + p)*2 + 1];
        float2 o;
        o.x = __uint_as_float(f2tf32((vx*cs - vy*sn) * 0.125f));
        o.y = __uint_as_float(f2tf32((vy*cs + vx*sn) * 0.125f));
        *(float2*)(g_q + ((size_t)h*SEQ + t)*HDIM + d) = o;
    } else if (c0 < DM + NKV*HDIM) {
        int c = c0 - DM;
        int kh = c >> 6, d = c & 63, p = d >> 1;
        float cs = freqs[((size_t)t*32 + p)*2 + 0];
        float sn = freqs[((size_t)t*32 + p)*2 + 1];
        float2 o;
        o.x = __uint_as_float(f2tf32(vx*cs - vy*sn));
        o.y = __uint_as_float(f2tf32(vy*cs + vx*sn));
        *(float2*)(g_k + ((size_t)kh*SEQ + t)*HDIM + d) = o;
    } else {
        int c = c0 - DM - NKV*HDIM;
        int vh = c >> 6, d = c & 63;
        g_vt[((size_t)(vh*HDIM + d  ))*SEQ + t] = __float2bfloat16(vx);
        g_vt[((size_t)(vh*HDIM + d+1))*SEQ + t] = __float2bfloat16(vy);
    }
}

__global__ __launch_bounds__(256) void gemm_qkv(
    const bf16* __restrict__ A, const bf16* __restrict__ B,
    const float* __restrict__ freqs)
{
    extern __shared__ char smem[];
    const int N = QKVN, K = DM;
    int m0 = blockIdx.y * 128, n0 = blockIdx.x * 128;
    int tid = threadIdx.x, warp = tid >> 5, lane = tid & 31;
    int wm = (warp >> 2) * 64, wn = (warp & 3) * 32;
    uint32_t sbase = (uint32_t)__cvta_generic_to_shared(smem);
    uint32_t aoff[3], boff[3];
    #pragma unroll
    for (int s = 0; s < 3; s++) {
        aoff[s] = sbase + s*GSTG;
        boff[s] = sbase + 3*GSTG + s*GSTG;
    }

    int lrow = tid >> 1;
    int lsg  = (tid & 1) * 4;
    const bf16* Arow = A + (size_t)(m0 + lrow) * K;
    const bf16* Brow = B + (size_t)(n0 + lrow) * K;
    uint32_t dsw = (uint32_t)lrow * 128u;
    int rxor = lrow & 7;

    float acc[4][4][4];
    #pragma unroll
    for (int i = 0; i < 4; i++)
        #pragma unroll
        for (int j = 0; j < 4; j++)
            #pragma unroll
            for (int q = 0; q < 4; q++) acc[i][j][q] = 0.f;

    const int CC = K / 64;
    auto loadChunk = [&](int c) {
        int s = c % 3;
        const char* pa = (const char*)(Arow + c*64);
        const char* pb = (const char*)(Brow + c*64);
        #pragma unroll
        for (int i = 0; i < 4; i++) {
            int seg = lsg + i;
            uint32_t o = dsw + (uint32_t)((seg ^ rxor) * 16);
            cpa(aoff[s] + o, pa + seg*16, 16);
            cpa(boff[s] + o, pb + seg*16, 16);
        }
        asm volatile("cp.async.commit_group;" ::: "memory");
    };
    loadChunk(0);
    loadChunk(1);

    int lt = lane >> 3;
    int rl = lane & 7;
    int th = (lt & 1) * 8;
    int ts = lane >> 4;

    for (int c = 0; c < CC; c++) {
        if (c + 1 < CC) asm volatile("cp.async.wait_group 1;" ::: "memory");
        else            asm volatile("cp.async.wait_group 0;" ::: "memory");
        __syncthreads();
        if (c + 2 < CC) loadChunk(c + 2);

        uint32_t Ab = aoff[c % 3], Bb = boff[c % 3];
        #pragma unroll
        for (int kk = 0; kk < 4; kk++) {
            uint32_t af[4][4], bfm[2][4];
            #pragma unroll
            for (int i = 0; i < 4; i++) {
                int row = wm + i*16 + th + rl;
                int seg = 2*kk + ts;
                ldsm4(af[i], Ab + row*128 + ((seg ^ (row & 7)) << 4));
            }
            #pragma unroll
            for (int j = 0; j < 2; j++) {
                int nr = wn + j*16 + th + rl;
                int seg = 2*kk + ts;
                ldsm4(bfm[j], Bb + nr*128 + ((seg ^ (nr & 7)) << 4));
            }
            #pragma unroll
            for (int i = 0; i < 4; i++)
                #pragma unroll
                for (int jn = 0; jn < 4; jn++) {
                    int jj = jn >> 1, hi = jn & 1;
                    mma_bf16(acc[i][jn], af[i][0], af[i][1], af[i][2], af[i][3],
                             bfm[jj][hi], bfm[jj][hi+2]);
                }
        }
        __syncthreads();
    }

    int g = lane >> 2, tg = lane & 3;
    #pragma unroll
    for (int i = 0; i < 4; i++) {
        int t0 = m0 + wm + i*16 + g;
        int t1 = t0 + 8;
        #pragma unroll
        for (int j = 0; j < 4; j++) {
            int c0 = n0 + wn + j*8 + tg*2;
            rope_write(t0, c0, acc[i][j][0], acc[i][j][1], freqs);
            rope_write(t1, c0, acc[i][j][2], acc[i][j][3], freqs);
        }
    }
}

// ---------------- fused MoE w1/w3 GEMM + silu*mul (bf16 out) ---------------
__global__ __launch_bounds__(256) void gemm_w13(
    const bf16* __restrict__ A, const bf16* __restrict__ B1,
    const bf16* __restrict__ B3)
{
    extern __shared__ char smem[];
    int e = blockIdx.z;
    int M = g_cnt[e];
    if ((int)blockIdx.y * 128 >= M) return;
    const int* sl = g_slot + e * SEQ;
    B1 += (size_t)e * NI * DM;
    B3 += (size_t)e * NI * DM;

    int m0 = blockIdx.y * 128, n0 = blockIdx.x * 128;
    int tid = threadIdx.x, warp = tid >> 5, lane = tid & 31;
    int wm = (warp >> 2) * 64, wn = (warp & 3) * 32;
    uint32_t sbase = (uint32_t)__cvta_generic_to_shared(smem);
    uint32_t aoff[3], b1off[3], b3off[3];
    #pragma unroll
    for (int s = 0; s < 3; s++) {
        aoff[s]  = sbase + s*GSTG;
        b1off[s] = sbase + 3*GSTG + s*GSTG;
        b3off[s] = sbase + 6*GSTG + s*GSTG;
    }

    int lrow = tid >> 1;
    int lsg  = (tid & 1) * 4;
    const bf16* Arow; int szA = 16;
    {
        int gm = m0 + lrow;
        if (gm < M) Arow = A + (size_t)(sl[gm] >> 1) * DM;
        else { Arow = A; szA = 0; }
    }
    const bf16* B1row = B1 + (size_t)(n0 + lrow) * DM;
    const bf16* B3row = B3 + (size_t)(n0 + lrow) * DM;
    uint32_t dsw = (uint32_t)lrow * 128u;
    int rxor = lrow & 7;

    float ac1[4][4][4], ac3[4][4][4];
    #pragma unroll
    for (int i = 0; i < 4; i++)
        #pragma unroll
        for (int j = 0; j < 4; j++)
            #pragma unroll
            for (int q = 0; q < 4; q++) { ac1[i][j][q] = 0.f; ac3[i][j][q] = 0.f; }

    const int CC = DM / 64;
    auto loadChunk = [&](int c) {
        int s = c % 3;
        const char* pa  = (const char*)(Arow  + c*64);
        const char* pb1 = (const char*)(B1row + c*64);
        const char* pb3 = (const char*)(B3row + c*64);
        #pragma unroll
        for (int i = 0; i < 4; i++) {
            int seg = lsg + i;
            uint32_t o = dsw + (uint32_t)((seg ^ rxor) * 16);
            cpa(aoff[s]  + o, pa  + seg*16, szA);
            cpa(b1off[s] + o, pb1 + seg*16, 16);
            cpa(b3off[s] + o, pb3 + seg*16, 16);
        }
        asm volatile("cp.async.commit_group;" ::: "memory");
    };
    loadChunk(0);
    loadChunk(1);

    int lt = lane >> 3, rl = lane & 7;
    int th = (lt & 1) * 8;
    int ts = lane >> 4;

    for (int c = 0; c < CC; c++) {
        if (c + 1 < CC) asm volatile("cp.async.wait_group 1;" ::: "memory");
        else            asm volatile("cp.async.wait_group 0;" ::: "memory");
        __syncthreads();
        if (c + 2 < CC) loadChunk(c + 2);

        uint32_t Ab = aoff[c % 3], B1b = b1off[c % 3], B3b = b3off[c % 3];
        #pragma unroll
        for (int kk = 0; kk < 4; kk++) {
            uint32_t af[4][4], f1[2][4], f3[2][4];
            #pragma unroll
            for (int i = 0; i < 4; i++) {
                int row = wm + i*16 + th + rl;
                int seg = 2*kk + ts;
                ldsm4(af[i], Ab + row*128 + ((seg ^ (row & 7)) << 4));
            }
            #pragma unroll
            for (int j = 0; j < 2; j++) {
                int nr = wn + j*16 + th + rl;
                int seg = 2*kk + ts;
                ldsm4(f1[j], B1b + nr*128 + ((seg ^ (nr & 7)) << 4));
                ldsm4(f3[j], B3b + nr*128 + ((seg ^ (nr & 7)) << 4));
            }
            #pragma unroll
            for (int i = 0; i < 4; i++)
                #pragma unroll
                for (int jn = 0; jn < 4; jn++) {
                    int jj = jn >> 1, hi = jn & 1;
                    mma_bf16(ac1[i][jn], af[i][0], af[i][1], af[i][2], af[i][3],
                             f1[jj][hi], f1[jj][hi+2]);
                    mma_bf16(ac3[i][jn], af[i][0], af[i][1], af[i][2], af[i][3],
                             f3[jj][hi], f3[jj][hi+2]);
                }
        }
        __syncthreads();
    }

    int g = lane >> 2, tg = lane & 3;
    #pragma unroll
    for (int i = 0; i < 4; i++) {
        int r0 = m0 + wm + i*16 + g;
        int r1 = r0 + 8;
        bool v0 = r0 < M, v1 = r1 < M;
        int row0 = v0 ? sl[r0] : 0;
        int row1 = v1 ? sl[r1] : 0;
        #pragma unroll
        for (int j = 0; j < 4; j++) {
            int c0 = n0 + wn + j*8 + tg*2;
            if (v0) {
                float a0 = ac1[i][j][0], a1 = ac1[i][j][1];
                float u0 = a0 / (1.f + __expf(-a0)) * ac3[i][j][0];
                float u1 = a1 / (1.f + __expf(-a1)) * ac3[i][j][1];
                *(__nv_bfloat162*)(g_gb + (size_t)row0*NI + c0) = __floats2bfloat162_rn(u0, u1);
            }
            if (v1) {
                float a0 = ac1[i][j][2], a1 = ac1[i][j][3];
                float u0 = a0 / (1.f + __expf(-a0)) * ac3[i][j][2];
                float u1 = a1 / (1.f + __expf(-a1)) * ac3[i][j][3];
                *(__nv_bfloat162*)(g_gb + (size_t)row1*NI + c0) = __floats2bfloat162_rn(u0, u1);
            }
        }
    }
}

// ---------------- attention v4: tf32 QK + bf16 PV from registers ------------
// 128 threads (4 warps), grid (32, NH). Static smem 26.6KB (~4 blocks/SM).
// Q/K pre-rounded tf32 (raw-copy staging); V bf16 transposed [d][kv].
#define ASTR 68
#define VSTR 72
__global__ __launch_bounds__(128) void attn4_kernel()
{
    __shared__ float Ks[64*ASTR];
    __shared__ bf16  Vt[64*VSTR];

    int qt = blockIdx.x, h = blockIdx.y;
    int kvh = h >> 2;
    int tid = threadIdx.x, warp = tid >> 5, lane = tid & 31;
    int g = lane >> 2, tg = lane & 3;
    int wq = warp * 16;
    int q0 = qt * 64;

    // stage Q into Ks scratch (pre-scaled + tf32-rounded): raw copy
    for (int i = tid; i < 64*16; i += 128) {
        int row = i >> 4, c4 = (i & 15) * 4;
        *(float4*)&Ks[row*ASTR + c4] =
            *(const float4*)(g_q + ((size_t)h*SEQ + q0 + row)*HDIM + c4);
    }
    __syncthreads();
    uint32_t aq[8][4];
    #pragma unroll
    for (int kk = 0; kk < 8; kk++) {
        aq[kk][0] = __float_as_uint(Ks[(wq+g)*ASTR + kk*8 + tg]);
        aq[kk][1] = __float_as_uint(Ks[(wq+g+8)*ASTR + kk*8 + tg]);
        aq[kk][2] = __float_as_uint(Ks[(wq+g)*ASTR + kk*8 + tg + 4]);
        aq[kk][3] = __float_as_uint(Ks[(wq+g+8)*ASTR + kk*8 + tg + 4]);
    }
    __syncthreads();

    float oc[8][4];
    #pragma unroll
    for (int j = 0; j < 8; j++)
        #pragma unroll
        for (int q = 0; q < 4; q++) oc[j][q] = 0.f;
    float mrow[2] = {-1e30f, -1e30f};
    float lrow[2] = {0.f, 0.f};

    for (int kt = 0; kt <= qt; kt++) {
        // stage K (raw fp32 copy) and V (raw bf16 transposed copy)
        for (int i = tid; i < 1024; i += 128) {
            int row = i >> 4, c4 = (i & 15) * 4;
            *(float4*)&Ks[row*ASTR + c4] =
                *(const float4*)(g_k + ((size_t)kvh*SEQ + kt*64 + row)*HDIM + c4);
        }
        for (int i = tid; i < 512; i += 128) {
            int row = i >> 3, seg = i & 7;
            *(uint4*)&Vt[row*VSTR + seg*8] =
                *(const uint4*)(g_vt + ((size_t)(kvh*HDIM + row))*SEQ + kt*64 + seg*8);
        }
        __syncthreads();

        // S = Q @ K^T (tf32)
        float sc[8][4];
        #pragma unroll
        for (int j = 0; j < 8; j++)
            #pragma unroll
            for (int q = 0; q < 4; q++) sc[j][q] = 0.f;
        #pragma unroll
        for (int kk = 0; kk < 8; kk++) {
            #pragma unroll
            for (int j = 0; j < 8; j++) {
                uint32_t b0 = __float_as_uint(Ks[(j*8+g)*ASTR + kk*8 + tg]);
                uint32_t b1 = __float_as_uint(Ks[(j*8+g)*ASTR + kk*8 + tg + 4]);
                mma_tf32(sc[j], aq[kk][0], aq[kk][1], aq[kk][2], aq[kk][3], b0, b1);
            }
        }

        if (kt == qt) {
            int r0g = q0 + wq + g, r1g = r0g + 8;
            #pragma unroll
            for (int j = 0; j < 8; j++) {
                int c0 = kt*64 + j*8 + tg*2;
                if (c0     > r0g) sc[j][0] = -1e30f;
                if (c0 + 1 > r0g) sc[j][1] = -1e30f;
                if (c0     > r1g) sc[j][2] = -1e30f;
                if (c0 + 1 > r1g) sc[j][3] = -1e30f;
            }
        }

        float mx0 = -1e30f, mx1 = -1e30f;
        #pragma unroll
        for (int j = 0; j < 8; j++) {
            mx0 = fmaxf(mx0, fmaxf(sc[j][0], sc[j][1]));
            mx1 = fmaxf(mx1, fmaxf(sc[j][2], sc[j][3]));
        }
        mx0 = fmaxf(mx0, __shfl_xor_sync(0xffffffffu, mx0, 1));
        mx0 = fmaxf(mx0, __shfl_xor_sync(0xffffffffu, mx0, 2));
        mx1 = fmaxf(mx1, __shfl_xor_sync(0xffffffffu, mx1, 1));
        mx1 = fmaxf(mx1, __shfl_xor_sync(0xffffffffu, mx1, 2));
        float mn0 = fmaxf(mrow[0], mx0), mn1 = fmaxf(mrow[1], mx1);
        float s0 = __expf(mrow[0] - mn0), s1 = __expf(mrow[1] - mn1);
        float ls0 = 0.f, ls1 = 0.f;
        #pragma unroll
        for (int j = 0; j < 8; j++) {
            sc[j][0] = __expf(sc[j][0] - mn0);
            sc[j][1] = __expf(sc[j][1] - mn0);
            sc[j][2] = __expf(sc[j][2] - mn1);
            sc[j][3] = __expf(sc[j][3] - mn1);
            ls0 += sc[j][0] + sc[j][1];
            ls1 += sc[j][2] + sc[j][3];
        }
        ls0 += __shfl_xor_sync(0xffffffffu, ls0, 1);
        ls0 += __shfl_xor_sync(0xffffffffu, ls0, 2);
        ls1 += __shfl_xor_sync(0xffffffffu, ls1, 1);
        ls1 += __shfl_xor_sync(0xffffffffu, ls1, 2);
        lrow[0] = lrow[0]*s0 + ls0;
        lrow[1] = lrow[1]*s1 + ls1;
        mrow[0] = mn0; mrow[1] = mn1;
        #pragma unroll
        for (int j = 0; j < 8; j++) {
            oc[j][0] *= s0; oc[j][1] *= s0;
            oc[j][2] *= s1; oc[j][3] *= s1;
        }

        // pack P into bf16 A-fragments directly from registers
        uint32_t pa[4][4];
        #pragma unroll
        for (int kk = 0; kk < 4; kk++) {
            pa[kk][0] = packbf(sc[2*kk][0],   sc[2*kk][1]);
            pa[kk][1] = packbf(sc[2*kk][2],   sc[2*kk][3]);
            pa[kk][2] = packbf(sc[2*kk+1][0], sc[2*kk+1][1]);
            pa[kk][3] = packbf(sc[2*kk+1][2], sc[2*kk+1][3]);
        }

        // O += P @ V (bf16 m16n8k16), V frags = single 32-bit LDS
        #pragma unroll
        for (int kk = 0; kk < 4; kk++) {
            #pragma unroll
            for (int j = 0; j < 8; j++) {
                uint32_t b0 = *(const uint32_t*)&Vt[(j*8+g)*VSTR + kk*16 + tg*2];
                uint32_t b1 = *(const uint32_t*)&Vt[(j*8+g)*VSTR + kk*16 + tg*2 + 8];
                mma_bf16(oc[j], pa[kk][0], pa[kk][1], pa[kk][2], pa[kk][3], b0, b1);
            }
        }
        __syncthreads();
    }

    float inv0 = 1.f / lrow[0], inv1 = 1.f / lrow[1];
    #pragma unroll
    for (int j = 0; j < 8; j++) {
        int col = h*HDIM + j*8 + tg*2;
        __nv_bfloat162 b0 = __floats2bfloat162_rn(oc[j][0]*inv0, oc[j][1]*inv0);
        __nv_bfloat162 b1 = __floats2bfloat162_rn(oc[j][2]*inv1, oc[j][3]*inv1);
        *(__nv_bfloat162*)(g_y_bf + (size_t)(q0+wq+g)*DM + col)   = b0;
        *(__nv_bfloat162*)(g_y_bf + (size_t)(q0+wq+g+8)*DM + col) = b1;
    }
}

// ---------------- gating ----------------------------------------------------
__global__ __launch_bounds__(256) void gating_kernel(const float* __restrict__ gw)
{
    int t = blockIdx.x;
    int tid = threadIdx.x;
    int e = tid >> 5, lane = tid & 31;
    float s = 0.f;
    const float* hr = g_hf + (size_t)t*DM;
    const float* wr = gw + (size_t)e*DM;
    for (int d = lane; d < DM; d += 32) s += hr[d]*wr[d];
    #pragma unroll
    for (int ofs = 16; ofs > 0; ofs >>= 1) s += __shfl_down_sync(0xffffffffu, s, ofs);
    __shared__ float lg[NE];
    if (lane == 0) lg[e] = s;
    __syncthreads();
    if (tid == 0) {
        float mx = lg[0];
        #pragma unroll
        for (int i = 1; i < NE; i++) mx = fmaxf(mx, lg[i]);
        float p[NE]; float den = 0.f;
        #pragma unroll
        for (int i = 0; i < NE; i++) { p[i] = expf(lg[i]-mx); den += p[i]; }
        #pragma unroll
        for (int i = 0; i < NE; i++) p[i] /= den;
        int i1 = 0;
        #pragma unroll
        for (int i = 1; i < NE; i++) if (p[i] > p[i1]) i1 = i;
        int i2 = (i1 == 0) ? 1 : 0;
        #pragma unroll
        for (int i = 0; i < NE; i++) if (i != i1 && p[i] > p[i2]) i2 = i;
        float w1 = p[i1], w2 = p[i2];
        float sw2 = w1 + w2;
        w1 /= sw2; w2 /= sw2;
        int pos1 = atomicAdd(&g_cnt[i1], 1);
        g_slot[i1*SEQ + pos1] = 2*t;
        g_wslot[2*t] = w1;
        int pos2 = atomicAdd(&g_cnt[i2], 1);
        g_slot[i2*SEQ + pos2] = 2*t + 1;
        g_wslot[2*t+1] = w2;
    }
}

// ---------------- final combine ---------------------------------------------
__global__ __launch_bounds__(256) void combine_kernel(float* __restrict__ out)
{
    int t = blockIdx.x;
    int tid = threadIdx.x;
    float w0 = g_wslot[2*t], w1 = g_wslot[2*t+1];
    float4 hv = ((const float4*)(g_h + (size_t)t*DM))[tid];
    float4 a = ((const float4*)(g_os + (size_t)(2*t)*DM))[tid];
    float4 b = ((const float4*)(g_os + (size_t)(2*t+1)*DM))[tid];
    float4 o;
    o.x = hv.x + w0*a.x + w1*b.x;
    o.y = hv.y + w0*a.y + w1*b.y;
    o.z = hv.z + w0*a.z + w1*b.z;
    o.w = hv.w + w0*a.w + w1*b.w;
    ((float4*)(out + (size_t)t*DM))[tid] = o;
}

// ---------------- host launch ----------------------------------------------
#define GEMM_SMEM (6*GSTG)
#define W13_SMEM  (9*GSTG)

extern "C" void kernel_launch(void* const* d_in, const int* in_sizes, int n_in,
                              void* d_out, int out_size)
{
    const float* x      = (const float*)d_in[0];
    const float* wqkv   = (const float*)d_in[1];
    const float* wo     = (const float*)d_in[2];
    const float* gate_w = (const float*)d_in[3];
    const float* w1     = (const float*)d_in[4];
    const float* w2     = (const float*)d_in[5];
    const float* w3     = (const float*)d_in[6];
    const float* anw    = (const float*)d_in[7];
    const float* fnw    = (const float*)d_in[8];
    const float* freqs  = (const float*)d_in[9];
    float* out = (float*)d_out;

    bf16 *p_wqkv_bf, *p_wo_bf, *p_w1_bf, *p_w3_bf, *p_w2_bf;
    bf16 *p_hn_bf, *p_hf_bf, *p_y_bf, *p_gb;
    float *p_h, *p_hf, *p_os;
    int *p_cnt;
    cudaGetSymbolAddress((void**)&p_wqkv_bf, g_wqkv_bf);
    cudaGetSymbolAddress((void**)&p_wo_bf,   g_wo_bf);
    cudaGetSymbolAddress((void**)&p_w1_bf,   g_w1_bf);
    cudaGetSymbolAddress((void**)&p_w3_bf,   g_w3_bf);
    cudaGetSymbolAddress((void**)&p_w2_bf,   g_w2_bf);
    cudaGetSymbolAddress((void**)&p_hn_bf,   g_hn_bf);
    cudaGetSymbolAddress((void**)&p_hf_bf,   g_hf_bf);
    cudaGetSymbolAddress((void**)&p_y_bf,    g_y_bf);
    cudaGetSymbolAddress((void**)&p_gb,      g_gb);
    cudaGetSymbolAddress((void**)&p_h,       g_h);
    cudaGetSymbolAddress((void**)&p_hf,      g_hf);
    cudaGetSymbolAddress((void**)&p_os,      g_os);
    cudaGetSymbolAddress((void**)&p_cnt,     g_cnt);

    static cudaStream_t s2 = nullptr;
    static cudaEvent_t ev0 = nullptr, ev1 = nullptr;
    static bool attr_set = false;
    if (!attr_set) {
        cudaFuncSetAttribute(gemm_bf<false>,
            cudaFuncAttributeMaxDynamicSharedMemorySize, GEMM_SMEM);
        cudaFuncSetAttribute(gemm_bf<true>,
            cudaFuncAttributeMaxDynamicSharedMemorySize, GEMM_SMEM);
        cudaFuncSetAttribute(gemm_qkv,
            cudaFuncAttributeMaxDynamicSharedMemorySize, GEMM_SMEM);
        cudaFuncSetAttribute(gemm_w13,
            cudaFuncAttributeMaxDynamicSharedMemorySize, W13_SMEM);
        cudaStreamCreateWithFlags(&s2, cudaStreamNonBlocking);
        cudaEventCreateWithFlags(&ev0, cudaEventDisableTiming);
        cudaEventCreateWithFlags(&ev1, cudaEventDisableTiming);
        attr_set = true;
    }

    // ---- fork: big MoE weight converts on side stream
    cudaEventRecord(ev0, 0);
    cudaStreamWaitEvent(s2, ev0, 0);
    {
        int n4 = (int)((size_t)NE*NI*DM/4);
        f2bf_kernel<<<(n4+255)/256, 256, 0, s2>>>((const float4*)w1, (uint2*)p_w1_bf, n4);
        f2bf_kernel<<<(n4+255)/256, 256, 0, s2>>>((const float4*)w3, (uint2*)p_w3_bf, n4);
        f2bf_kernel<<<(n4+255)/256, 256, 0, s2>>>((const float4*)w2, (uint2*)p_w2_bf, n4);
    }
    cudaEventRecord(ev1, s2);

    // ---- main stream: attention path
    {
        int n4 = QKVN*DM/4;
        f2bf_kernel<<<(n4+255)/256, 256>>>((const float4*)wqkv, (uint2*)p_wqkv_bf, n4);
        n4 = DM*DM/4;
        f2bf_kernel<<<(n4+255)/256, 256>>>((const float4*)wo, (uint2*)p_wo_bf, n4);
    }
    rmsnorm_kernel<<<SEQ, 256>>>(x, anw, p_hn_bf, nullptr);
    // qkv GEMM with fused RoPE/split epilogue
    gemm_qkv<<<dim3(QKVN/128, SEQ/128), 256, GEMM_SMEM>>>(p_hn_bf, p_wqkv_bf, freqs);
    // attention v4
    attn4_kernel<<<dim3(SEQ/64, NH), 128>>>();
    gemm_bf<false><<<dim3(DM/128, SEQ/128), 256, GEMM_SMEM>>>(
        p_y_bf, p_wo_bf, x, p_h, SEQ, DM, DM, 0);
    rmsnorm_kernel<<<SEQ, 256>>>(p_h, fnw, p_hf_bf, p_hf);
    cudaMemsetAsync(p_cnt, 0, NE*sizeof(int), 0);
    gating_kernel<<<SEQ, 256>>>(gate_w);

    // ---- join: MoE phase needs converted w1/w3/w2
    cudaStreamWaitEvent(0, ev1, 0);
    gemm_w13<<<dim3(NI/128, SEQ/128, NE), 256, W13_SMEM>>>(
        p_hf_bf, p_w1_bf, p_w3_bf);
    gemm_bf<true><<<dim3(DM/128, SEQ/128, NE), 256, GEMM_SMEM>>>(
        p_gb, p_w2_bf, nullptr, p_os, 0, DM, NI, 0);
    combine_kernel<<<SEQ, 256>>>(out);
}

// round 10
// speedup vs baseline: 1.1805x; 1.0289x over previous
#include <cuda_runtime.h>
#include <cuda_bf16.h>
#include <math.h>
#include <stdint.h>

#define SEQ 2048
#define DM 1024
#define NH 16
#define NKV 4
#define HDIM 64
#define NE 8
#define NI 3584
#define QKVN 1536
#define NSLOTS (2*SEQ)

typedef __nv_bfloat16 bf16;

// ---------------- scratch (device globals; no allocations) ----------------
__device__ bf16  g_wqkv_bf[QKVN*DM];
__device__ bf16  g_wo_bf[DM*DM];
__device__ bf16  g_w1_bf[(size_t)NE*NI*DM];
__device__ bf16  g_w3_bf[(size_t)NE*NI*DM];
__device__ bf16  g_w2_bf[(size_t)NE*DM*NI];
__device__ bf16  g_hn_bf[SEQ*DM];
__device__ float g_q[NH*SEQ*HDIM];      // tf32-rounded, pre-scaled 0.125
__device__ float g_k[NKV*SEQ*HDIM];     // tf32-rounded
__device__ bf16  g_vt[NKV*HDIM*SEQ];    // bf16, transposed [kvh][d][t]
__device__ float g_po[(size_t)2*NH*SEQ*HDIM];  // split-K partial O
__device__ float g_pm[2*NH*SEQ];               // partial max
__device__ float g_pl[2*NH*SEQ];               // partial sum
__device__ bf16  g_y_bf[SEQ*DM];
__device__ float g_h[SEQ*DM];
__device__ float g_hf[SEQ*DM];
__device__ bf16  g_hf_bf[SEQ*DM];
__device__ int   g_cnt[NE];
__device__ int   g_slot[NE*SEQ];
__device__ float g_wslot[NSLOTS];
__device__ bf16  g_gb[(size_t)NSLOTS*NI];
__device__ float g_os[(size_t)NSLOTS*DM];

// ---------------- helpers ---------------------------------------------------
__device__ __forceinline__ uint32_t f2tf32(float f) {
    uint32_t r;
    asm("cvt.rna.tf32.f32 %0, %1;" : "=r"(r) : "f"(f));
    return r;
}
__device__ __forceinline__ void mma_tf32(float c[4],
    uint32_t a0, uint32_t a1, uint32_t a2, uint32_t a3,
    uint32_t b0, uint32_t b1)
{
    asm volatile(
        "mma.sync.aligned.m16n8k8.row.col.f32.tf32.tf32.f32 "
        "{%0,%1,%2,%3}, {%4,%5,%6,%7}, {%8,%9}, {%0,%1,%2,%3};"
        : "+f"(c[0]), "+f"(c[1]), "+f"(c[2]), "+f"(c[3])
        : "r"(a0), "r"(a1), "r"(a2), "r"(a3), "r"(b0), "r"(b1));
}
__device__ __forceinline__ void mma_bf16(float c[4],
    uint32_t a0, uint32_t a1, uint32_t a2, uint32_t a3,
    uint32_t b0, uint32_t b1)
{
    asm volatile(
        "mma.sync.aligned.m16n8k16.row.col.f32.bf16.bf16.f32 "
        "{%0,%1,%2,%3}, {%4,%5,%6,%7}, {%8,%9}, {%0,%1,%2,%3};"
        : "+f"(c[0]), "+f"(c[1]), "+f"(c[2]), "+f"(c[3])
        : "r"(a0), "r"(a1), "r"(a2), "r"(a3), "r"(b0), "r"(b1));
}
__device__ __forceinline__ void ldsm4(uint32_t r[4], uint32_t addr) {
    asm volatile("ldmatrix.sync.aligned.m8n8.x4.shared.b16 {%0,%1,%2,%3}, [%4];"
                 : "=r"(r[0]), "=r"(r[1]), "=r"(r[2]), "=r"(r[3]) : "r"(addr));
}
__device__ __forceinline__ void cpa(uint32_t dst, const void* src, int sz) {
    asm volatile("cp.async.cg.shared.global [%0], [%1], 16, %2;"
                 :: "r"(dst), "l"(src), "r"(sz));
}
__device__ __forceinline__ uint32_t packbf(float a, float b) {
    __nv_bfloat162 p = __floats2bfloat162_rn(a, b);
    return *(uint32_t*)&p;
}

// ---------------- fp32 -> bf16 convert --------------------------------------
__global__ void f2bf_kernel(const float4* __restrict__ s, uint2* __restrict__ d, int n4)
{
    int i = blockIdx.x * blockDim.x + threadIdx.x;
    if (i >= n4) return;
    float4 v = s[i];
    __nv_bfloat162 lo = __floats2bfloat162_rn(v.x, v.y);
    __nv_bfloat162 hi = __floats2bfloat162_rn(v.z, v.w);
    uint2 o;
    o.x = *(uint32_t*)&lo;
    o.y = *(uint32_t*)&hi;
    d[i] = o;
}

// ---------------- rmsnorm (bf16 out + optional fp32 out) -------------------
__global__ __launch_bounds__(256) void rmsnorm_kernel(
    const float* __restrict__ x, const float* __restrict__ w,
    bf16* __restrict__ obf, float* __restrict__ ofp)
{
    int row = blockIdx.x;
    int tid = threadIdx.x;
    const float4* xr = (const float4*)(x + (size_t)row*DM);
    float4 v = xr[tid];
    float ss = v.x*v.x + v.y*v.y + v.z*v.z + v.w*v.w;
    __shared__ float red[8];
    #pragma unroll
    for (int ofs = 16; ofs > 0; ofs >>= 1) ss += __shfl_down_sync(0xffffffffu, ss, ofs);
    if ((tid & 31) == 0) red[tid >> 5] = ss;
    __syncthreads();
    __shared__ float sr;
    if (tid == 0) {
        float t = 0.f;
        #pragma unroll
        for (int i = 0; i < 8; i++) t += red[i];
        sr = rsqrtf(t / (float)DM + 1e-5f);
    }
    __syncthreads();
    float r = sr;
    float4 wv = ((const float4*)w)[tid];
    float4 o;
    o.x = v.x*r*wv.x; o.y = v.y*r*wv.y; o.z = v.z*r*wv.z; o.w = v.w*r*wv.w;
    __nv_bfloat162 lo = __floats2bfloat162_rn(o.x, o.y);
    __nv_bfloat162 hi = __floats2bfloat162_rn(o.z, o.w);
    uint2 ob; ob.x = *(uint32_t*)&lo; ob.y = *(uint32_t*)&hi;
    *(uint2*)(obf + (size_t)row*DM + tid*4) = ob;
    if (ofp) ((float4*)(ofp + (size_t)row*DM))[tid] = o;
}

// ---------------- bf16 HMMA GEMM: C[M,N] = A @ B^T (+resid) ----------------
#define GSTG 16384
template<bool GATHER>
__global__ __launch_bounds__(256) void gemm_bf(
    const bf16* __restrict__ A, const bf16* __restrict__ B,
    const float* __restrict__ resid, float* __restrict__ C,
    int M, int N, int K, int shiftA)
{
    extern __shared__ char smem[];
    const int* sl = nullptr;
    if (GATHER) {
        int e = blockIdx.z;
        M = g_cnt[e];
        if ((int)blockIdx.y * 128 >= M) return;
        sl = g_slot + e * SEQ;
        B += (size_t)e * N * K;
    }
    int m0 = blockIdx.y * 128, n0 = blockIdx.x * 128;
    int tid = threadIdx.x, warp = tid >> 5, lane = tid & 31;
    int wm = (warp >> 2) * 64, wn = (warp & 3) * 32;
    uint32_t sbase = (uint32_t)__cvta_generic_to_shared(smem);
    uint32_t aoff[3], boff[3];
    #pragma unroll
    for (int s = 0; s < 3; s++) {
        aoff[s] = sbase + s*GSTG;
        boff[s] = sbase + 3*GSTG + s*GSTG;
    }

    int lrow = tid >> 1;
    int lsg  = (tid & 1) * 4;
    const bf16* Arow; int szA = 16;
    if (GATHER) {
        int gm = m0 + lrow;
        if (gm < M) Arow = A + (size_t)(sl[gm] >> shiftA) * K;
        else { Arow = A; szA = 0; }
    } else {
        Arow = A + (size_t)(m0 + lrow) * K;
    }
    const bf16* Brow = B + (size_t)(n0 + lrow) * K;
    uint32_t dsw = (uint32_t)lrow * 128u;
    int rxor = lrow & 7;

    float acc[4][4][4];
    #pragma unroll
    for (int i = 0; i < 4; i++)
        #pragma unroll
        for (int j = 0; j < 4; j++)
            #pragma unroll
            for (int q = 0; q < 4; q++) acc[i][j][q] = 0.f;

    int CC = K / 64;
    auto loadChunk = [&](int c) {
        int s = c % 3;
        const char* pa = (const char*)(Arow + c*64);
        const char* pb = (const char*)(Brow + c*64);
        #pragma unroll
        for (int i = 0; i < 4; i++) {
            int seg = lsg + i;
            uint32_t o = dsw + (uint32_t)((seg ^ rxor) * 16);
            cpa(aoff[s] + o, pa + seg*16, szA);
            cpa(boff[s] + o, pb + seg*16, 16);
        }
        asm volatile("cp.async.commit_group;" ::: "memory");
    };
    loadChunk(0);
    if (CC > 1) loadChunk(1);

    int lt = lane >> 3;
    int rl = lane & 7;
    int th = (lt & 1) * 8;
    int ts = lane >> 4;

    for (int c = 0; c < CC; c++) {
        if (c + 1 < CC) asm volatile("cp.async.wait_group 1;" ::: "memory");
        else            asm volatile("cp.async.wait_group 0;" ::: "memory");
        __syncthreads();
        if (c + 2 < CC) loadChunk(c + 2);

        uint32_t Ab = aoff[c % 3], Bb = boff[c % 3];
        #pragma unroll
        for (int kk = 0; kk < 4; kk++) {
            uint32_t af[4][4], bfm[2][4];
            #pragma unroll
            for (int i = 0; i < 4; i++) {
                int row = wm + i*16 + th + rl;
                int seg = 2*kk + ts;
                ldsm4(af[i], Ab + row*128 + ((seg ^ (row & 7)) << 4));
            }
            #pragma unroll
            for (int j = 0; j < 2; j++) {
                int nr = wn + j*16 + th + rl;
                int seg = 2*kk + ts;
                ldsm4(bfm[j], Bb + nr*128 + ((seg ^ (nr & 7)) << 4));
            }
            #pragma unroll
            for (int i = 0; i < 4; i++)
                #pragma unroll
                for (int jn = 0; jn < 4; jn++) {
                    int jj = jn >> 1, hi = jn & 1;
                    mma_bf16(acc[i][jn], af[i][0], af[i][1], af[i][2], af[i][3],
                             bfm[jj][hi], bfm[jj][hi+2]);
                }
        }
        __syncthreads();
    }

    int g = lane >> 2, tg = lane & 3;
    #pragma unroll
    for (int i = 0; i < 4; i++) {
        int r0 = m0 + wm + i*16 + g;
        int r1 = r0 + 8;
        bool v0, v1;
        int row0, row1;
        if (GATHER) {
            v0 = r0 < M; v1 = r1 < M;
            row0 = v0 ? sl[r0] : 0;
            row1 = v1 ? sl[r1] : 0;
        } else {
            v0 = v1 = true; row0 = r0; row1 = r1;
        }
        #pragma unroll
        for (int j = 0; j < 4; j++) {
            int c0 = n0 + wn + j*8 + tg*2;
            if (v0) {
                float2 v; v.x = acc[i][j][0]; v.y = acc[i][j][1];
                if (resid) {
                    v.x += resid[(size_t)row0*N + c0];
                    v.y += resid[(size_t)row0*N + c0 + 1];
                }
                *(float2*)(C + (size_t)row0*N + c0) = v;
            }
            if (v1) {
                float2 v; v.x = acc[i][j][2]; v.y = acc[i][j][3];
                if (resid) {
                    v.x += resid[(size_t)row1*N + c0];
                    v.y += resid[(size_t)row1*N + c0 + 1];
                }
                *(float2*)(C + (size_t)row1*N + c0) = v;
            }
        }
    }
}

// ---------------- QKV GEMM with fused RoPE/split epilogue -------------------
__device__ __forceinline__ void rope_write(
    int t, int c0, float vx, float vy, const float* __restrict__ freqs)
{
    if (c0 < DM) {
        int h = c0 >> 6, d = c0 & 63, p = d >> 1;
        float cs = freqs[((size_t)t*32 + p)*2 + 0];
        float sn = freqs[((size_t)t*32 + p)*2 + 1];
        float2 o;
        o.x = __uint_as_float(f2tf32((vx*cs - vy*sn) * 0.125f));
        o.y = __uint_as_float(f2tf32((vy*cs + vx*sn) * 0.125f));
        *(float2*)(g_q + ((size_t)h*SEQ + t)*HDIM + d) = o;
    } else if (c0 < DM + NKV*HDIM) {
        int c = c0 - DM;
        int kh = c >> 6, d = c & 63, p = d >> 1;
        float cs = freqs[((size_t)t*32 + p)*2 + 0];
        float sn = freqs[((size_t)t*32 + p)*2 + 1];
        float2 o;
        o.x = __uint_as_float(f2tf32(vx*cs - vy*sn));
        o.y = __uint_as_float(f2tf32(vy*cs + vx*sn));
        *(float2*)(g_k + ((size_t)kh*SEQ + t)*HDIM + d) = o;
    } else {
        int c = c0 - DM - NKV*HDIM;
        int vh = c >> 6, d = c & 63;
        g_vt[((size_t)(vh*HDIM + d  ))*SEQ + t] = __float2bfloat16(vx);
        g_vt[((size_t)(vh*HDIM + d+1))*SEQ + t] = __float2bfloat16(vy);
    }
}

__global__ __launch_bounds__(256) void gemm_qkv(
    const bf16* __restrict__ A, const bf16* __restrict__ B,
    const float* __restrict__ freqs)
{
    extern __shared__ char smem[];
    const int K = DM;
    int m0 = blockIdx.y * 128, n0 = blockIdx.x * 128;
    int tid = threadIdx.x, warp = tid >> 5, lane = tid & 31;
    int wm = (warp >> 2) * 64, wn = (warp & 3) * 32;
    uint32_t sbase = (uint32_t)__cvta_generic_to_shared(smem);
    uint32_t aoff[3], boff[3];
    #pragma unroll
    for (int s = 0; s < 3; s++) {
        aoff[s] = sbase + s*GSTG;
        boff[s] = sbase + 3*GSTG + s*GSTG;
    }

    int lrow = tid >> 1;
    int lsg  = (tid & 1) * 4;
    const bf16* Arow = A + (size_t)(m0 + lrow) * K;
    const bf16* Brow = B + (size_t)(n0 + lrow) * K;
    uint32_t dsw = (uint32_t)lrow * 128u;
    int rxor = lrow & 7;

    float acc[4][4][4];
    #pragma unroll
    for (int i = 0; i < 4; i++)
        #pragma unroll
        for (int j = 0; j < 4; j++)
            #pragma unroll
            for (int q = 0; q < 4; q++) acc[i][j][q] = 0.f;

    const int CC = K / 64;
    auto loadChunk = [&](int c) {
        int s = c % 3;
        const char* pa = (const char*)(Arow + c*64);
        const char* pb = (const char*)(Brow + c*64);
        #pragma unroll
        for (int i = 0; i < 4; i++) {
            int seg = lsg + i;
            uint32_t o = dsw + (uint32_t)((seg ^ rxor) * 16);
            cpa(aoff[s] + o, pa + seg*16, 16);
            cpa(boff[s] + o, pb + seg*16, 16);
        }
        asm volatile("cp.async.commit_group;" ::: "memory");
    };
    loadChunk(0);
    loadChunk(1);

    int lt = lane >> 3;
    int rl = lane & 7;
    int th = (lt & 1) * 8;
    int ts = lane >> 4;

    for (int c = 0; c < CC; c++) {
        if (c + 1 < CC) asm volatile("cp.async.wait_group 1;" ::: "memory");
        else            asm volatile("cp.async.wait_group 0;" ::: "memory");
        __syncthreads();
        if (c + 2 < CC) loadChunk(c + 2);

        uint32_t Ab = aoff[c % 3], Bb = boff[c % 3];
        #pragma unroll
        for (int kk = 0; kk < 4; kk++) {
            uint32_t af[4][4], bfm[2][4];
            #pragma unroll
            for (int i = 0; i < 4; i++) {
                int row = wm + i*16 + th + rl;
                int seg = 2*kk + ts;
                ldsm4(af[i], Ab + row*128 + ((seg ^ (row & 7)) << 4));
            }
            #pragma unroll
            for (int j = 0; j < 2; j++) {
                int nr = wn + j*16 + th + rl;
                int seg = 2*kk + ts;
                ldsm4(bfm[j], Bb + nr*128 + ((seg ^ (nr & 7)) << 4));
            }
            #pragma unroll
            for (int i = 0; i < 4; i++)
                #pragma unroll
                for (int jn = 0; jn < 4; jn++) {
                    int jj = jn >> 1, hi = jn & 1;
                    mma_bf16(acc[i][jn], af[i][0], af[i][1], af[i][2], af[i][3],
                             bfm[jj][hi], bfm[jj][hi+2]);
                }
        }
        __syncthreads();
    }

    int g = lane >> 2, tg = lane & 3;
    #pragma unroll
    for (int i = 0; i < 4; i++) {
        int t0 = m0 + wm + i*16 + g;
        int t1 = t0 + 8;
        #pragma unroll
        for (int j = 0; j < 4; j++) {
            int c0 = n0 + wn + j*8 + tg*2;
            rope_write(t0, c0, acc[i][j][0], acc[i][j][1], freqs);
            rope_write(t1, c0, acc[i][j][2], acc[i][j][3], freqs);
        }
    }
}

// ---------------- fused MoE w1/w3 GEMM + silu*mul (bf16 out) ---------------
__global__ __launch_bounds__(256) void gemm_w13(
    const bf16* __restrict__ A, const bf16* __restrict__ B1,
    const bf16* __restrict__ B3)
{
    extern __shared__ char smem[];
    int e = blockIdx.z;
    int M = g_cnt[e];
    if ((int)blockIdx.y * 128 >= M) return;
    const int* sl = g_slot + e * SEQ;
    B1 += (size_t)e * NI * DM;
    B3 += (size_t)e * NI * DM;

    int m0 = blockIdx.y * 128, n0 = blockIdx.x * 128;
    int tid = threadIdx.x, warp = tid >> 5, lane = tid & 31;
    int wm = (warp >> 2) * 64, wn = (warp & 3) * 32;
    uint32_t sbase = (uint32_t)__cvta_generic_to_shared(smem);
    uint32_t aoff[3], b1off[3], b3off[3];
    #pragma unroll
    for (int s = 0; s < 3; s++) {
        aoff[s]  = sbase + s*GSTG;
        b1off[s] = sbase + 3*GSTG + s*GSTG;
        b3off[s] = sbase + 6*GSTG + s*GSTG;
    }

    int lrow = tid >> 1;
    int lsg  = (tid & 1) * 4;
    const bf16* Arow; int szA = 16;
    {
        int gm = m0 + lrow;
        if (gm < M) Arow = A + (size_t)(sl[gm] >> 1) * DM;
        else { Arow = A; szA = 0; }
    }
    const bf16* B1row = B1 + (size_t)(n0 + lrow) * DM;
    const bf16* B3row = B3 + (size_t)(n0 + lrow) * DM;
    uint32_t dsw = (uint32_t)lrow * 128u;
    int rxor = lrow & 7;

    float ac1[4][4][4], ac3[4][4][4];
    #pragma unroll
    for (int i = 0; i < 4; i++)
        #pragma unroll
        for (int j = 0; j < 4; j++)
            #pragma unroll
            for (int q = 0; q < 4; q++) { ac1[i][j][q] = 0.f; ac3[i][j][q] = 0.f; }

    const int CC = DM / 64;
    auto loadChunk = [&](int c) {
        int s = c % 3;
        const char* pa  = (const char*)(Arow  + c*64);
        const char* pb1 = (const char*)(B1row + c*64);
        const char* pb3 = (const char*)(B3row + c*64);
        #pragma unroll
        for (int i = 0; i < 4; i++) {
            int seg = lsg + i;
            uint32_t o = dsw + (uint32_t)((seg ^ rxor) * 16);
            cpa(aoff[s]  + o, pa  + seg*16, szA);
            cpa(b1off[s] + o, pb1 + seg*16, 16);
            cpa(b3off[s] + o, pb3 + seg*16, 16);
        }
        asm volatile("cp.async.commit_group;" ::: "memory");
    };
    loadChunk(0);
    loadChunk(1);

    int lt = lane >> 3, rl = lane & 7;
    int th = (lt & 1) * 8;
    int ts = lane >> 4;

    for (int c = 0; c < CC; c++) {
        if (c + 1 < CC) asm volatile("cp.async.wait_group 1;" ::: "memory");
        else            asm volatile("cp.async.wait_group 0;" ::: "memory");
        __syncthreads();
        if (c + 2 < CC) loadChunk(c + 2);

        uint32_t Ab = aoff[c % 3], B1b = b1off[c % 3], B3b = b3off[c % 3];
        #pragma unroll
        for (int kk = 0; kk < 4; kk++) {
            uint32_t af[4][4], f1[2][4], f3[2][4];
            #pragma unroll
            for (int i = 0; i < 4; i++) {
                int row = wm + i*16 + th + rl;
                int seg = 2*kk + ts;
                ldsm4(af[i], Ab + row*128 + ((seg ^ (row & 7)) << 4));
            }
            #pragma unroll
            for (int j = 0; j < 2; j++) {
                int nr = wn + j*16 + th + rl;
                int seg = 2*kk + ts;
                ldsm4(f1[j], B1b + nr*128 + ((seg ^ (nr & 7)) << 4));
                ldsm4(f3[j], B3b + nr*128 + ((seg ^ (nr & 7)) << 4));
            }
            #pragma unroll
            for (int i = 0; i < 4; i++)
                #pragma unroll
                for (int jn = 0; jn < 4; jn++) {
                    int jj = jn >> 1, hi = jn & 1;
                    mma_bf16(ac1[i][jn], af[i][0], af[i][1], af[i][2], af[i][3],
                             f1[jj][hi], f1[jj][hi+2]);
                    mma_bf16(ac3[i][jn], af[i][0], af[i][1], af[i][2], af[i][3],
                             f3[jj][hi], f3[jj][hi+2]);
                }
        }
        __syncthreads();
    }

    int g = lane >> 2, tg = lane & 3;
    #pragma unroll
    for (int i = 0; i < 4; i++) {
        int r0 = m0 + wm + i*16 + g;
        int r1 = r0 + 8;
        bool v0 = r0 < M, v1 = r1 < M;
        int row0 = v0 ? sl[r0] : 0;
        int row1 = v1 ? sl[r1] : 0;
        #pragma unroll
        for (int j = 0; j < 4; j++) {
            int c0 = n0 + wn + j*8 + tg*2;
            if (v0) {
                float a0 = ac1[i][j][0], a1 = ac1[i][j][1];
                float u0 = a0 / (1.f + __expf(-a0)) * ac3[i][j][0];
                float u1 = a1 / (1.f + __expf(-a1)) * ac3[i][j][1];
                *(__nv_bfloat162*)(g_gb + (size_t)row0*NI + c0) = __floats2bfloat162_rn(u0, u1);
            }
            if (v1) {
                float a0 = ac1[i][j][2], a1 = ac1[i][j][3];
                float u0 = a0 / (1.f + __expf(-a0)) * ac3[i][j][2];
                float u1 = a1 / (1.f + __expf(-a1)) * ac3[i][j][3];
                *(__nv_bfloat162*)(g_gb + (size_t)row1*NI + c0) = __floats2bfloat162_rn(u0, u1);
            }
        }
    }
}

// ---------------- attention v5: split-K flash (tf32 QK + bf16 PV) -----------
// grid (32, NH, 2), 128 threads. Split z covers kt in [lo,hi):
// lo = z ? ceil((qt+1)/2) : 0 ; hi = z ? qt+1 : ceil((qt+1)/2).
// Writes unnormalized partial O + (m,l); reduce kernel merges.
#define ASTR 68
#define VSTR 72
__global__ __launch_bounds__(128) void attn5_kernel()
{
    __shared__ float Ks[64*ASTR];
    __shared__ bf16  Vt[64*VSTR];

    int qt = blockIdx.x, h = blockIdx.y, z = blockIdx.z;
    int kvh = h >> 2;
    int tid = threadIdx.x, warp = tid >> 5, lane = tid & 31;
    int g = lane >> 2, tg = lane & 3;
    int wq = warp * 16;
    int q0 = qt * 64;

    int n = qt + 1;
    int half = (n + 1) >> 1;
    int lo = z ? half : 0;
    int hi = z ? n : half;

    float oc[8][4];
    #pragma unroll
    for (int j = 0; j < 8; j++)
        #pragma unroll
        for (int q = 0; q < 4; q++) oc[j][q] = 0.f;
    float mrow[2] = {-1e30f, -1e30f};
    float lrow[2] = {0.f, 0.f};

    if (lo < hi) {
        // stage Q into Ks scratch (pre-scaled + tf32-rounded): raw copy
        for (int i = tid; i < 64*16; i += 128) {
            int row = i >> 4, c4 = (i & 15) * 4;
            *(float4*)&Ks[row*ASTR + c4] =
                *(const float4*)(g_q + ((size_t)h*SEQ + q0 + row)*HDIM + c4);
        }
        __syncthreads();
        uint32_t aq[8][4];
        #pragma unroll
        for (int kk = 0; kk < 8; kk++) {
            aq[kk][0] = __float_as_uint(Ks[(wq+g)*ASTR + kk*8 + tg]);
            aq[kk][1] = __float_as_uint(Ks[(wq+g+8)*ASTR + kk*8 + tg]);
            aq[kk][2] = __float_as_uint(Ks[(wq+g)*ASTR + kk*8 + tg + 4]);
            aq[kk][3] = __float_as_uint(Ks[(wq+g+8)*ASTR + kk*8 + tg + 4]);
        }
        __syncthreads();

        for (int kt = lo; kt < hi; kt++) {
            for (int i = tid; i < 1024; i += 128) {
                int row = i >> 4, c4 = (i & 15) * 4;
                *(float4*)&Ks[row*ASTR + c4] =
                    *(const float4*)(g_k + ((size_t)kvh*SEQ + kt*64 + row)*HDIM + c4);
            }
            for (int i = tid; i < 512; i += 128) {
                int row = i >> 3, seg = i & 7;
                *(uint4*)&Vt[row*VSTR + seg*8] =
                    *(const uint4*)(g_vt + ((size_t)(kvh*HDIM + row))*SEQ + kt*64 + seg*8);
            }
            __syncthreads();

            float sc[8][4];
            #pragma unroll
            for (int j = 0; j < 8; j++)
                #pragma unroll
                for (int q = 0; q < 4; q++) sc[j][q] = 0.f;
            #pragma unroll
            for (int kk = 0; kk < 8; kk++) {
                #pragma unroll
                for (int j = 0; j < 8; j++) {
                    uint32_t b0 = __float_as_uint(Ks[(j*8+g)*ASTR + kk*8 + tg]);
                    uint32_t b1 = __float_as_uint(Ks[(j*8+g)*ASTR + kk*8 + tg + 4]);
                    mma_tf32(sc[j], aq[kk][0], aq[kk][1], aq[kk][2], aq[kk][3], b0, b1);
                }
            }

            if (kt == qt) {
                int r0g = q0 + wq + g, r1g = r0g + 8;
                #pragma unroll
                for (int j = 0; j < 8; j++) {
                    int c0 = kt*64 + j*8 + tg*2;
                    if (c0     > r0g) sc[j][0] = -1e30f;
                    if (c0 + 1 > r0g) sc[j][1] = -1e30f;
                    if (c0     > r1g) sc[j][2] = -1e30f;
                    if (c0 + 1 > r1g) sc[j][3] = -1e30f;
                }
            }

            float mx0 = -1e30f, mx1 = -1e30f;
            #pragma unroll
            for (int j = 0; j < 8; j++) {
                mx0 = fmaxf(mx0, fmaxf(sc[j][0], sc[j][1]));
                mx1 = fmaxf(mx1, fmaxf(sc[j][2], sc[j][3]));
            }
            mx0 = fmaxf(mx0, __shfl_xor_sync(0xffffffffu, mx0, 1));
            mx0 = fmaxf(mx0, __shfl_xor_sync(0xffffffffu, mx0, 2));
            mx1 = fmaxf(mx1, __shfl_xor_sync(0xffffffffu, mx1, 1));
            mx1 = fmaxf(mx1, __shfl_xor_sync(0xffffffffu, mx1, 2));
            float mn0 = fmaxf(mrow[0], mx0), mn1 = fmaxf(mrow[1], mx1);
            float s0 = __expf(mrow[0] - mn0), s1 = __expf(mrow[1] - mn1);
            float ls0 = 0.f, ls1 = 0.f;
            #pragma unroll
            for (int j = 0; j < 8; j++) {
                sc[j][0] = __expf(sc[j][0] - mn0);
                sc[j][1] = __expf(sc[j][1] - mn0);
                sc[j][2] = __expf(sc[j][2] - mn1);
                sc[j][3] = __expf(sc[j][3] - mn1);
                ls0 += sc[j][0] + sc[j][1];
                ls1 += sc[j][2] + sc[j][3];
            }
            ls0 += __shfl_xor_sync(0xffffffffu, ls0, 1);
            ls0 += __shfl_xor_sync(0xffffffffu, ls0, 2);
            ls1 += __shfl_xor_sync(0xffffffffu, ls1, 1);
            ls1 += __shfl_xor_sync(0xffffffffu, ls1, 2);
            lrow[0] = lrow[0]*s0 + ls0;
            lrow[1] = lrow[1]*s1 + ls1;
            mrow[0] = mn0; mrow[1] = mn1;
            #pragma unroll
            for (int j = 0; j < 8; j++) {
                oc[j][0] *= s0; oc[j][1] *= s0;
                oc[j][2] *= s1; oc[j][3] *= s1;
            }

            uint32_t pa[4][4];
            #pragma unroll
            for (int kk = 0; kk < 4; kk++) {
                pa[kk][0] = packbf(sc[2*kk][0],   sc[2*kk][1]);
                pa[kk][1] = packbf(sc[2*kk][2],   sc[2*kk][3]);
                pa[kk][2] = packbf(sc[2*kk+1][0], sc[2*kk+1][1]);
                pa[kk][3] = packbf(sc[2*kk+1][2], sc[2*kk+1][3]);
            }
            #pragma unroll
            for (int kk = 0; kk < 4; kk++) {
                #pragma unroll
                for (int j = 0; j < 8; j++) {
                    uint32_t b0 = *(const uint32_t*)&Vt[(j*8+g)*VSTR + kk*16 + tg*2];
                    uint32_t b1 = *(const uint32_t*)&Vt[(j*8+g)*VSTR + kk*16 + tg*2 + 8];
                    mma_bf16(oc[j], pa[kk][0], pa[kk][1], pa[kk][2], pa[kk][3], b0, b1);
                }
            }
            __syncthreads();
        }
    }

    // write partials (unnormalized O, m, l)
    size_t pb = (size_t)z * NH * SEQ;
    int r0 = q0 + wq + g, r1 = r0 + 8;
    size_t hr0 = (size_t)h*SEQ + r0, hr1 = (size_t)h*SEQ + r1;
    #pragma unroll
    for (int j = 0; j < 8; j++) {
        int c0 = j*8 + tg*2;
        float2 v0; v0.x = oc[j][0]; v0.y = oc[j][1];
        float2 v1; v1.x = oc[j][2]; v1.y = oc[j][3];
        *(float2*)&g_po[(pb + hr0)*HDIM + c0] = v0;
        *(float2*)&g_po[(pb + hr1)*HDIM + c0] = v1;
    }
    if (tg == 0) {
        g_pm[pb + hr0] = mrow[0];
        g_pm[pb + hr1] = mrow[1];
        g_pl[pb + hr0] = lrow[0];
        g_pl[pb + hr1] = lrow[1];
    }
}

// ---------------- split-K reduce: merge 2 partials -> y_bf ------------------
__global__ void attn_reduce_kernel()
{
    int i = blockIdx.x * blockDim.x + threadIdx.x;
    if (i >= NH*SEQ*(HDIM/2)) return;
    int hrow = i >> 5;
    int c2 = (i & 31) * 2;
    int h = hrow / SEQ, row = hrow % SEQ;
    float m0 = g_pm[hrow],          m1 = g_pm[NH*SEQ + hrow];
    float l0 = g_pl[hrow],          l1 = g_pl[NH*SEQ + hrow];
    float M = fmaxf(m0, m1);
    float w0 = __expf(m0 - M), w1 = __expf(m1 - M);
    float inv = 1.f / (l0*w0 + l1*w1);
    float2 o0 = *(const float2*)&g_po[(size_t)hrow*HDIM + c2];
    float2 o1 = *(const float2*)&g_po[((size_t)NH*SEQ + hrow)*HDIM + c2];
    float vx = (o0.x*w0 + o1.x*w1) * inv;
    float vy = (o0.y*w0 + o1.y*w1) * inv;
    *(__nv_bfloat162*)(g_y_bf + (size_t)row*DM + h*HDIM + c2) =
        __floats2bfloat162_rn(vx, vy);
}

// ---------------- gating ----------------------------------------------------
__global__ __launch_bounds__(256) void gating_kernel(const float* __restrict__ gw)
{
    int t = blockIdx.x;
    int tid = threadIdx.x;
    int e = tid >> 5, lane = tid & 31;
    float s = 0.f;
    const float* hr = g_hf + (size_t)t*DM;
    const float* wr = gw + (size_t)e*DM;
    for (int d = lane; d < DM; d += 32) s += hr[d]*wr[d];
    #pragma unroll
    for (int ofs = 16; ofs > 0; ofs >>= 1) s += __shfl_down_sync(0xffffffffu, s, ofs);
    __shared__ float lg[NE];
    if (lane == 0) lg[e] = s;
    __syncthreads();
    if (tid == 0) {
        float mx = lg[0];
        #pragma unroll
        for (int i = 1; i < NE; i++) mx = fmaxf(mx, lg[i]);
        float p[NE]; float den = 0.f;
        #pragma unroll
        for (int i = 0; i < NE; i++) { p[i] = expf(lg[i]-mx); den += p[i]; }
        #pragma unroll
        for (int i = 0; i < NE; i++) p[i] /= den;
        int i1 = 0;
        #pragma unroll
        for (int i = 1; i < NE; i++) if (p[i] > p[i1]) i1 = i;
        int i2 = (i1 == 0) ? 1 : 0;
        #pragma unroll
        for (int i = 0; i < NE; i++) if (i != i1 && p[i] > p[i2]) i2 = i;
        float w1 = p[i1], w2 = p[i2];
        float sw2 = w1 + w2;
        w1 /= sw2; w2 /= sw2;
        int pos1 = atomicAdd(&g_cnt[i1], 1);
        g_slot[i1*SEQ + pos1] = 2*t;
        g_wslot[2*t] = w1;
        int pos2 = atomicAdd(&g_cnt[i2], 1);
        g_slot[i2*SEQ + pos2] = 2*t + 1;
        g_wslot[2*t+1] = w2;
    }
}

// ---------------- final combine ---------------------------------------------
__global__ __launch_bounds__(256) void combine_kernel(float* __restrict__ out)
{
    int t = blockIdx.x;
    int tid = threadIdx.x;
    float w0 = g_wslot[2*t], w1 = g_wslot[2*t+1];
    float4 hv = ((const float4*)(g_h + (size_t)t*DM))[tid];
    float4 a = ((const float4*)(g_os + (size_t)(2*t)*DM))[tid];
    float4 b = ((const float4*)(g_os + (size_t)(2*t+1)*DM))[tid];
    float4 o;
    o.x = hv.x + w0*a.x + w1*b.x;
    o.y = hv.y + w0*a.y + w1*b.y;
    o.z = hv.z + w0*a.z + w1*b.z;
    o.w = hv.w + w0*a.w + w1*b.w;
    ((float4*)(out + (size_t)t*DM))[tid] = o;
}

// ---------------- host launch ----------------------------------------------
#define GEMM_SMEM (6*GSTG)
#define W13_SMEM  (9*GSTG)

extern "C" void kernel_launch(void* const* d_in, const int* in_sizes, int n_in,
                              void* d_out, int out_size)
{
    const float* x      = (const float*)d_in[0];
    const float* wqkv   = (const float*)d_in[1];
    const float* wo     = (const float*)d_in[2];
    const float* gate_w = (const float*)d_in[3];
    const float* w1     = (const float*)d_in[4];
    const float* w2     = (const float*)d_in[5];
    const float* w3     = (const float*)d_in[6];
    const float* anw    = (const float*)d_in[7];
    const float* fnw    = (const float*)d_in[8];
    const float* freqs  = (const float*)d_in[9];
    float* out = (float*)d_out;

    bf16 *p_wqkv_bf, *p_wo_bf, *p_w1_bf, *p_w3_bf, *p_w2_bf;
    bf16 *p_hn_bf, *p_hf_bf, *p_y_bf, *p_gb;
    float *p_h, *p_hf, *p_os;
    int *p_cnt;
    cudaGetSymbolAddress((void**)&p_wqkv_bf, g_wqkv_bf);
    cudaGetSymbolAddress((void**)&p_wo_bf,   g_wo_bf);
    cudaGetSymbolAddress((void**)&p_w1_bf,   g_w1_bf);
    cudaGetSymbolAddress((void**)&p_w3_bf,   g_w3_bf);
    cudaGetSymbolAddress((void**)&p_w2_bf,   g_w2_bf);
    cudaGetSymbolAddress((void**)&p_hn_bf,   g_hn_bf);
    cudaGetSymbolAddress((void**)&p_hf_bf,   g_hf_bf);
    cudaGetSymbolAddress((void**)&p_y_bf,    g_y_bf);
    cudaGetSymbolAddress((void**)&p_gb,      g_gb);
    cudaGetSymbolAddress((void**)&p_h,       g_h);
    cudaGetSymbolAddress((void**)&p_hf,      g_hf);
    cudaGetSymbolAddress((void**)&p_os,      g_os);
    cudaGetSymbolAddress((void**)&p_cnt,     g_cnt);

    static cudaStream_t s2 = nullptr;
    static cudaEvent_t ev0 = nullptr, ev1 = nullptr;
    static bool attr_set = false;
    if (!attr_set) {
        cudaFuncSetAttribute(gemm_bf<false>,
            cudaFuncAttributeMaxDynamicSharedMemorySize, GEMM_SMEM);
        cudaFuncSetAttribute(gemm_bf<true>,
            cudaFuncAttributeMaxDynamicSharedMemorySize, GEMM_SMEM);
        cudaFuncSetAttribute(gemm_qkv,
            cudaFuncAttributeMaxDynamicSharedMemorySize, GEMM_SMEM);
        cudaFuncSetAttribute(gemm_w13,
            cudaFuncAttributeMaxDynamicSharedMemorySize, W13_SMEM);
        cudaStreamCreateWithFlags(&s2, cudaStreamNonBlocking);
        cudaEventCreateWithFlags(&ev0, cudaEventDisableTiming);
        cudaEventCreateWithFlags(&ev1, cudaEventDisableTiming);
        attr_set = true;
    }

    // ---- fork: big MoE weight converts on side stream
    cudaEventRecord(ev0, 0);
    cudaStreamWaitEvent(s2, ev0, 0);
    {
        int n4 = (int)((size_t)NE*NI*DM/4);
        f2bf_kernel<<<(n4+255)/256, 256, 0, s2>>>((const float4*)w1, (uint2*)p_w1_bf, n4);
        f2bf_kernel<<<(n4+255)/256, 256, 0, s2>>>((const float4*)w3, (uint2*)p_w3_bf, n4);
        f2bf_kernel<<<(n4+255)/256, 256, 0, s2>>>((const float4*)w2, (uint2*)p_w2_bf, n4);
    }
    cudaEventRecord(ev1, s2);

    // ---- main stream: attention path
    {
        int n4 = QKVN*DM/4;
        f2bf_kernel<<<(n4+255)/256, 256>>>((const float4*)wqkv, (uint2*)p_wqkv_bf, n4);
        n4 = DM*DM/4;
        f2bf_kernel<<<(n4+255)/256, 256>>>((const float4*)wo, (uint2*)p_wo_bf, n4);
    }
    rmsnorm_kernel<<<SEQ, 256>>>(x, anw, p_hn_bf, nullptr);
    gemm_qkv<<<dim3(QKVN/128, SEQ/128), 256, GEMM_SMEM>>>(p_hn_bf, p_wqkv_bf, freqs);
    // attention v5: split-K + reduce
    attn5_kernel<<<dim3(SEQ/64, NH, 2), 128>>>();
    attn_reduce_kernel<<<(NH*SEQ*(HDIM/2) + 255)/256, 256>>>();
    gemm_bf<false><<<dim3(DM/128, SEQ/128), 256, GEMM_SMEM>>>(
        p_y_bf, p_wo_bf, x, p_h, SEQ, DM, DM, 0);
    rmsnorm_kernel<<<SEQ, 256>>>(p_h, fnw, p_hf_bf, p_hf);
    cudaMemsetAsync(p_cnt, 0, NE*sizeof(int), 0);
    gating_kernel<<<SEQ, 256>>>(gate_w);

    // ---- join: MoE phase needs converted w1/w3/w2
    cudaStreamWaitEvent(0, ev1, 0);
    gemm_w13<<<dim3(NI/128, SEQ/128, NE), 256, W13_SMEM>>>(
        p_hf_bf, p_w1_bf, p_w3_bf);
    gemm_bf<true><<<dim3(DM/128, SEQ/128, NE), 256, GEMM_SMEM>>>(
        p_gb, p_w2_bf, nullptr, p_os, 0, DM, NI, 0);
    combine_kernel<<<SEQ, 256>>>(out);
}

// round 11
// speedup vs baseline: 1.2005x; 1.0170x over previous
#include <cuda_runtime.h>
#include <cuda_bf16.h>
#include <math.h>
#include <stdint.h>

#define SEQ 2048
#define DM 1024
#define NH 16
#define NKV 4
#define HDIM 64
#define NE 8
#define NI 3584
#define QKVN 1536
#define NSLOTS (2*SEQ)
#define NSPLIT 8
#define CHUNK 4

typedef __nv_bfloat16 bf16;

// ---------------- scratch (device globals; no allocations) ----------------
__device__ bf16  g_wqkv_bf[QKVN*DM];
__device__ bf16  g_wo_bf[DM*DM];
__device__ bf16  g_w1_bf[(size_t)NE*NI*DM];
__device__ bf16  g_w3_bf[(size_t)NE*NI*DM];
__device__ bf16  g_w2_bf[(size_t)NE*DM*NI];
__device__ bf16  g_hn_bf[SEQ*DM];
__device__ float g_q[NH*SEQ*HDIM];      // tf32-rounded, pre-scaled 0.125
__device__ float g_k[NKV*SEQ*HDIM];     // tf32-rounded
__device__ bf16  g_vt[NKV*HDIM*SEQ];    // bf16, transposed [kvh][d][t]
__device__ float g_po[(size_t)NSPLIT*NH*SEQ*HDIM];  // split partial O
__device__ float g_pm[NSPLIT*NH*SEQ];               // partial max
__device__ float g_pl[NSPLIT*NH*SEQ];               // partial sum
__device__ bf16  g_y_bf[SEQ*DM];
__device__ float g_h[SEQ*DM];
__device__ float g_hf[SEQ*DM];
__device__ bf16  g_hf_bf[SEQ*DM];
__device__ int   g_cnt[NE];
__device__ int   g_slot[NE*SEQ];
__device__ float g_wslot[NSLOTS];
__device__ bf16  g_gb[(size_t)NSLOTS*NI];
__device__ float g_os[(size_t)NSLOTS*DM];

// ---------------- helpers ---------------------------------------------------
__device__ __forceinline__ uint32_t f2tf32(float f) {
    uint32_t r;
    asm("cvt.rna.tf32.f32 %0, %1;" : "=r"(r) : "f"(f));
    return r;
}
__device__ __forceinline__ void mma_tf32(float c[4],
    uint32_t a0, uint32_t a1, uint32_t a2, uint32_t a3,
    uint32_t b0, uint32_t b1)
{
    asm volatile(
        "mma.sync.aligned.m16n8k8.row.col.f32.tf32.tf32.f32 "
        "{%0,%1,%2,%3}, {%4,%5,%6,%7}, {%8,%9}, {%0,%1,%2,%3};"
        : "+f"(c[0]), "+f"(c[1]), "+f"(c[2]), "+f"(c[3])
        : "r"(a0), "r"(a1), "r"(a2), "r"(a3), "r"(b0), "r"(b1));
}
__device__ __forceinline__ void mma_bf16(float c[4],
    uint32_t a0, uint32_t a1, uint32_t a2, uint32_t a3,
    uint32_t b0, uint32_t b1)
{
    asm volatile(
        "mma.sync.aligned.m16n8k16.row.col.f32.bf16.bf16.f32 "
        "{%0,%1,%2,%3}, {%4,%5,%6,%7}, {%8,%9}, {%0,%1,%2,%3};"
        : "+f"(c[0]), "+f"(c[1]), "+f"(c[2]), "+f"(c[3])
        : "r"(a0), "r"(a1), "r"(a2), "r"(a3), "r"(b0), "r"(b1));
}
__device__ __forceinline__ void ldsm4(uint32_t r[4], uint32_t addr) {
    asm volatile("ldmatrix.sync.aligned.m8n8.x4.shared.b16 {%0,%1,%2,%3}, [%4];"
                 : "=r"(r[0]), "=r"(r[1]), "=r"(r[2]), "=r"(r[3]) : "r"(addr));
}
__device__ __forceinline__ void cpa(uint32_t dst, const void* src, int sz) {
    asm volatile("cp.async.cg.shared.global [%0], [%1], 16, %2;"
                 :: "r"(dst), "l"(src), "r"(sz));
}
__device__ __forceinline__ uint32_t packbf(float a, float b) {
    __nv_bfloat162 p = __floats2bfloat162_rn(a, b);
    return *(uint32_t*)&p;
}

// ---------------- fp32 -> bf16 convert --------------------------------------
__global__ void f2bf_kernel(const float4* __restrict__ s, uint2* __restrict__ d, int n4)
{
    int i = blockIdx.x * blockDim.x + threadIdx.x;
    if (i >= n4) return;
    float4 v = s[i];
    __nv_bfloat162 lo = __floats2bfloat162_rn(v.x, v.y);
    __nv_bfloat162 hi = __floats2bfloat162_rn(v.z, v.w);
    uint2 o;
    o.x = *(uint32_t*)&lo;
    o.y = *(uint32_t*)&hi;
    d[i] = o;
}

// ---------------- rmsnorm (bf16 out + optional fp32 out) -------------------
__global__ __launch_bounds__(256) void rmsnorm_kernel(
    const float* __restrict__ x, const float* __restrict__ w,
    bf16* __restrict__ obf, float* __restrict__ ofp)
{
    int row = blockIdx.x;
    int tid = threadIdx.x;
    const float4* xr = (const float4*)(x + (size_t)row*DM);
    float4 v = xr[tid];
    float ss = v.x*v.x + v.y*v.y + v.z*v.z + v.w*v.w;
    __shared__ float red[8];
    #pragma unroll
    for (int ofs = 16; ofs > 0; ofs >>= 1) ss += __shfl_down_sync(0xffffffffu, ss, ofs);
    if ((tid & 31) == 0) red[tid >> 5] = ss;
    __syncthreads();
    __shared__ float sr;
    if (tid == 0) {
        float t = 0.f;
        #pragma unroll
        for (int i = 0; i < 8; i++) t += red[i];
        sr = rsqrtf(t / (float)DM + 1e-5f);
    }
    __syncthreads();
    float r = sr;
    float4 wv = ((const float4*)w)[tid];
    float4 o;
    o.x = v.x*r*wv.x; o.y = v.y*r*wv.y; o.z = v.z*r*wv.z; o.w = v.w*r*wv.w;
    __nv_bfloat162 lo = __floats2bfloat162_rn(o.x, o.y);
    __nv_bfloat162 hi = __floats2bfloat162_rn(o.z, o.w);
    uint2 ob; ob.x = *(uint32_t*)&lo; ob.y = *(uint32_t*)&hi;
    *(uint2*)(obf + (size_t)row*DM + tid*4) = ob;
    if (ofp) ((float4*)(ofp + (size_t)row*DM))[tid] = o;
}

// ---------------- bf16 HMMA GEMM: C[M,N] = A @ B^T (+resid) ----------------
#define GSTG 16384
template<bool GATHER>
__global__ __launch_bounds__(256) void gemm_bf(
    const bf16* __restrict__ A, const bf16* __restrict__ B,
    const float* __restrict__ resid, float* __restrict__ C,
    int M, int N, int K, int shiftA)
{
    extern __shared__ char smem[];
    const int* sl = nullptr;
    if (GATHER) {
        int e = blockIdx.z;
        M = g_cnt[e];
        if ((int)blockIdx.y * 128 >= M) return;
        sl = g_slot + e * SEQ;
        B += (size_t)e * N * K;
    }
    int m0 = blockIdx.y * 128, n0 = blockIdx.x * 128;
    int tid = threadIdx.x, warp = tid >> 5, lane = tid & 31;
    int wm = (warp >> 2) * 64, wn = (warp & 3) * 32;
    uint32_t sbase = (uint32_t)__cvta_generic_to_shared(smem);
    uint32_t aoff[3], boff[3];
    #pragma unroll
    for (int s = 0; s < 3; s++) {
        aoff[s] = sbase + s*GSTG;
        boff[s] = sbase + 3*GSTG + s*GSTG;
    }

    int lrow = tid >> 1;
    int lsg  = (tid & 1) * 4;
    const bf16* Arow; int szA = 16;
    if (GATHER) {
        int gm = m0 + lrow;
        if (gm < M) Arow = A + (size_t)(sl[gm] >> shiftA) * K;
        else { Arow = A; szA = 0; }
    } else {
        Arow = A + (size_t)(m0 + lrow) * K;
    }
    const bf16* Brow = B + (size_t)(n0 + lrow) * K;
    uint32_t dsw = (uint32_t)lrow * 128u;
    int rxor = lrow & 7;

    float acc[4][4][4];
    #pragma unroll
    for (int i = 0; i < 4; i++)
        #pragma unroll
        for (int j = 0; j < 4; j++)
            #pragma unroll
            for (int q = 0; q < 4; q++) acc[i][j][q] = 0.f;

    int CC = K / 64;
    auto loadChunk = [&](int c) {
        int s = c % 3;
        const char* pa = (const char*)(Arow + c*64);
        const char* pb = (const char*)(Brow + c*64);
        #pragma unroll
        for (int i = 0; i < 4; i++) {
            int seg = lsg + i;
            uint32_t o = dsw + (uint32_t)((seg ^ rxor) * 16);
            cpa(aoff[s] + o, pa + seg*16, szA);
            cpa(boff[s] + o, pb + seg*16, 16);
        }
        asm volatile("cp.async.commit_group;" ::: "memory");
    };
    loadChunk(0);
    if (CC > 1) loadChunk(1);

    int lt = lane >> 3;
    int rl = lane & 7;
    int th = (lt & 1) * 8;
    int ts = lane >> 4;

    for (int c = 0; c < CC; c++) {
        if (c + 1 < CC) asm volatile("cp.async.wait_group 1;" ::: "memory");
        else            asm volatile("cp.async.wait_group 0;" ::: "memory");
        __syncthreads();
        if (c + 2 < CC) loadChunk(c + 2);

        uint32_t Ab = aoff[c % 3], Bb = boff[c % 3];
        #pragma unroll
        for (int kk = 0; kk < 4; kk++) {
            uint32_t af[4][4], bfm[2][4];
            #pragma unroll
            for (int i = 0; i < 4; i++) {
                int row = wm + i*16 + th + rl;
                int seg = 2*kk + ts;
                ldsm4(af[i], Ab + row*128 + ((seg ^ (row & 7)) << 4));
            }
            #pragma unroll
            for (int j = 0; j < 2; j++) {
                int nr = wn + j*16 + th + rl;
                int seg = 2*kk + ts;
                ldsm4(bfm[j], Bb + nr*128 + ((seg ^ (nr & 7)) << 4));
            }
            #pragma unroll
            for (int i = 0; i < 4; i++)
                #pragma unroll
                for (int jn = 0; jn < 4; jn++) {
                    int jj = jn >> 1, hi = jn & 1;
                    mma_bf16(acc[i][jn], af[i][0], af[i][1], af[i][2], af[i][3],
                             bfm[jj][hi], bfm[jj][hi+2]);
                }
        }
        __syncthreads();
    }

    int g = lane >> 2, tg = lane & 3;
    #pragma unroll
    for (int i = 0; i < 4; i++) {
        int r0 = m0 + wm + i*16 + g;
        int r1 = r0 + 8;
        bool v0, v1;
        int row0, row1;
        if (GATHER) {
            v0 = r0 < M; v1 = r1 < M;
            row0 = v0 ? sl[r0] : 0;
            row1 = v1 ? sl[r1] : 0;
        } else {
            v0 = v1 = true; row0 = r0; row1 = r1;
        }
        #pragma unroll
        for (int j = 0; j < 4; j++) {
            int c0 = n0 + wn + j*8 + tg*2;
            if (v0) {
                float2 v; v.x = acc[i][j][0]; v.y = acc[i][j][1];
                if (resid) {
                    v.x += resid[(size_t)row0*N + c0];
                    v.y += resid[(size_t)row0*N + c0 + 1];
                }
                *(float2*)(C + (size_t)row0*N + c0) = v;
            }
            if (v1) {
                float2 v; v.x = acc[i][j][2]; v.y = acc[i][j][3];
                if (resid) {
                    v.x += resid[(size_t)row1*N + c0];
                    v.y += resid[(size_t)row1*N + c0 + 1];
                }
                *(float2*)(C + (size_t)row1*N + c0) = v;
            }
        }
    }
}

// ---------------- QKV GEMM with fused RoPE/split epilogue -------------------
__device__ __forceinline__ void rope_write(
    int t, int c0, float vx, float vy, const float* __restrict__ freqs)
{
    if (c0 < DM) {
        int h = c0 >> 6, d = c0 & 63, p = d >> 1;
        float cs = freqs[((size_t)t*32 + p)*2 + 0];
        float sn = freqs[((size_t)t*32 + p)*2 + 1];
        float2 o;
        o.x = __uint_as_float(f2tf32((vx*cs - vy*sn) * 0.125f));
        o.y = __uint_as_float(f2tf32((vy*cs + vx*sn) * 0.125f));
        *(float2*)(g_q + ((size_t)h*SEQ + t)*HDIM + d) = o;
    } else if (c0 < DM + NKV*HDIM) {
        int c = c0 - DM;
        int kh = c >> 6, d = c & 63, p = d >> 1;
        float cs = freqs[((size_t)t*32 + p)*2 + 0];
        float sn = freqs[((size_t)t*32 + p)*2 + 1];
        float2 o;
        o.x = __uint_as_float(f2tf32(vx*cs - vy*sn));
        o.y = __uint_as_float(f2tf32(vy*cs + vx*sn));
        *(float2*)(g_k + ((size_t)kh*SEQ + t)*HDIM + d) = o;
    } else {
        int c = c0 - DM - NKV*HDIM;
        int vh = c >> 6, d = c & 63;
        g_vt[((size_t)(vh*HDIM + d  ))*SEQ + t] = __float2bfloat16(vx);
        g_vt[((size_t)(vh*HDIM + d+1))*SEQ + t] = __float2bfloat16(vy);
    }
}

__global__ __launch_bounds__(256) void gemm_qkv(
    const bf16* __restrict__ A, const bf16* __restrict__ B,
    const float* __restrict__ freqs)
{
    extern __shared__ char smem[];
    const int K = DM;
    int m0 = blockIdx.y * 128, n0 = blockIdx.x * 128;
    int tid = threadIdx.x, warp = tid >> 5, lane = tid & 31;
    int wm = (warp >> 2) * 64, wn = (warp & 3) * 32;
    uint32_t sbase = (uint32_t)__cvta_generic_to_shared(smem);
    uint32_t aoff[3], boff[3];
    #pragma unroll
    for (int s = 0; s < 3; s++) {
        aoff[s] = sbase + s*GSTG;
        boff[s] = sbase + 3*GSTG + s*GSTG;
    }

    int lrow = tid >> 1;
    int lsg  = (tid & 1) * 4;
    const bf16* Arow = A + (size_t)(m0 + lrow) * K;
    const bf16* Brow = B + (size_t)(n0 + lrow) * K;
    uint32_t dsw = (uint32_t)lrow * 128u;
    int rxor = lrow & 7;

    float acc[4][4][4];
    #pragma unroll
    for (int i = 0; i < 4; i++)
        #pragma unroll
        for (int j = 0; j < 4; j++)
            #pragma unroll
            for (int q = 0; q < 4; q++) acc[i][j][q] = 0.f;

    const int CC = K / 64;
    auto loadChunk = [&](int c) {
        int s = c % 3;
        const char* pa = (const char*)(Arow + c*64);
        const char* pb = (const char*)(Brow + c*64);
        #pragma unroll
        for (int i = 0; i < 4; i++) {
            int seg = lsg + i;
            uint32_t o = dsw + (uint32_t)((seg ^ rxor) * 16);
            cpa(aoff[s] + o, pa + seg*16, 16);
            cpa(boff[s] + o, pb + seg*16, 16);
        }
        asm volatile("cp.async.commit_group;" ::: "memory");
    };
    loadChunk(0);
    loadChunk(1);

    int lt = lane >> 3;
    int rl = lane & 7;
    int th = (lt & 1) * 8;
    int ts = lane >> 4;

    for (int c = 0; c < CC; c++) {
        if (c + 1 < CC) asm volatile("cp.async.wait_group 1;" ::: "memory");
        else            asm volatile("cp.async.wait_group 0;" ::: "memory");
        __syncthreads();
        if (c + 2 < CC) loadChunk(c + 2);

        uint32_t Ab = aoff[c % 3], Bb = boff[c % 3];
        #pragma unroll
        for (int kk = 0; kk < 4; kk++) {
            uint32_t af[4][4], bfm[2][4];
            #pragma unroll
            for (int i = 0; i < 4; i++) {
                int row = wm + i*16 + th + rl;
                int seg = 2*kk + ts;
                ldsm4(af[i], Ab + row*128 + ((seg ^ (row & 7)) << 4));
            }
            #pragma unroll
            for (int j = 0; j < 2; j++) {
                int nr = wn + j*16 + th + rl;
                int seg = 2*kk + ts;
                ldsm4(bfm[j], Bb + nr*128 + ((seg ^ (nr & 7)) << 4));
            }
            #pragma unroll
            for (int i = 0; i < 4; i++)
                #pragma unroll
                for (int jn = 0; jn < 4; jn++) {
                    int jj = jn >> 1, hi = jn & 1;
                    mma_bf16(acc[i][jn], af[i][0], af[i][1], af[i][2], af[i][3],
                             bfm[jj][hi], bfm[jj][hi+2]);
                }
        }
        __syncthreads();
    }

    int g = lane >> 2, tg = lane & 3;
    #pragma unroll
    for (int i = 0; i < 4; i++) {
        int t0 = m0 + wm + i*16 + g;
        int t1 = t0 + 8;
        #pragma unroll
        for (int j = 0; j < 4; j++) {
            int c0 = n0 + wn + j*8 + tg*2;
            rope_write(t0, c0, acc[i][j][0], acc[i][j][1], freqs);
            rope_write(t1, c0, acc[i][j][2], acc[i][j][3], freqs);
        }
    }
}

// ---------------- fused MoE w1/w3 GEMM + silu*mul (bf16 out) ---------------
__global__ __launch_bounds__(256) void gemm_w13(
    const bf16* __restrict__ A, const bf16* __restrict__ B1,
    const bf16* __restrict__ B3)
{
    extern __shared__ char smem[];
    int e = blockIdx.z;
    int M = g_cnt[e];
    if ((int)blockIdx.y * 128 >= M) return;
    const int* sl = g_slot + e * SEQ;
    B1 += (size_t)e * NI * DM;
    B3 += (size_t)e * NI * DM;

    int m0 = blockIdx.y * 128, n0 = blockIdx.x * 128;
    int tid = threadIdx.x, warp = tid >> 5, lane = tid & 31;
    int wm = (warp >> 2) * 64, wn = (warp & 3) * 32;
    uint32_t sbase = (uint32_t)__cvta_generic_to_shared(smem);
    uint32_t aoff[3], b1off[3], b3off[3];
    #pragma unroll
    for (int s = 0; s < 3; s++) {
        aoff[s]  = sbase + s*GSTG;
        b1off[s] = sbase + 3*GSTG + s*GSTG;
        b3off[s] = sbase + 6*GSTG + s*GSTG;
    }

    int lrow = tid >> 1;
    int lsg  = (tid & 1) * 4;
    const bf16* Arow; int szA = 16;
    {
        int gm = m0 + lrow;
        if (gm < M) Arow = A + (size_t)(sl[gm] >> 1) * DM;
        else { Arow = A; szA = 0; }
    }
    const bf16* B1row = B1 + (size_t)(n0 + lrow) * DM;
    const bf16* B3row = B3 + (size_t)(n0 + lrow) * DM;
    uint32_t dsw = (uint32_t)lrow * 128u;
    int rxor = lrow & 7;

    float ac1[4][4][4], ac3[4][4][4];
    #pragma unroll
    for (int i = 0; i < 4; i++)
        #pragma unroll
        for (int j = 0; j < 4; j++)
            #pragma unroll
            for (int q = 0; q < 4; q++) { ac1[i][j][q] = 0.f; ac3[i][j][q] = 0.f; }

    const int CC = DM / 64;
    auto loadChunk = [&](int c) {
        int s = c % 3;
        const char* pa  = (const char*)(Arow  + c*64);
        const char* pb1 = (const char*)(B1row + c*64);
        const char* pb3 = (const char*)(B3row + c*64);
        #pragma unroll
        for (int i = 0; i < 4; i++) {
            int seg = lsg + i;
            uint32_t o = dsw + (uint32_t)((seg ^ rxor) * 16);
            cpa(aoff[s]  + o, pa  + seg*16, szA);
            cpa(b1off[s] + o, pb1 + seg*16, 16);
            cpa(b3off[s] + o, pb3 + seg*16, 16);
        }
        asm volatile("cp.async.commit_group;" ::: "memory");
    };
    loadChunk(0);
    loadChunk(1);

    int lt = lane >> 3, rl = lane & 7;
    int th = (lt & 1) * 8;
    int ts = lane >> 4;

    for (int c = 0; c < CC; c++) {
        if (c + 1 < CC) asm volatile("cp.async.wait_group 1;" ::: "memory");
        else            asm volatile("cp.async.wait_group 0;" ::: "memory");
        __syncthreads();
        if (c + 2 < CC) loadChunk(c + 2);

        uint32_t Ab = aoff[c % 3], B1b = b1off[c % 3], B3b = b3off[c % 3];
        #pragma unroll
        for (int kk = 0; kk < 4; kk++) {
            uint32_t af[4][4], f1[2][4], f3[2][4];
            #pragma unroll
            for (int i = 0; i < 4; i++) {
                int row = wm + i*16 + th + rl;
                int seg = 2*kk + ts;
                ldsm4(af[i], Ab + row*128 + ((seg ^ (row & 7)) << 4));
            }
            #pragma unroll
            for (int j = 0; j < 2; j++) {
                int nr = wn + j*16 + th + rl;
                int seg = 2*kk + ts;
                ldsm4(f1[j], B1b + nr*128 + ((seg ^ (nr & 7)) << 4));
                ldsm4(f3[j], B3b + nr*128 + ((seg ^ (nr & 7)) << 4));
            }
            #pragma unroll
            for (int i = 0; i < 4; i++)
                #pragma unroll
                for (int jn = 0; jn < 4; jn++) {
                    int jj = jn >> 1, hi = jn & 1;
                    mma_bf16(ac1[i][jn], af[i][0], af[i][1], af[i][2], af[i][3],
                             f1[jj][hi], f1[jj][hi+2]);
                    mma_bf16(ac3[i][jn], af[i][0], af[i][1], af[i][2], af[i][3],
                             f3[jj][hi], f3[jj][hi+2]);
                }
        }
        __syncthreads();
    }

    int g = lane >> 2, tg = lane & 3;
    #pragma unroll
    for (int i = 0; i < 4; i++) {
        int r0 = m0 + wm + i*16 + g;
        int r1 = r0 + 8;
        bool v0 = r0 < M, v1 = r1 < M;
        int row0 = v0 ? sl[r0] : 0;
        int row1 = v1 ? sl[r1] : 0;
        #pragma unroll
        for (int j = 0; j < 4; j++) {
            int c0 = n0 + wn + j*8 + tg*2;
            if (v0) {
                float a0 = ac1[i][j][0], a1 = ac1[i][j][1];
                float u0 = a0 / (1.f + __expf(-a0)) * ac3[i][j][0];
                float u1 = a1 / (1.f + __expf(-a1)) * ac3[i][j][1];
                *(__nv_bfloat162*)(g_gb + (size_t)row0*NI + c0) = __floats2bfloat162_rn(u0, u1);
            }
            if (v1) {
                float a0 = ac1[i][j][2], a1 = ac1[i][j][3];
                float u0 = a0 / (1.f + __expf(-a0)) * ac3[i][j][2];
                float u1 = a1 / (1.f + __expf(-a1)) * ac3[i][j][3];
                *(__nv_bfloat162*)(g_gb + (size_t)row1*NI + c0) = __floats2bfloat162_rn(u0, u1);
            }
        }
    }
}

// ---------------- attention v6: uniform-chunk split flash -------------------
// grid (32, NH, NSPLIT), 128 threads. Chunk z covers kt in
// [z*CHUNK, min(qt+1, z*CHUNK+CHUNK)); empty chunks write neutral partials.
#define ASTR 68
#define VSTR 72
__global__ __launch_bounds__(128) void attn6_kernel()
{
    __shared__ float Ks[64*ASTR];
    __shared__ bf16  Vt[64*VSTR];

    int qt = blockIdx.x, h = blockIdx.y, z = blockIdx.z;
    int kvh = h >> 2;
    int tid = threadIdx.x, warp = tid >> 5, lane = tid & 31;
    int g = lane >> 2, tg = lane & 3;
    int wq = warp * 16;
    int q0 = qt * 64;

    int n = qt + 1;
    int lo = z * CHUNK;
    int hi = min(n, lo + CHUNK);

    float oc[8][4];
    #pragma unroll
    for (int j = 0; j < 8; j++)
        #pragma unroll
        for (int q = 0; q < 4; q++) oc[j][q] = 0.f;
    float mrow[2] = {-1e30f, -1e30f};
    float lrow[2] = {0.f, 0.f};

    if (lo < hi) {
        for (int i = tid; i < 64*16; i += 128) {
            int row = i >> 4, c4 = (i & 15) * 4;
            *(float4*)&Ks[row*ASTR + c4] =
                *(const float4*)(g_q + ((size_t)h*SEQ + q0 + row)*HDIM + c4);
        }
        __syncthreads();
        uint32_t aq[8][4];
        #pragma unroll
        for (int kk = 0; kk < 8; kk++) {
            aq[kk][0] = __float_as_uint(Ks[(wq+g)*ASTR + kk*8 + tg]);
            aq[kk][1] = __float_as_uint(Ks[(wq+g+8)*ASTR + kk*8 + tg]);
            aq[kk][2] = __float_as_uint(Ks[(wq+g)*ASTR + kk*8 + tg + 4]);
            aq[kk][3] = __float_as_uint(Ks[(wq+g+8)*ASTR + kk*8 + tg + 4]);
        }
        __syncthreads();

        for (int kt = lo; kt < hi; kt++) {
            for (int i = tid; i < 1024; i += 128) {
                int row = i >> 4, c4 = (i & 15) * 4;
                *(float4*)&Ks[row*ASTR + c4] =
                    *(const float4*)(g_k + ((size_t)kvh*SEQ + kt*64 + row)*HDIM + c4);
            }
            for (int i = tid; i < 512; i += 128) {
                int row = i >> 3, seg = i & 7;
                *(uint4*)&Vt[row*VSTR + seg*8] =
                    *(const uint4*)(g_vt + ((size_t)(kvh*HDIM + row))*SEQ + kt*64 + seg*8);
            }
            __syncthreads();

            float sc[8][4];
            #pragma unroll
            for (int j = 0; j < 8; j++)
                #pragma unroll
                for (int q = 0; q < 4; q++) sc[j][q] = 0.f;
            #pragma unroll
            for (int kk = 0; kk < 8; kk++) {
                #pragma unroll
                for (int j = 0; j < 8; j++) {
                    uint32_t b0 = __float_as_uint(Ks[(j*8+g)*ASTR + kk*8 + tg]);
                    uint32_t b1 = __float_as_uint(Ks[(j*8+g)*ASTR + kk*8 + tg + 4]);
                    mma_tf32(sc[j], aq[kk][0], aq[kk][1], aq[kk][2], aq[kk][3], b0, b1);
                }
            }

            if (kt == qt) {
                int r0g = q0 + wq + g, r1g = r0g + 8;
                #pragma unroll
                for (int j = 0; j < 8; j++) {
                    int c0 = kt*64 + j*8 + tg*2;
                    if (c0     > r0g) sc[j][0] = -1e30f;
                    if (c0 + 1 > r0g) sc[j][1] = -1e30f;
                    if (c0     > r1g) sc[j][2] = -1e30f;
                    if (c0 + 1 > r1g) sc[j][3] = -1e30f;
                }
            }

            float mx0 = -1e30f, mx1 = -1e30f;
            #pragma unroll
            for (int j = 0; j < 8; j++) {
                mx0 = fmaxf(mx0, fmaxf(sc[j][0], sc[j][1]));
                mx1 = fmaxf(mx1, fmaxf(sc[j][2], sc[j][3]));
            }
            mx0 = fmaxf(mx0, __shfl_xor_sync(0xffffffffu, mx0, 1));
            mx0 = fmaxf(mx0, __shfl_xor_sync(0xffffffffu, mx0, 2));
            mx1 = fmaxf(mx1, __shfl_xor_sync(0xffffffffu, mx1, 1));
            mx1 = fmaxf(mx1, __shfl_xor_sync(0xffffffffu, mx1, 2));
            float mn0 = fmaxf(mrow[0], mx0), mn1 = fmaxf(mrow[1], mx1);
            float s0 = __expf(mrow[0] - mn0), s1 = __expf(mrow[1] - mn1);
            float ls0 = 0.f, ls1 = 0.f;
            #pragma unroll
            for (int j = 0; j < 8; j++) {
                sc[j][0] = __expf(sc[j][0] - mn0);
                sc[j][1] = __expf(sc[j][1] - mn0);
                sc[j][2] = __expf(sc[j][2] - mn1);
                sc[j][3] = __expf(sc[j][3] - mn1);
                ls0 += sc[j][0] + sc[j][1];
                ls1 += sc[j][2] + sc[j][3];
            }
            ls0 += __shfl_xor_sync(0xffffffffu, ls0, 1);
            ls0 += __shfl_xor_sync(0xffffffffu, ls0, 2);
            ls1 += __shfl_xor_sync(0xffffffffu, ls1, 1);
            ls1 += __shfl_xor_sync(0xffffffffu, ls1, 2);
            lrow[0] = lrow[0]*s0 + ls0;
            lrow[1] = lrow[1]*s1 + ls1;
            mrow[0] = mn0; mrow[1] = mn1;
            #pragma unroll
            for (int j = 0; j < 8; j++) {
                oc[j][0] *= s0; oc[j][1] *= s0;
                oc[j][2] *= s1; oc[j][3] *= s1;
            }

            uint32_t pa[4][4];
            #pragma unroll
            for (int kk = 0; kk < 4; kk++) {
                pa[kk][0] = packbf(sc[2*kk][0],   sc[2*kk][1]);
                pa[kk][1] = packbf(sc[2*kk][2],   sc[2*kk][3]);
                pa[kk][2] = packbf(sc[2*kk+1][0], sc[2*kk+1][1]);
                pa[kk][3] = packbf(sc[2*kk+1][2], sc[2*kk+1][3]);
            }
            #pragma unroll
            for (int kk = 0; kk < 4; kk++) {
                #pragma unroll
                for (int j = 0; j < 8; j++) {
                    uint32_t b0 = *(const uint32_t*)&Vt[(j*8+g)*VSTR + kk*16 + tg*2];
                    uint32_t b1 = *(const uint32_t*)&Vt[(j*8+g)*VSTR + kk*16 + tg*2 + 8];
                    mma_bf16(oc[j], pa[kk][0], pa[kk][1], pa[kk][2], pa[kk][3], b0, b1);
                }
            }
            __syncthreads();
        }
    }

    size_t pb = (size_t)z * NH * SEQ;
    int r0 = q0 + wq + g, r1 = r0 + 8;
    size_t hr0 = (size_t)h*SEQ + r0, hr1 = (size_t)h*SEQ + r1;
    #pragma unroll
    for (int j = 0; j < 8; j++) {
        int c0 = j*8 + tg*2;
        float2 v0; v0.x = oc[j][0]; v0.y = oc[j][1];
        float2 v1; v1.x = oc[j][2]; v1.y = oc[j][3];
        *(float2*)&g_po[(pb + hr0)*HDIM + c0] = v0;
        *(float2*)&g_po[(pb + hr1)*HDIM + c0] = v1;
    }
    if (tg == 0) {
        g_pm[pb + hr0] = mrow[0];
        g_pm[pb + hr1] = mrow[1];
        g_pl[pb + hr0] = lrow[0];
        g_pl[pb + hr1] = lrow[1];
    }
}

// ---------------- split reduce: merge NSPLIT partials -> y_bf ---------------
__global__ void attn_reduce_kernel()
{
    int i = blockIdx.x * blockDim.x + threadIdx.x;
    if (i >= NH*SEQ*(HDIM/2)) return;
    int hrow = i >> 5;
    int c2 = (i & 31) * 2;
    int h = hrow / SEQ, row = hrow % SEQ;
    float M = -1e30f;
    float ms[NSPLIT], ls[NSPLIT];
    #pragma unroll
    for (int s = 0; s < NSPLIT; s++) {
        ms[s] = g_pm[s*NH*SEQ + hrow];
        ls[s] = g_pl[s*NH*SEQ + hrow];
        M = fmaxf(M, ms[s]);
    }
    float den = 0.f, vx = 0.f, vy = 0.f;
    #pragma unroll
    for (int s = 0; s < NSPLIT; s++) {
        float w = __expf(ms[s] - M);
        den += ls[s] * w;
        float2 o = *(const float2*)&g_po[((size_t)s*NH*SEQ + hrow)*HDIM + c2];
        vx += o.x * w;
        vy += o.y * w;
    }
    float inv = 1.f / den;
    *(__nv_bfloat162*)(g_y_bf + (size_t)row*DM + h*HDIM + c2) =
        __floats2bfloat162_rn(vx*inv, vy*inv);
}

// ---------------- gating ----------------------------------------------------
__global__ __launch_bounds__(256) void gating_kernel(const float* __restrict__ gw)
{
    int t = blockIdx.x;
    int tid = threadIdx.x;
    int e = tid >> 5, lane = tid & 31;
    float s = 0.f;
    const float* hr = g_hf + (size_t)t*DM;
    const float* wr = gw + (size_t)e*DM;
    for (int d = lane; d < DM; d += 32) s += hr[d]*wr[d];
    #pragma unroll
    for (int ofs = 16; ofs > 0; ofs >>= 1) s += __shfl_down_sync(0xffffffffu, s, ofs);
    __shared__ float lg[NE];
    if (lane == 0) lg[e] = s;
    __syncthreads();
    if (tid == 0) {
        float mx = lg[0];
        #pragma unroll
        for (int i = 1; i < NE; i++) mx = fmaxf(mx, lg[i]);
        float p[NE]; float den = 0.f;
        #pragma unroll
        for (int i = 0; i < NE; i++) { p[i] = expf(lg[i]-mx); den += p[i]; }
        #pragma unroll
        for (int i = 0; i < NE; i++) p[i] /= den;
        int i1 = 0;
        #pragma unroll
        for (int i = 1; i < NE; i++) if (p[i] > p[i1]) i1 = i;
        int i2 = (i1 == 0) ? 1 : 0;
        #pragma unroll
        for (int i = 0; i < NE; i++) if (i != i1 && p[i] > p[i2]) i2 = i;
        float w1 = p[i1], w2 = p[i2];
        float sw2 = w1 + w2;
        w1 /= sw2; w2 /= sw2;
        int pos1 = atomicAdd(&g_cnt[i1], 1);
        g_slot[i1*SEQ + pos1] = 2*t;
        g_wslot[2*t] = w1;
        int pos2 = atomicAdd(&g_cnt[i2], 1);
        g_slot[i2*SEQ + pos2] = 2*t + 1;
        g_wslot[2*t+1] = w2;
    }
}

// ---------------- final combine ---------------------------------------------
__global__ __launch_bounds__(256) void combine_kernel(float* __restrict__ out)
{
    int t = blockIdx.x;
    int tid = threadIdx.x;
    float w0 = g_wslot[2*t], w1 = g_wslot[2*t+1];
    float4 hv = ((const float4*)(g_h + (size_t)t*DM))[tid];
    float4 a = ((const float4*)(g_os + (size_t)(2*t)*DM))[tid];
    float4 b = ((const float4*)(g_os + (size_t)(2*t+1)*DM))[tid];
    float4 o;
    o.x = hv.x + w0*a.x + w1*b.x;
    o.y = hv.y + w0*a.y + w1*b.y;
    o.z = hv.z + w0*a.z + w1*b.z;
    o.w = hv.w + w0*a.w + w1*b.w;
    ((float4*)(out + (size_t)t*DM))[tid] = o;
}

// ---------------- host launch ----------------------------------------------
#define GEMM_SMEM (6*GSTG)
#define W13_SMEM  (9*GSTG)

extern "C" void kernel_launch(void* const* d_in, const int* in_sizes, int n_in,
                              void* d_out, int out_size)
{
    const float* x      = (const float*)d_in[0];
    const float* wqkv   = (const float*)d_in[1];
    const float* wo     = (const float*)d_in[2];
    const float* gate_w = (const float*)d_in[3];
    const float* w1     = (const float*)d_in[4];
    const float* w2     = (const float*)d_in[5];
    const float* w3     = (const float*)d_in[6];
    const float* anw    = (const float*)d_in[7];
    const float* fnw    = (const float*)d_in[8];
    const float* freqs  = (const float*)d_in[9];
    float* out = (float*)d_out;

    bf16 *p_wqkv_bf, *p_wo_bf, *p_w1_bf, *p_w3_bf, *p_w2_bf;
    bf16 *p_hn_bf, *p_hf_bf, *p_y_bf, *p_gb;
    float *p_h, *p_hf, *p_os;
    int *p_cnt;
    cudaGetSymbolAddress((void**)&p_wqkv_bf, g_wqkv_bf);
    cudaGetSymbolAddress((void**)&p_wo_bf,   g_wo_bf);
    cudaGetSymbolAddress((void**)&p_w1_bf,   g_w1_bf);
    cudaGetSymbolAddress((void**)&p_w3_bf,   g_w3_bf);
    cudaGetSymbolAddress((void**)&p_w2_bf,   g_w2_bf);
    cudaGetSymbolAddress((void**)&p_hn_bf,   g_hn_bf);
    cudaGetSymbolAddress((void**)&p_hf_bf,   g_hf_bf);
    cudaGetSymbolAddress((void**)&p_y_bf,    g_y_bf);
    cudaGetSymbolAddress((void**)&p_gb,      g_gb);
    cudaGetSymbolAddress((void**)&p_h,       g_h);
    cudaGetSymbolAddress((void**)&p_hf,      g_hf);
    cudaGetSymbolAddress((void**)&p_os,      g_os);
    cudaGetSymbolAddress((void**)&p_cnt,     g_cnt);

    static cudaStream_t s2 = nullptr;
    static cudaEvent_t ev0 = nullptr, ev1 = nullptr;
    static bool attr_set = false;
    if (!attr_set) {
        cudaFuncSetAttribute(gemm_bf<false>,
            cudaFuncAttributeMaxDynamicSharedMemorySize, GEMM_SMEM);
        cudaFuncSetAttribute(gemm_bf<true>,
            cudaFuncAttributeMaxDynamicSharedMemorySize, GEMM_SMEM);
        cudaFuncSetAttribute(gemm_qkv,
            cudaFuncAttributeMaxDynamicSharedMemorySize, GEMM_SMEM);
        cudaFuncSetAttribute(gemm_w13,
            cudaFuncAttributeMaxDynamicSharedMemorySize, W13_SMEM);
        cudaStreamCreateWithFlags(&s2, cudaStreamNonBlocking);
        cudaEventCreateWithFlags(&ev0, cudaEventDisableTiming);
        cudaEventCreateWithFlags(&ev1, cudaEventDisableTiming);
        attr_set = true;
    }

    // launch order arranged so attn6_kernel is the 6th launch (ncu -s 5 -c 1)
    // (1) wqkv convert (main)
    {
        int n4 = QKVN*DM/4;
        f2bf_kernel<<<(n4+255)/256, 256>>>((const float4*)wqkv, (uint2*)p_wqkv_bf, n4);
    }
    // (2,3) fork first two big MoE converts on side stream
    cudaEventRecord(ev0, 0);
    cudaStreamWaitEvent(s2, ev0, 0);
    {
        int n4 = (int)((size_t)NE*NI*DM/4);
        f2bf_kernel<<<(n4+255)/256, 256, 0, s2>>>((const float4*)w1, (uint2*)p_w1_bf, n4);
        f2bf_kernel<<<(n4+255)/256, 256, 0, s2>>>((const float4*)w3, (uint2*)p_w3_bf, n4);
    }
    // (4) attn rmsnorm
    rmsnorm_kernel<<<SEQ, 256>>>(x, anw, p_hn_bf, nullptr);
    // (5) qkv GEMM + fused RoPE
    gemm_qkv<<<dim3(QKVN/128, SEQ/128), 256, GEMM_SMEM>>>(p_hn_bf, p_wqkv_bf, freqs);
    // (6) attention v6  <-- profiled by ncu -s 5 -c 1
    attn6_kernel<<<dim3(SEQ/64, NH, NSPLIT), 128>>>();
    // (7+) rest
    {
        int n4 = (int)((size_t)NE*NI*DM/4);
        f2bf_kernel<<<(n4+255)/256, 256, 0, s2>>>((const float4*)w2, (uint2*)p_w2_bf, n4);
    }
    cudaEventRecord(ev1, s2);
    {
        int n4 = DM*DM/4;
        f2bf_kernel<<<(n4+255)/256, 256>>>((const float4*)wo, (uint2*)p_wo_bf, n4);
    }
    attn_reduce_kernel<<<(NH*SEQ*(HDIM/2) + 255)/256, 256>>>();
    gemm_bf<false><<<dim3(DM/128, SEQ/128), 256, GEMM_SMEM>>>(
        p_y_bf, p_wo_bf, x, p_h, SEQ, DM, DM, 0);
    rmsnorm_kernel<<<SEQ, 256>>>(p_h, fnw, p_hf_bf, p_hf);
    cudaMemsetAsync(p_cnt, 0, NE*sizeof(int), 0);
    gating_kernel<<<SEQ, 256>>>(gate_w);

    cudaStreamWaitEvent(0, ev1, 0);
    gemm_w13<<<dim3(NI/128, SEQ/128, NE), 256, W13_SMEM>>>(
        p_hf_bf, p_w1_bf, p_w3_bf);
    gemm_bf<true><<<dim3(DM/128, SEQ/128, NE), 256, GEMM_SMEM>>>(
        p_gb, p_w2_bf, nullptr, p_os, 0, DM, NI, 0);
    combine_kernel<<<SEQ, 256>>>(out);
}

// round 12
// speedup vs baseline: 1.2037x; 1.0026x over previous
#include <cuda_runtime.h>
#include <cuda_bf16.h>
#include <math.h>
#include <stdint.h>

#define SEQ 2048
#define DM 1024
#define NH 16
#define NKV 4
#define HDIM 64
#define NE 8
#define NI 3584
#define QKVN 1536
#define NSLOTS (2*SEQ)
#define NSPLIT 8
#define CHUNK 4

typedef __nv_bfloat16 bf16;

// ---------------- scratch (device globals; no allocations) ----------------
__device__ bf16  g_wqkv_bf[QKVN*DM];
__device__ bf16  g_wo_bf[DM*DM];
__device__ bf16  g_w1_bf[(size_t)NE*NI*DM];
__device__ bf16  g_w3_bf[(size_t)NE*NI*DM];
__device__ bf16  g_w2_bf[(size_t)NE*DM*NI];
__device__ bf16  g_hn_bf[SEQ*DM];
__device__ float g_q[NH*SEQ*HDIM];      // tf32-rounded, pre-scaled 0.125
__device__ float g_k[NKV*SEQ*HDIM];     // tf32-rounded
__device__ bf16  g_vt[NKV*HDIM*SEQ];    // bf16, transposed [kvh][d][t]
__device__ float g_po[(size_t)NSPLIT*NH*SEQ*HDIM];
__device__ float g_pm[NSPLIT*NH*SEQ];
__device__ float g_pl[NSPLIT*NH*SEQ];
__device__ bf16  g_y_bf[SEQ*DM];
__device__ float g_h[SEQ*DM];
__device__ float g_hf[SEQ*DM];
__device__ bf16  g_hf_bf[SEQ*DM];
__device__ int   g_cnt[NE];
__device__ int   g_slot[NE*SEQ];
__device__ float g_wslot[NSLOTS];
__device__ bf16  g_gb[(size_t)NSLOTS*NI];
__device__ float g_os[(size_t)NSLOTS*DM];

// ---------------- helpers ---------------------------------------------------
__device__ __forceinline__ uint32_t f2tf32(float f) {
    uint32_t r;
    asm("cvt.rna.tf32.f32 %0, %1;" : "=r"(r) : "f"(f));
    return r;
}
__device__ __forceinline__ void mma_tf32(float c[4],
    uint32_t a0, uint32_t a1, uint32_t a2, uint32_t a3,
    uint32_t b0, uint32_t b1)
{
    asm volatile(
        "mma.sync.aligned.m16n8k8.row.col.f32.tf32.tf32.f32 "
        "{%0,%1,%2,%3}, {%4,%5,%6,%7}, {%8,%9}, {%0,%1,%2,%3};"
        : "+f"(c[0]), "+f"(c[1]), "+f"(c[2]), "+f"(c[3])
        : "r"(a0), "r"(a1), "r"(a2), "r"(a3), "r"(b0), "r"(b1));
}
__device__ __forceinline__ void mma_bf16(float c[4],
    uint32_t a0, uint32_t a1, uint32_t a2, uint32_t a3,
    uint32_t b0, uint32_t b1)
{
    asm volatile(
        "mma.sync.aligned.m16n8k16.row.col.f32.bf16.bf16.f32 "
        "{%0,%1,%2,%3}, {%4,%5,%6,%7}, {%8,%9}, {%0,%1,%2,%3};"
        : "+f"(c[0]), "+f"(c[1]), "+f"(c[2]), "+f"(c[3])
        : "r"(a0), "r"(a1), "r"(a2), "r"(a3), "r"(b0), "r"(b1));
}
__device__ __forceinline__ void ldsm4(uint32_t r[4], uint32_t addr) {
    asm volatile("ldmatrix.sync.aligned.m8n8.x4.shared.b16 {%0,%1,%2,%3}, [%4];"
                 : "=r"(r[0]), "=r"(r[1]), "=r"(r[2]), "=r"(r[3]) : "r"(addr));
}
__device__ __forceinline__ void cpa(uint32_t dst, const void* src, int sz) {
    asm volatile("cp.async.cg.shared.global [%0], [%1], 16, %2;"
                 :: "r"(dst), "l"(src), "r"(sz));
}
__device__ __forceinline__ uint32_t packbf(float a, float b) {
    __nv_bfloat162 p = __floats2bfloat162_rn(a, b);
    return *(uint32_t*)&p;
}

// ---------------- fp32 -> bf16 convert --------------------------------------
__global__ void f2bf_kernel(const float4* __restrict__ s, uint2* __restrict__ d, int n4)
{
    int i = blockIdx.x * blockDim.x + threadIdx.x;
    if (i >= n4) return;
    float4 v = s[i];
    __nv_bfloat162 lo = __floats2bfloat162_rn(v.x, v.y);
    __nv_bfloat162 hi = __floats2bfloat162_rn(v.z, v.w);
    uint2 o;
    o.x = *(uint32_t*)&lo;
    o.y = *(uint32_t*)&hi;
    d[i] = o;
}

// ---------------- rmsnorm (bf16 out + optional fp32 out) -------------------
__global__ __launch_bounds__(256) void rmsnorm_kernel(
    const float* __restrict__ x, const float* __restrict__ w,
    bf16* __restrict__ obf, float* __restrict__ ofp)
{
    int row = blockIdx.x;
    int tid = threadIdx.x;
    const float4* xr = (const float4*)(x + (size_t)row*DM);
    float4 v = xr[tid];
    float ss = v.x*v.x + v.y*v.y + v.z*v.z + v.w*v.w;
    __shared__ float red[8];
    #pragma unroll
    for (int ofs = 16; ofs > 0; ofs >>= 1) ss += __shfl_down_sync(0xffffffffu, ss, ofs);
    if ((tid & 31) == 0) red[tid >> 5] = ss;
    __syncthreads();
    __shared__ float sr;
    if (tid == 0) {
        float t = 0.f;
        #pragma unroll
        for (int i = 0; i < 8; i++) t += red[i];
        sr = rsqrtf(t / (float)DM + 1e-5f);
    }
    __syncthreads();
    float r = sr;
    float4 wv = ((const float4*)w)[tid];
    float4 o;
    o.x = v.x*r*wv.x; o.y = v.y*r*wv.y; o.z = v.z*r*wv.z; o.w = v.w*r*wv.w;
    __nv_bfloat162 lo = __floats2bfloat162_rn(o.x, o.y);
    __nv_bfloat162 hi = __floats2bfloat162_rn(o.z, o.w);
    uint2 ob; ob.x = *(uint32_t*)&lo; ob.y = *(uint32_t*)&hi;
    *(uint2*)(obf + (size_t)row*DM + tid*4) = ob;
    if (ofp) ((float4*)(ofp + (size_t)row*DM))[tid] = o;
}

// ---------------- bf16 HMMA GEMM: C[M,N] = A @ B^T (+resid) ----------------
// 3-stage cp.async, SINGLE barrier per K-chunk (CUTLASS multistage style):
// stage s read at iter c is next overwritten by loadChunk(c+3), issued after
// the top barrier of iter c+1, which orders all iter-c ldsm reads first.
#define GSTG 16384
template<bool GATHER>
__global__ __launch_bounds__(256) void gemm_bf(
    const bf16* __restrict__ A, const bf16* __restrict__ B,
    const float* __restrict__ resid, float* __restrict__ C,
    int M, int N, int K, int shiftA)
{
    extern __shared__ char smem[];
    const int* sl = nullptr;
    if (GATHER) {
        int e = blockIdx.z;
        M = g_cnt[e];
        if ((int)blockIdx.y * 128 >= M) return;
        sl = g_slot + e * SEQ;
        B += (size_t)e * N * K;
    }
    int m0 = blockIdx.y * 128, n0 = blockIdx.x * 128;
    int tid = threadIdx.x, warp = tid >> 5, lane = tid & 31;
    int wm = (warp >> 2) * 64, wn = (warp & 3) * 32;
    uint32_t sbase = (uint32_t)__cvta_generic_to_shared(smem);
    uint32_t aoff[3], boff[3];
    #pragma unroll
    for (int s = 0; s < 3; s++) {
        aoff[s] = sbase + s*GSTG;
        boff[s] = sbase + 3*GSTG + s*GSTG;
    }

    int lrow = tid >> 1;
    int lsg  = (tid & 1) * 4;
    const bf16* Arow; int szA = 16;
    if (GATHER) {
        int gm = m0 + lrow;
        if (gm < M) Arow = A + (size_t)(sl[gm] >> shiftA) * K;
        else { Arow = A; szA = 0; }
    } else {
        Arow = A + (size_t)(m0 + lrow) * K;
    }
    const bf16* Brow = B + (size_t)(n0 + lrow) * K;
    uint32_t dsw = (uint32_t)lrow * 128u;
    int rxor = lrow & 7;

    float acc[4][4][4];
    #pragma unroll
    for (int i = 0; i < 4; i++)
        #pragma unroll
        for (int j = 0; j < 4; j++)
            #pragma unroll
            for (int q = 0; q < 4; q++) acc[i][j][q] = 0.f;

    int CC = K / 64;
    auto loadChunk = [&](int c) {
        int s = c % 3;
        const char* pa = (const char*)(Arow + c*64);
        const char* pb = (const char*)(Brow + c*64);
        #pragma unroll
        for (int i = 0; i < 4; i++) {
            int seg = lsg + i;
            uint32_t o = dsw + (uint32_t)((seg ^ rxor) * 16);
            cpa(aoff[s] + o, pa + seg*16, szA);
            cpa(boff[s] + o, pb + seg*16, 16);
        }
        asm volatile("cp.async.commit_group;" ::: "memory");
    };
    loadChunk(0);
    if (CC > 1) loadChunk(1);

    int lt = lane >> 3;
    int rl = lane & 7;
    int th = (lt & 1) * 8;
    int ts = lane >> 4;

    for (int c = 0; c < CC; c++) {
        if (c + 1 < CC) asm volatile("cp.async.wait_group 1;" ::: "memory");
        else            asm volatile("cp.async.wait_group 0;" ::: "memory");
        __syncthreads();
        if (c + 2 < CC) loadChunk(c + 2);

        uint32_t Ab = aoff[c % 3], Bb = boff[c % 3];
        #pragma unroll
        for (int kk = 0; kk < 4; kk++) {
            uint32_t af[4][4], bfm[2][4];
            #pragma unroll
            for (int i = 0; i < 4; i++) {
                int row = wm + i*16 + th + rl;
                int seg = 2*kk + ts;
                ldsm4(af[i], Ab + row*128 + ((seg ^ (row & 7)) << 4));
            }
            #pragma unroll
            for (int j = 0; j < 2; j++) {
                int nr = wn + j*16 + th + rl;
                int seg = 2*kk + ts;
                ldsm4(bfm[j], Bb + nr*128 + ((seg ^ (nr & 7)) << 4));
            }
            #pragma unroll
            for (int i = 0; i < 4; i++)
                #pragma unroll
                for (int jn = 0; jn < 4; jn++) {
                    int jj = jn >> 1, hi = jn & 1;
                    mma_bf16(acc[i][jn], af[i][0], af[i][1], af[i][2], af[i][3],
                             bfm[jj][hi], bfm[jj][hi+2]);
                }
        }
        // no trailing barrier: next write to this stage happens after the
        // top barrier of iteration c+1 (3-stage invariant).
    }

    int g = lane >> 2, tg = lane & 3;
    #pragma unroll
    for (int i = 0; i < 4; i++) {
        int r0 = m0 + wm + i*16 + g;
        int r1 = r0 + 8;
        bool v0, v1;
        int row0, row1;
        if (GATHER) {
            v0 = r0 < M; v1 = r1 < M;
            row0 = v0 ? sl[r0] : 0;
            row1 = v1 ? sl[r1] : 0;
        } else {
            v0 = v1 = true; row0 = r0; row1 = r1;
        }
        #pragma unroll
        for (int j = 0; j < 4; j++) {
            int c0 = n0 + wn + j*8 + tg*2;
            if (v0) {
                float2 v; v.x = acc[i][j][0]; v.y = acc[i][j][1];
                if (resid) {
                    v.x += resid[(size_t)row0*N + c0];
                    v.y += resid[(size_t)row0*N + c0 + 1];
                }
                *(float2*)(C + (size_t)row0*N + c0) = v;
            }
            if (v1) {
                float2 v; v.x = acc[i][j][2]; v.y = acc[i][j][3];
                if (resid) {
                    v.x += resid[(size_t)row1*N + c0];
                    v.y += resid[(size_t)row1*N + c0 + 1];
                }
                *(float2*)(C + (size_t)row1*N + c0) = v;
            }
        }
    }
}

// ---------------- QKV GEMM with fused RoPE/split epilogue -------------------
__device__ __forceinline__ void rope_write(
    int t, int c0, float vx, float vy, const float* __restrict__ freqs)
{
    if (c0 < DM) {
        int h = c0 >> 6, d = c0 & 63, p = d >> 1;
        float cs = freqs[((size_t)t*32 + p)*2 + 0];
        float sn = freqs[((size_t)t*32 + p)*2 + 1];
        float2 o;
        o.x = __uint_as_float(f2tf32((vx*cs - vy*sn) * 0.125f));
        o.y = __uint_as_float(f2tf32((vy*cs + vx*sn) * 0.125f));
        *(float2*)(g_q + ((size_t)h*SEQ + t)*HDIM + d) = o;
    } else if (c0 < DM + NKV*HDIM) {
        int c = c0 - DM;
        int kh = c >> 6, d = c & 63, p = d >> 1;
        float cs = freqs[((size_t)t*32 + p)*2 + 0];
        float sn = freqs[((size_t)t*32 + p)*2 + 1];
        float2 o;
        o.x = __uint_as_float(f2tf32(vx*cs - vy*sn));
        o.y = __uint_as_float(f2tf32(vy*cs + vx*sn));
        *(float2*)(g_k + ((size_t)kh*SEQ + t)*HDIM + d) = o;
    } else {
        int c = c0 - DM - NKV*HDIM;
        int vh = c >> 6, d = c & 63;
        g_vt[((size_t)(vh*HDIM + d  ))*SEQ + t] = __float2bfloat16(vx);
        g_vt[((size_t)(vh*HDIM + d+1))*SEQ + t] = __float2bfloat16(vy);
    }
}

__global__ __launch_bounds__(256) void gemm_qkv(
    const bf16* __restrict__ A, const bf16* __restrict__ B,
    const float* __restrict__ freqs)
{
    extern __shared__ char smem[];
    const int K = DM;
    int m0 = blockIdx.y * 128, n0 = blockIdx.x * 128;
    int tid = threadIdx.x, warp = tid >> 5, lane = tid & 31;
    int wm = (warp >> 2) * 64, wn = (warp & 3) * 32;
    uint32_t sbase = (uint32_t)__cvta_generic_to_shared(smem);
    uint32_t aoff[3], boff[3];
    #pragma unroll
    for (int s = 0; s < 3; s++) {
        aoff[s] = sbase + s*GSTG;
        boff[s] = sbase + 3*GSTG + s*GSTG;
    }

    int lrow = tid >> 1;
    int lsg  = (tid & 1) * 4;
    const bf16* Arow = A + (size_t)(m0 + lrow) * K;
    const bf16* Brow = B + (size_t)(n0 + lrow) * K;
    uint32_t dsw = (uint32_t)lrow * 128u;
    int rxor = lrow & 7;

    float acc[4][4][4];
    #pragma unroll
    for (int i = 0; i < 4; i++)
        #pragma unroll
        for (int j = 0; j < 4; j++)
            #pragma unroll
            for (int q = 0; q < 4; q++) acc[i][j][q] = 0.f;

    const int CC = K / 64;
    auto loadChunk = [&](int c) {
        int s = c % 3;
        const char* pa = (const char*)(Arow + c*64);
        const char* pb = (const char*)(Brow + c*64);
        #pragma unroll
        for (int i = 0; i < 4; i++) {
            int seg = lsg + i;
            uint32_t o = dsw + (uint32_t)((seg ^ rxor) * 16);
            cpa(aoff[s] + o, pa + seg*16, 16);
            cpa(boff[s] + o, pb + seg*16, 16);
        }
        asm volatile("cp.async.commit_group;" ::: "memory");
    };
    loadChunk(0);
    loadChunk(1);

    int lt = lane >> 3;
    int rl = lane & 7;
    int th = (lt & 1) * 8;
    int ts = lane >> 4;

    for (int c = 0; c < CC; c++) {
        if (c + 1 < CC) asm volatile("cp.async.wait_group 1;" ::: "memory");
        else            asm volatile("cp.async.wait_group 0;" ::: "memory");
        __syncthreads();
        if (c + 2 < CC) loadChunk(c + 2);

        uint32_t Ab = aoff[c % 3], Bb = boff[c % 3];
        #pragma unroll
        for (int kk = 0; kk < 4; kk++) {
            uint32_t af[4][4], bfm[2][4];
            #pragma unroll
            for (int i = 0; i < 4; i++) {
                int row = wm + i*16 + th + rl;
                int seg = 2*kk + ts;
                ldsm4(af[i], Ab + row*128 + ((seg ^ (row & 7)) << 4));
            }
            #pragma unroll
            for (int j = 0; j < 2; j++) {
                int nr = wn + j*16 + th + rl;
                int seg = 2*kk + ts;
                ldsm4(bfm[j], Bb + nr*128 + ((seg ^ (nr & 7)) << 4));
            }
            #pragma unroll
            for (int i = 0; i < 4; i++)
                #pragma unroll
                for (int jn = 0; jn < 4; jn++) {
                    int jj = jn >> 1, hi = jn & 1;
                    mma_bf16(acc[i][jn], af[i][0], af[i][1], af[i][2], af[i][3],
                             bfm[jj][hi], bfm[jj][hi+2]);
                }
        }
    }

    int g = lane >> 2, tg = lane & 3;
    #pragma unroll
    for (int i = 0; i < 4; i++) {
        int t0 = m0 + wm + i*16 + g;
        int t1 = t0 + 8;
        #pragma unroll
        for (int j = 0; j < 4; j++) {
            int c0 = n0 + wn + j*8 + tg*2;
            rope_write(t0, c0, acc[i][j][0], acc[i][j][1], freqs);
            rope_write(t1, c0, acc[i][j][2], acc[i][j][3], freqs);
        }
    }
}

// ---------------- fused MoE w1/w3 GEMM + silu*mul (bf16 out) ---------------
__global__ __launch_bounds__(256) void gemm_w13(
    const bf16* __restrict__ A, const bf16* __restrict__ B1,
    const bf16* __restrict__ B3)
{
    extern __shared__ char smem[];
    int e = blockIdx.z;
    int M = g_cnt[e];
    if ((int)blockIdx.y * 128 >= M) return;
    const int* sl = g_slot + e * SEQ;
    B1 += (size_t)e * NI * DM;
    B3 += (size_t)e * NI * DM;

    int m0 = blockIdx.y * 128, n0 = blockIdx.x * 128;
    int tid = threadIdx.x, warp = tid >> 5, lane = tid & 31;
    int wm = (warp >> 2) * 64, wn = (warp & 3) * 32;
    uint32_t sbase = (uint32_t)__cvta_generic_to_shared(smem);
    uint32_t aoff[3], b1off[3], b3off[3];
    #pragma unroll
    for (int s = 0; s < 3; s++) {
        aoff[s]  = sbase + s*GSTG;
        b1off[s] = sbase + 3*GSTG + s*GSTG;
        b3off[s] = sbase + 6*GSTG + s*GSTG;
    }

    int lrow = tid >> 1;
    int lsg  = (tid & 1) * 4;
    const bf16* Arow; int szA = 16;
    {
        int gm = m0 + lrow;
        if (gm < M) Arow = A + (size_t)(sl[gm] >> 1) * DM;
        else { Arow = A; szA = 0; }
    }
    const bf16* B1row = B1 + (size_t)(n0 + lrow) * DM;
    const bf16* B3row = B3 + (size_t)(n0 + lrow) * DM;
    uint32_t dsw = (uint32_t)lrow * 128u;
    int rxor = lrow & 7;

    float ac1[4][4][4], ac3[4][4][4];
    #pragma unroll
    for (int i = 0; i < 4; i++)
        #pragma unroll
        for (int j = 0; j < 4; j++)
            #pragma unroll
            for (int q = 0; q < 4; q++) { ac1[i][j][q] = 0.f; ac3[i][j][q] = 0.f; }

    const int CC = DM / 64;
    auto loadChunk = [&](int c) {
        int s = c % 3;
        const char* pa  = (const char*)(Arow  + c*64);
        const char* pb1 = (const char*)(B1row + c*64);
        const char* pb3 = (const char*)(B3row + c*64);
        #pragma unroll
        for (int i = 0; i < 4; i++) {
            int seg = lsg + i;
            uint32_t o = dsw + (uint32_t)((seg ^ rxor) * 16);
            cpa(aoff[s]  + o, pa  + seg*16, szA);
            cpa(b1off[s] + o, pb1 + seg*16, 16);
            cpa(b3off[s] + o, pb3 + seg*16, 16);
        }
        asm volatile("cp.async.commit_group;" ::: "memory");
    };
    loadChunk(0);
    loadChunk(1);

    int lt = lane >> 3, rl = lane & 7;
    int th = (lt & 1) * 8;
    int ts = lane >> 4;

    for (int c = 0; c < CC; c++) {
        if (c + 1 < CC) asm volatile("cp.async.wait_group 1;" ::: "memory");
        else            asm volatile("cp.async.wait_group 0;" ::: "memory");
        __syncthreads();
        if (c + 2 < CC) loadChunk(c + 2);

        uint32_t Ab = aoff[c % 3], B1b = b1off[c % 3], B3b = b3off[c % 3];
        #pragma unroll
        for (int kk = 0; kk < 4; kk++) {
            uint32_t af[4][4], f1[2][4], f3[2][4];
            #pragma unroll
            for (int i = 0; i < 4; i++) {
                int row = wm + i*16 + th + rl;
                int seg = 2*kk + ts;
                ldsm4(af[i], Ab + row*128 + ((seg ^ (row & 7)) << 4));
            }
            #pragma unroll
            for (int j = 0; j < 2; j++) {
                int nr = wn + j*16 + th + rl;
                int seg = 2*kk + ts;
                ldsm4(f1[j], B1b + nr*128 + ((seg ^ (nr & 7)) << 4));
                ldsm4(f3[j], B3b + nr*128 + ((seg ^ (nr & 7)) << 4));
            }
            #pragma unroll
            for (int i = 0; i < 4; i++)
                #pragma unroll
                for (int jn = 0; jn < 4; jn++) {
                    int jj = jn >> 1, hi = jn & 1;
                    mma_bf16(ac1[i][jn], af[i][0], af[i][1], af[i][2], af[i][3],
                             f1[jj][hi], f1[jj][hi+2]);
                    mma_bf16(ac3[i][jn], af[i][0], af[i][1], af[i][2], af[i][3],
                             f3[jj][hi], f3[jj][hi+2]);
                }
        }
    }

    int g = lane >> 2, tg = lane & 3;
    #pragma unroll
    for (int i = 0; i < 4; i++) {
        int r0 = m0 + wm + i*16 + g;
        int r1 = r0 + 8;
        bool v0 = r0 < M, v1 = r1 < M;
        int row0 = v0 ? sl[r0] : 0;
        int row1 = v1 ? sl[r1] : 0;
        #pragma unroll
        for (int j = 0; j < 4; j++) {
            int c0 = n0 + wn + j*8 + tg*2;
            if (v0) {
                float a0 = ac1[i][j][0], a1 = ac1[i][j][1];
                float u0 = a0 / (1.f + __expf(-a0)) * ac3[i][j][0];
                float u1 = a1 / (1.f + __expf(-a1)) * ac3[i][j][1];
                *(__nv_bfloat162*)(g_gb + (size_t)row0*NI + c0) = __floats2bfloat162_rn(u0, u1);
            }
            if (v1) {
                float a0 = ac1[i][j][2], a1 = ac1[i][j][3];
                float u0 = a0 / (1.f + __expf(-a0)) * ac3[i][j][2];
                float u1 = a1 / (1.f + __expf(-a1)) * ac3[i][j][3];
                *(__nv_bfloat162*)(g_gb + (size_t)row1*NI + c0) = __floats2bfloat162_rn(u0, u1);
            }
        }
    }
}

// ---------------- attention v6: uniform-chunk split flash -------------------
#define ASTR 68
#define VSTR 72
__global__ __launch_bounds__(128) void attn6_kernel()
{
    __shared__ float Ks[64*ASTR];
    __shared__ bf16  Vt[64*VSTR];

    int qt = blockIdx.x, h = blockIdx.y, z = blockIdx.z;
    int kvh = h >> 2;
    int tid = threadIdx.x, warp = tid >> 5, lane = tid & 31;
    int g = lane >> 2, tg = lane & 3;
    int wq = warp * 16;
    int q0 = qt * 64;

    int n = qt + 1;
    int lo = z * CHUNK;
    int hi = min(n, lo + CHUNK);

    float oc[8][4];
    #pragma unroll
    for (int j = 0; j < 8; j++)
        #pragma unroll
        for (int q = 0; q < 4; q++) oc[j][q] = 0.f;
    float mrow[2] = {-1e30f, -1e30f};
    float lrow[2] = {0.f, 0.f};

    if (lo < hi) {
        for (int i = tid; i < 64*16; i += 128) {
            int row = i >> 4, c4 = (i & 15) * 4;
            *(float4*)&Ks[row*ASTR + c4] =
                *(const float4*)(g_q + ((size_t)h*SEQ + q0 + row)*HDIM + c4);
        }
        __syncthreads();
        uint32_t aq[8][4];
        #pragma unroll
        for (int kk = 0; kk < 8; kk++) {
            aq[kk][0] = __float_as_uint(Ks[(wq+g)*ASTR + kk*8 + tg]);
            aq[kk][1] = __float_as_uint(Ks[(wq+g+8)*ASTR + kk*8 + tg]);
            aq[kk][2] = __float_as_uint(Ks[(wq+g)*ASTR + kk*8 + tg + 4]);
            aq[kk][3] = __float_as_uint(Ks[(wq+g+8)*ASTR + kk*8 + tg + 4]);
        }
        __syncthreads();

        for (int kt = lo; kt < hi; kt++) {
            for (int i = tid; i < 1024; i += 128) {
                int row = i >> 4, c4 = (i & 15) * 4;
                *(float4*)&Ks[row*ASTR + c4] =
                    *(const float4*)(g_k + ((size_t)kvh*SEQ + kt*64 + row)*HDIM + c4);
            }
            for (int i = tid; i < 512; i += 128) {
                int row = i >> 3, seg = i & 7;
                *(uint4*)&Vt[row*VSTR + seg*8] =
                    *(const uint4*)(g_vt + ((size_t)(kvh*HDIM + row))*SEQ + kt*64 + seg*8);
            }
            __syncthreads();

            float sc[8][4];
            #pragma unroll
            for (int j = 0; j < 8; j++)
                #pragma unroll
                for (int q = 0; q < 4; q++) sc[j][q] = 0.f;
            #pragma unroll
            for (int kk = 0; kk < 8; kk++) {
                #pragma unroll
                for (int j = 0; j < 8; j++) {
                    uint32_t b0 = __float_as_uint(Ks[(j*8+g)*ASTR + kk*8 + tg]);
                    uint32_t b1 = __float_as_uint(Ks[(j*8+g)*ASTR + kk*8 + tg + 4]);
                    mma_tf32(sc[j], aq[kk][0], aq[kk][1], aq[kk][2], aq[kk][3], b0, b1);
                }
            }

            if (kt == qt) {
                int r0g = q0 + wq + g, r1g = r0g + 8;
                #pragma unroll
                for (int j = 0; j < 8; j++) {
                    int c0 = kt*64 + j*8 + tg*2;
                    if (c0     > r0g) sc[j][0] = -1e30f;
                    if (c0 + 1 > r0g) sc[j][1] = -1e30f;
                    if (c0     > r1g) sc[j][2] = -1e30f;
                    if (c0 + 1 > r1g) sc[j][3] = -1e30f;
                }
            }

            float mx0 = -1e30f, mx1 = -1e30f;
            #pragma unroll
            for (int j = 0; j < 8; j++) {
                mx0 = fmaxf(mx0, fmaxf(sc[j][0], sc[j][1]));
                mx1 = fmaxf(mx1, fmaxf(sc[j][2], sc[j][3]));
            }
            mx0 = fmaxf(mx0, __shfl_xor_sync(0xffffffffu, mx0, 1));
            mx0 = fmaxf(mx0, __shfl_xor_sync(0xffffffffu, mx0, 2));
            mx1 = fmaxf(mx1, __shfl_xor_sync(0xffffffffu, mx1, 1));
            mx1 = fmaxf(mx1, __shfl_xor_sync(0xffffffffu, mx1, 2));
            float mn0 = fmaxf(mrow[0], mx0), mn1 = fmaxf(mrow[1], mx1);
            float s0 = __expf(mrow[0] - mn0), s1 = __expf(mrow[1] - mn1);
            float ls0 = 0.f, ls1 = 0.f;
            #pragma unroll
            for (int j = 0; j < 8; j++) {
                sc[j][0] = __expf(sc[j][0] - mn0);
                sc[j][1] = __expf(sc[j][1] - mn0);
                sc[j][2] = __expf(sc[j][2] - mn1);
                sc[j][3] = __expf(sc[j][3] - mn1);
                ls0 += sc[j][0] + sc[j][1];
                ls1 += sc[j][2] + sc[j][3];
            }
            ls0 += __shfl_xor_sync(0xffffffffu, ls0, 1);
            ls0 += __shfl_xor_sync(0xffffffffu, ls0, 2);
            ls1 += __shfl_xor_sync(0xffffffffu, ls1, 1);
            ls1 += __shfl_xor_sync(0xffffffffu, ls1, 2);
            lrow[0] = lrow[0]*s0 + ls0;
            lrow[1] = lrow[1]*s1 + ls1;
            mrow[0] = mn0; mrow[1] = mn1;
            #pragma unroll
            for (int j = 0; j < 8; j++) {
                oc[j][0] *= s0; oc[j][1] *= s0;
                oc[j][2] *= s1; oc[j][3] *= s1;
            }

            uint32_t pa[4][4];
            #pragma unroll
            for (int kk = 0; kk < 4; kk++) {
                pa[kk][0] = packbf(sc[2*kk][0],   sc[2*kk][1]);
                pa[kk][1] = packbf(sc[2*kk][2],   sc[2*kk][3]);
                pa[kk][2] = packbf(sc[2*kk+1][0], sc[2*kk+1][1]);
                pa[kk][3] = packbf(sc[2*kk+1][2], sc[2*kk+1][3]);
            }
            #pragma unroll
            for (int kk = 0; kk < 4; kk++) {
                #pragma unroll
                for (int j = 0; j < 8; j++) {
                    uint32_t b0 = *(const uint32_t*)&Vt[(j*8+g)*VSTR + kk*16 + tg*2];
                    uint32_t b1 = *(const uint32_t*)&Vt[(j*8+g)*VSTR + kk*16 + tg*2 + 8];
                    mma_bf16(oc[j], pa[kk][0], pa[kk][1], pa[kk][2], pa[kk][3], b0, b1);
                }
            }
            __syncthreads();
        }
    }

    size_t pb = (size_t)z * NH * SEQ;
    int r0 = q0 + wq + g, r1 = r0 + 8;
    size_t hr0 = (size_t)h*SEQ + r0, hr1 = (size_t)h*SEQ + r1;
    #pragma unroll
    for (int j = 0; j < 8; j++) {
        int c0 = j*8 + tg*2;
        float2 v0; v0.x = oc[j][0]; v0.y = oc[j][1];
        float2 v1; v1.x = oc[j][2]; v1.y = oc[j][3];
        *(float2*)&g_po[(pb + hr0)*HDIM + c0] = v0;
        *(float2*)&g_po[(pb + hr1)*HDIM + c0] = v1;
    }
    if (tg == 0) {
        g_pm[pb + hr0] = mrow[0];
        g_pm[pb + hr1] = mrow[1];
        g_pl[pb + hr0] = lrow[0];
        g_pl[pb + hr1] = lrow[1];
    }
}

// ---------------- split reduce: merge NSPLIT partials -> y_bf ---------------
__global__ void attn_reduce_kernel()
{
    int i = blockIdx.x * blockDim.x + threadIdx.x;
    if (i >= NH*SEQ*(HDIM/2)) return;
    int hrow = i >> 5;
    int c2 = (i & 31) * 2;
    int h = hrow / SEQ, row = hrow % SEQ;
    float M = -1e30f;
    float ms[NSPLIT], ls[NSPLIT];
    #pragma unroll
    for (int s = 0; s < NSPLIT; s++) {
        ms[s] = g_pm[s*NH*SEQ + hrow];
        ls[s] = g_pl[s*NH*SEQ + hrow];
        M = fmaxf(M, ms[s]);
    }
    float den = 0.f, vx = 0.f, vy = 0.f;
    #pragma unroll
    for (int s = 0; s < NSPLIT; s++) {
        float w = __expf(ms[s] - M);
        den += ls[s] * w;
        float2 o = *(const float2*)&g_po[((size_t)s*NH*SEQ + hrow)*HDIM + c2];
        vx += o.x * w;
        vy += o.y * w;
    }
    float inv = 1.f / den;
    *(__nv_bfloat162*)(g_y_bf + (size_t)row*DM + h*HDIM + c2) =
        __floats2bfloat162_rn(vx*inv, vy*inv);
}

// ---------------- gating ----------------------------------------------------
__global__ __launch_bounds__(256) void gating_kernel(const float* __restrict__ gw)
{
    int t = blockIdx.x;
    int tid = threadIdx.x;
    int e = tid >> 5, lane = tid & 31;
    float s = 0.f;
    const float* hr = g_hf + (size_t)t*DM;
    const float* wr = gw + (size_t)e*DM;
    for (int d = lane; d < DM; d += 32) s += hr[d]*wr[d];
    #pragma unroll
    for (int ofs = 16; ofs > 0; ofs >>= 1) s += __shfl_down_sync(0xffffffffu, s, ofs);
    __shared__ float lg[NE];
    if (lane == 0) lg[e] = s;
    __syncthreads();
    if (tid == 0) {
        float mx = lg[0];
        #pragma unroll
        for (int i = 1; i < NE; i++) mx = fmaxf(mx, lg[i]);
        float p[NE]; float den = 0.f;
        #pragma unroll
        for (int i = 0; i < NE; i++) { p[i] = expf(lg[i]-mx); den += p[i]; }
        #pragma unroll
        for (int i = 0; i < NE; i++) p[i] /= den;
        int i1 = 0;
        #pragma unroll
        for (int i = 1; i < NE; i++) if (p[i] > p[i1]) i1 = i;
        int i2 = (i1 == 0) ? 1 : 0;
        #pragma unroll
        for (int i = 0; i < NE; i++) if (i != i1 && p[i] > p[i2]) i2 = i;
        float w1 = p[i1], w2 = p[i2];
        float sw2 = w1 + w2;
        w1 /= sw2; w2 /= sw2;
        int pos1 = atomicAdd(&g_cnt[i1], 1);
        g_slot[i1*SEQ + pos1] = 2*t;
        g_wslot[2*t] = w1;
        int pos2 = atomicAdd(&g_cnt[i2], 1);
        g_slot[i2*SEQ + pos2] = 2*t + 1;
        g_wslot[2*t+1] = w2;
    }
}

// ---------------- final combine ---------------------------------------------
__global__ __launch_bounds__(256) void combine_kernel(float* __restrict__ out)
{
    int t = blockIdx.x;
    int tid = threadIdx.x;
    float w0 = g_wslot[2*t], w1 = g_wslot[2*t+1];
    float4 hv = ((const float4*)(g_h + (size_t)t*DM))[tid];
    float4 a = ((const float4*)(g_os + (size_t)(2*t)*DM))[tid];
    float4 b = ((const float4*)(g_os + (size_t)(2*t+1)*DM))[tid];
    float4 o;
    o.x = hv.x + w0*a.x + w1*b.x;
    o.y = hv.y + w0*a.y + w1*b.y;
    o.z = hv.z + w0*a.z + w1*b.z;
    o.w = hv.w + w0*a.w + w1*b.w;
    ((float4*)(out + (size_t)t*DM))[tid] = o;
}

// ---------------- host launch ----------------------------------------------
#define GEMM_SMEM (6*GSTG)
#define W13_SMEM  (9*GSTG)

extern "C" void kernel_launch(void* const* d_in, const int* in_sizes, int n_in,
                              void* d_out, int out_size)
{
    const float* x      = (const float*)d_in[0];
    const float* wqkv   = (const float*)d_in[1];
    const float* wo     = (const float*)d_in[2];
    const float* gate_w = (const float*)d_in[3];
    const float* w1     = (const float*)d_in[4];
    const float* w2     = (const float*)d_in[5];
    const float* w3     = (const float*)d_in[6];
    const float* anw    = (const float*)d_in[7];
    const float* fnw    = (const float*)d_in[8];
    const float* freqs  = (const float*)d_in[9];
    float* out = (float*)d_out;

    bf16 *p_wqkv_bf, *p_wo_bf, *p_w1_bf, *p_w3_bf, *p_w2_bf;
    bf16 *p_hn_bf, *p_hf_bf, *p_y_bf, *p_gb;
    float *p_h, *p_hf, *p_os;
    int *p_cnt;
    cudaGetSymbolAddress((void**)&p_wqkv_bf, g_wqkv_bf);
    cudaGetSymbolAddress((void**)&p_wo_bf,   g_wo_bf);
    cudaGetSymbolAddress((void**)&p_w1_bf,   g_w1_bf);
    cudaGetSymbolAddress((void**)&p_w3_bf,   g_w3_bf);
    cudaGetSymbolAddress((void**)&p_w2_bf,   g_w2_bf);
    cudaGetSymbolAddress((void**)&p_hn_bf,   g_hn_bf);
    cudaGetSymbolAddress((void**)&p_hf_bf,   g_hf_bf);
    cudaGetSymbolAddress((void**)&p_y_bf,    g_y_bf);
    cudaGetSymbolAddress((void**)&p_gb,      g_gb);
    cudaGetSymbolAddress((void**)&p_h,       g_h);
    cudaGetSymbolAddress((void**)&p_hf,      g_hf);
    cudaGetSymbolAddress((void**)&p_os,      g_os);
    cudaGetSymbolAddress((void**)&p_cnt,     g_cnt);

    static cudaStream_t s2 = nullptr;
    static cudaEvent_t ev0 = nullptr, ev1 = nullptr;
    static bool attr_set = false;
    if (!attr_set) {
        cudaFuncSetAttribute(gemm_bf<false>,
            cudaFuncAttributeMaxDynamicSharedMemorySize, GEMM_SMEM);
        cudaFuncSetAttribute(gemm_bf<true>,
            cudaFuncAttributeMaxDynamicSharedMemorySize, GEMM_SMEM);
        cudaFuncSetAttribute(gemm_qkv,
            cudaFuncAttributeMaxDynamicSharedMemorySize, GEMM_SMEM);
        cudaFuncSetAttribute(gemm_w13,
            cudaFuncAttributeMaxDynamicSharedMemorySize, W13_SMEM);
        cudaStreamCreateWithFlags(&s2, cudaStreamNonBlocking);
        cudaEventCreateWithFlags(&ev0, cudaEventDisableTiming);
        cudaEventCreateWithFlags(&ev1, cudaEventDisableTiming);
        attr_set = true;
    }

    // (1) wqkv convert (main)
    {
        int n4 = QKVN*DM/4;
        f2bf_kernel<<<(n4+255)/256, 256>>>((const float4*)wqkv, (uint2*)p_wqkv_bf, n4);
    }
    // (2,3) fork first two big MoE converts on side stream
    cudaEventRecord(ev0, 0);
    cudaStreamWaitEvent(s2, ev0, 0);
    {
        int n4 = (int)((size_t)NE*NI*DM/4);
        f2bf_kernel<<<(n4+255)/256, 256, 0, s2>>>((const float4*)w1, (uint2*)p_w1_bf, n4);
        f2bf_kernel<<<(n4+255)/256, 256, 0, s2>>>((const float4*)w3, (uint2*)p_w3_bf, n4);
    }
    // (4) attn rmsnorm
    rmsnorm_kernel<<<SEQ, 256>>>(x, anw, p_hn_bf, nullptr);
    // (5) qkv GEMM + fused RoPE
    gemm_qkv<<<dim3(QKVN/128, SEQ/128), 256, GEMM_SMEM>>>(p_hn_bf, p_wqkv_bf, freqs);
    // (6) attention v6
    attn6_kernel<<<dim3(SEQ/64, NH, NSPLIT), 128>>>();
    // (7+) rest
    {
        int n4 = (int)((size_t)NE*NI*DM/4);
        f2bf_kernel<<<(n4+255)/256, 256, 0, s2>>>((const float4*)w2, (uint2*)p_w2_bf, n4);
    }
    cudaEventRecord(ev1, s2);
    {
        int n4 = DM*DM/4;
        f2bf_kernel<<<(n4+255)/256, 256>>>((const float4*)wo, (uint2*)p_wo_bf, n4);
    }
    attn_reduce_kernel<<<(NH*SEQ*(HDIM/2) + 255)/256, 256>>>();
    gemm_bf<false><<<dim3(DM/128, SEQ/128), 256, GEMM_SMEM>>>(
        p_y_bf, p_wo_bf, x, p_h, SEQ, DM, DM, 0);
    rmsnorm_kernel<<<SEQ, 256>>>(p_h, fnw, p_hf_bf, p_hf);
    cudaMemsetAsync(p_cnt, 0, NE*sizeof(int), 0);
    gating_kernel<<<SEQ, 256>>>(gate_w);

    cudaStreamWaitEvent(0, ev1, 0);
    gemm_w13<<<dim3(NI/128, SEQ/128, NE), 256, W13_SMEM>>>(
        p_hf_bf, p_w1_bf, p_w3_bf);
    gemm_bf<true><<<dim3(DM/128, SEQ/128, NE), 256, GEMM_SMEM>>>(
        p_gb, p_w2_bf, nullptr, p_os, 0, DM, NI, 0);
    combine_kernel<<<SEQ, 256>>>(out);
}

// round 13
// speedup vs baseline: 1.2105x; 1.0057x over previous
#include <cuda_runtime.h>
#include <cuda_bf16.h>
#include <math.h>
#include <stdint.h>

#define SEQ 2048
#define DM 1024
#define NH 16
#define NKV 4
#define HDIM 64
#define NE 8
#define NI 3584
#define QKVN 1536
#define NSLOTS (2*SEQ)
#define NSPLIT 8
#define CHUNK 4

typedef __nv_bfloat16 bf16;

// ---------------- scratch (device globals; no allocations) ----------------
__device__ bf16  g_wqkv_bf[QKVN*DM];
__device__ bf16  g_wo_bf[DM*DM];
__device__ bf16  g_w1_bf[(size_t)NE*NI*DM];
__device__ bf16  g_w3_bf[(size_t)NE*NI*DM];
__device__ bf16  g_w2_bf[(size_t)NE*DM*NI];
__device__ bf16  g_hn_bf[SEQ*DM];
__device__ float g_q[NH*SEQ*HDIM];      // tf32-rounded, pre-scaled 0.125
__device__ float g_k[NKV*SEQ*HDIM];     // tf32-rounded
__device__ bf16  g_vt[NKV*HDIM*SEQ];    // bf16, transposed [kvh][d][t]
__device__ float g_po[(size_t)NSPLIT*NH*SEQ*HDIM];
__device__ float g_pm[NSPLIT*NH*SEQ];
__device__ float g_pl[NSPLIT*NH*SEQ];
__device__ bf16  g_y_bf[SEQ*DM];
__device__ float g_h[SEQ*DM];
__device__ float g_hf[SEQ*DM];
__device__ bf16  g_hf_bf[SEQ*DM];
__device__ int   g_cnt[NE];
__device__ int   g_slot[NE*SEQ];
__device__ float g_wslot[NSLOTS];
__device__ bf16  g_gb[(size_t)NSLOTS*NI];
__device__ float g_os[(size_t)NSLOTS*DM];

// ---------------- helpers ---------------------------------------------------
__device__ __forceinline__ uint32_t f2tf32(float f) {
    uint32_t r;
    asm("cvt.rna.tf32.f32 %0, %1;" : "=r"(r) : "f"(f));
    return r;
}
__device__ __forceinline__ void mma_tf32(float c[4],
    uint32_t a0, uint32_t a1, uint32_t a2, uint32_t a3,
    uint32_t b0, uint32_t b1)
{
    asm volatile(
        "mma.sync.aligned.m16n8k8.row.col.f32.tf32.tf32.f32 "
        "{%0,%1,%2,%3}, {%4,%5,%6,%7}, {%8,%9}, {%0,%1,%2,%3};"
        : "+f"(c[0]), "+f"(c[1]), "+f"(c[2]), "+f"(c[3])
        : "r"(a0), "r"(a1), "r"(a2), "r"(a3), "r"(b0), "r"(b1));
}
__device__ __forceinline__ void mma_bf16(float c[4],
    uint32_t a0, uint32_t a1, uint32_t a2, uint32_t a3,
    uint32_t b0, uint32_t b1)
{
    asm volatile(
        "mma.sync.aligned.m16n8k16.row.col.f32.bf16.bf16.f32 "
        "{%0,%1,%2,%3}, {%4,%5,%6,%7}, {%8,%9}, {%0,%1,%2,%3};"
        : "+f"(c[0]), "+f"(c[1]), "+f"(c[2]), "+f"(c[3])
        : "r"(a0), "r"(a1), "r"(a2), "r"(a3), "r"(b0), "r"(b1));
}
__device__ __forceinline__ void ldsm4(uint32_t r[4], uint32_t addr) {
    asm volatile("ldmatrix.sync.aligned.m8n8.x4.shared.b16 {%0,%1,%2,%3}, [%4];"
                 : "=r"(r[0]), "=r"(r[1]), "=r"(r[2]), "=r"(r[3]) : "r"(addr));
}
__device__ __forceinline__ void cpa(uint32_t dst, const void* src, int sz) {
    asm volatile("cp.async.cg.shared.global [%0], [%1], 16, %2;"
                 :: "r"(dst), "l"(src), "r"(sz));
}
__device__ __forceinline__ uint32_t packbf(float a, float b) {
    __nv_bfloat162 p = __floats2bfloat162_rn(a, b);
    return *(uint32_t*)&p;
}

// ---------------- fp32 -> bf16 convert --------------------------------------
__global__ void f2bf_kernel(const float4* __restrict__ s, uint2* __restrict__ d, int n4)
{
    int i = blockIdx.x * blockDim.x + threadIdx.x;
    if (i >= n4) return;
    float4 v = s[i];
    __nv_bfloat162 lo = __floats2bfloat162_rn(v.x, v.y);
    __nv_bfloat162 hi = __floats2bfloat162_rn(v.z, v.w);
    uint2 o;
    o.x = *(uint32_t*)&lo;
    o.y = *(uint32_t*)&hi;
    d[i] = o;
}

// ---------------- rmsnorm (bf16 out + optional fp32 out) -------------------
__global__ __launch_bounds__(256) void rmsnorm_kernel(
    const float* __restrict__ x, const float* __restrict__ w,
    bf16* __restrict__ obf, float* __restrict__ ofp)
{
    int row = blockIdx.x;
    int tid = threadIdx.x;
    const float4* xr = (const float4*)(x + (size_t)row*DM);
    float4 v = xr[tid];
    float ss = v.x*v.x + v.y*v.y + v.z*v.z + v.w*v.w;
    __shared__ float red[8];
    #pragma unroll
    for (int ofs = 16; ofs > 0; ofs >>= 1) ss += __shfl_down_sync(0xffffffffu, ss, ofs);
    if ((tid & 31) == 0) red[tid >> 5] = ss;
    __syncthreads();
    __shared__ float sr;
    if (tid == 0) {
        float t = 0.f;
        #pragma unroll
        for (int i = 0; i < 8; i++) t += red[i];
        sr = rsqrtf(t / (float)DM + 1e-5f);
    }
    __syncthreads();
    float r = sr;
    float4 wv = ((const float4*)w)[tid];
    float4 o;
    o.x = v.x*r*wv.x; o.y = v.y*r*wv.y; o.z = v.z*r*wv.z; o.w = v.w*r*wv.w;
    __nv_bfloat162 lo = __floats2bfloat162_rn(o.x, o.y);
    __nv_bfloat162 hi = __floats2bfloat162_rn(o.z, o.w);
    uint2 ob; ob.x = *(uint32_t*)&lo; ob.y = *(uint32_t*)&hi;
    *(uint2*)(obf + (size_t)row*DM + tid*4) = ob;
    if (ofp) ((float4*)(ofp + (size_t)row*DM))[tid] = o;
}

// ---------------- bf16 HMMA GEMM: C[M,N] = A @ B^T (+resid) ----------------
// 3-stage cp.async, single barrier per K-chunk. 96KB smem -> 2 CTA/SM.
#define GSTG 16384
template<bool GATHER>
__global__ __launch_bounds__(256) void gemm_bf(
    const bf16* __restrict__ A, const bf16* __restrict__ B,
    const float* __restrict__ resid, float* __restrict__ C,
    int M, int N, int K, int shiftA)
{
    extern __shared__ char smem[];
    const int* sl = nullptr;
    if (GATHER) {
        int e = blockIdx.z;
        M = g_cnt[e];
        if ((int)blockIdx.y * 128 >= M) return;
        sl = g_slot + e * SEQ;
        B += (size_t)e * N * K;
    }
    int m0 = blockIdx.y * 128, n0 = blockIdx.x * 128;
    int tid = threadIdx.x, warp = tid >> 5, lane = tid & 31;
    int wm = (warp >> 2) * 64, wn = (warp & 3) * 32;
    uint32_t sbase = (uint32_t)__cvta_generic_to_shared(smem);
    uint32_t aoff[3], boff[3];
    #pragma unroll
    for (int s = 0; s < 3; s++) {
        aoff[s] = sbase + s*GSTG;
        boff[s] = sbase + 3*GSTG + s*GSTG;
    }

    int lrow = tid >> 1;
    int lsg  = (tid & 1) * 4;
    const bf16* Arow; int szA = 16;
    if (GATHER) {
        int gm = m0 + lrow;
        if (gm < M) Arow = A + (size_t)(sl[gm] >> shiftA) * K;
        else { Arow = A; szA = 0; }
    } else {
        Arow = A + (size_t)(m0 + lrow) * K;
    }
    const bf16* Brow = B + (size_t)(n0 + lrow) * K;
    uint32_t dsw = (uint32_t)lrow * 128u;
    int rxor = lrow & 7;

    float acc[4][4][4];
    #pragma unroll
    for (int i = 0; i < 4; i++)
        #pragma unroll
        for (int j = 0; j < 4; j++)
            #pragma unroll
            for (int q = 0; q < 4; q++) acc[i][j][q] = 0.f;

    int CC = K / 64;
    auto loadChunk = [&](int c) {
        int s = c % 3;
        const char* pa = (const char*)(Arow + c*64);
        const char* pb = (const char*)(Brow + c*64);
        #pragma unroll
        for (int i = 0; i < 4; i++) {
            int seg = lsg + i;
            uint32_t o = dsw + (uint32_t)((seg ^ rxor) * 16);
            cpa(aoff[s] + o, pa + seg*16, szA);
            cpa(boff[s] + o, pb + seg*16, 16);
        }
        asm volatile("cp.async.commit_group;" ::: "memory");
    };
    loadChunk(0);
    if (CC > 1) loadChunk(1);

    int lt = lane >> 3;
    int rl = lane & 7;
    int th = (lt & 1) * 8;
    int ts = lane >> 4;

    for (int c = 0; c < CC; c++) {
        if (c + 1 < CC) asm volatile("cp.async.wait_group 1;" ::: "memory");
        else            asm volatile("cp.async.wait_group 0;" ::: "memory");
        __syncthreads();
        if (c + 2 < CC) loadChunk(c + 2);

        uint32_t Ab = aoff[c % 3], Bb = boff[c % 3];
        #pragma unroll
        for (int kk = 0; kk < 4; kk++) {
            uint32_t af[4][4], bfm[2][4];
            #pragma unroll
            for (int i = 0; i < 4; i++) {
                int row = wm + i*16 + th + rl;
                int seg = 2*kk + ts;
                ldsm4(af[i], Ab + row*128 + ((seg ^ (row & 7)) << 4));
            }
            #pragma unroll
            for (int j = 0; j < 2; j++) {
                int nr = wn + j*16 + th + rl;
                int seg = 2*kk + ts;
                ldsm4(bfm[j], Bb + nr*128 + ((seg ^ (nr & 7)) << 4));
            }
            #pragma unroll
            for (int i = 0; i < 4; i++)
                #pragma unroll
                for (int jn = 0; jn < 4; jn++) {
                    int jj = jn >> 1, hi = jn & 1;
                    mma_bf16(acc[i][jn], af[i][0], af[i][1], af[i][2], af[i][3],
                             bfm[jj][hi], bfm[jj][hi+2]);
                }
        }
    }

    int g = lane >> 2, tg = lane & 3;
    #pragma unroll
    for (int i = 0; i < 4; i++) {
        int r0 = m0 + wm + i*16 + g;
        int r1 = r0 + 8;
        bool v0, v1;
        int row0, row1;
        if (GATHER) {
            v0 = r0 < M; v1 = r1 < M;
            row0 = v0 ? sl[r0] : 0;
            row1 = v1 ? sl[r1] : 0;
        } else {
            v0 = v1 = true; row0 = r0; row1 = r1;
        }
        #pragma unroll
        for (int j = 0; j < 4; j++) {
            int c0 = n0 + wn + j*8 + tg*2;
            if (v0) {
                float2 v; v.x = acc[i][j][0]; v.y = acc[i][j][1];
                if (resid) {
                    v.x += resid[(size_t)row0*N + c0];
                    v.y += resid[(size_t)row0*N + c0 + 1];
                }
                *(float2*)(C + (size_t)row0*N + c0) = v;
            }
            if (v1) {
                float2 v; v.x = acc[i][j][2]; v.y = acc[i][j][3];
                if (resid) {
                    v.x += resid[(size_t)row1*N + c0];
                    v.y += resid[(size_t)row1*N + c0 + 1];
                }
                *(float2*)(C + (size_t)row1*N + c0) = v;
            }
        }
    }
}

// ---------------- QKV GEMM with fused RoPE/split epilogue -------------------
__device__ __forceinline__ void rope_write(
    int t, int c0, float vx, float vy, const float* __restrict__ freqs)
{
    if (c0 < DM) {
        int h = c0 >> 6, d = c0 & 63, p = d >> 1;
        float cs = freqs[((size_t)t*32 + p)*2 + 0];
        float sn = freqs[((size_t)t*32 + p)*2 + 1];
        float2 o;
        o.x = __uint_as_float(f2tf32((vx*cs - vy*sn) * 0.125f));
        o.y = __uint_as_float(f2tf32((vy*cs + vx*sn) * 0.125f));
        *(float2*)(g_q + ((size_t)h*SEQ + t)*HDIM + d) = o;
    } else if (c0 < DM + NKV*HDIM) {
        int c = c0 - DM;
        int kh = c >> 6, d = c & 63, p = d >> 1;
        float cs = freqs[((size_t)t*32 + p)*2 + 0];
        float sn = freqs[((size_t)t*32 + p)*2 + 1];
        float2 o;
        o.x = __uint_as_float(f2tf32(vx*cs - vy*sn));
        o.y = __uint_as_float(f2tf32(vy*cs + vx*sn));
        *(float2*)(g_k + ((size_t)kh*SEQ + t)*HDIM + d) = o;
    } else {
        int c = c0 - DM - NKV*HDIM;
        int vh = c >> 6, d = c & 63;
        g_vt[((size_t)(vh*HDIM + d  ))*SEQ + t] = __float2bfloat16(vx);
        g_vt[((size_t)(vh*HDIM + d+1))*SEQ + t] = __float2bfloat16(vy);
    }
}

__global__ __launch_bounds__(256) void gemm_qkv(
    const bf16* __restrict__ A, const bf16* __restrict__ B,
    const float* __restrict__ freqs)
{
    extern __shared__ char smem[];
    const int K = DM;
    int m0 = blockIdx.y * 128, n0 = blockIdx.x * 128;
    int tid = threadIdx.x, warp = tid >> 5, lane = tid & 31;
    int wm = (warp >> 2) * 64, wn = (warp & 3) * 32;
    uint32_t sbase = (uint32_t)__cvta_generic_to_shared(smem);
    uint32_t aoff[3], boff[3];
    #pragma unroll
    for (int s = 0; s < 3; s++) {
        aoff[s] = sbase + s*GSTG;
        boff[s] = sbase + 3*GSTG + s*GSTG;
    }

    int lrow = tid >> 1;
    int lsg  = (tid & 1) * 4;
    const bf16* Arow = A + (size_t)(m0 + lrow) * K;
    const bf16* Brow = B + (size_t)(n0 + lrow) * K;
    uint32_t dsw = (uint32_t)lrow * 128u;
    int rxor = lrow & 7;

    float acc[4][4][4];
    #pragma unroll
    for (int i = 0; i < 4; i++)
        #pragma unroll
        for (int j = 0; j < 4; j++)
            #pragma unroll
            for (int q = 0; q < 4; q++) acc[i][j][q] = 0.f;

    const int CC = K / 64;
    auto loadChunk = [&](int c) {
        int s = c % 3;
        const char* pa = (const char*)(Arow + c*64);
        const char* pb = (const char*)(Brow + c*64);
        #pragma unroll
        for (int i = 0; i < 4; i++) {
            int seg = lsg + i;
            uint32_t o = dsw + (uint32_t)((seg ^ rxor) * 16);
            cpa(aoff[s] + o, pa + seg*16, 16);
            cpa(boff[s] + o, pb + seg*16, 16);
        }
        asm volatile("cp.async.commit_group;" ::: "memory");
    };
    loadChunk(0);
    loadChunk(1);

    int lt = lane >> 3;
    int rl = lane & 7;
    int th = (lt & 1) * 8;
    int ts = lane >> 4;

    for (int c = 0; c < CC; c++) {
        if (c + 1 < CC) asm volatile("cp.async.wait_group 1;" ::: "memory");
        else            asm volatile("cp.async.wait_group 0;" ::: "memory");
        __syncthreads();
        if (c + 2 < CC) loadChunk(c + 2);

        uint32_t Ab = aoff[c % 3], Bb = boff[c % 3];
        #pragma unroll
        for (int kk = 0; kk < 4; kk++) {
            uint32_t af[4][4], bfm[2][4];
            #pragma unroll
            for (int i = 0; i < 4; i++) {
                int row = wm + i*16 + th + rl;
                int seg = 2*kk + ts;
                ldsm4(af[i], Ab + row*128 + ((seg ^ (row & 7)) << 4));
            }
            #pragma unroll
            for (int j = 0; j < 2; j++) {
                int nr = wn + j*16 + th + rl;
                int seg = 2*kk + ts;
                ldsm4(bfm[j], Bb + nr*128 + ((seg ^ (nr & 7)) << 4));
            }
            #pragma unroll
            for (int i = 0; i < 4; i++)
                #pragma unroll
                for (int jn = 0; jn < 4; jn++) {
                    int jj = jn >> 1, hi = jn & 1;
                    mma_bf16(acc[i][jn], af[i][0], af[i][1], af[i][2], af[i][3],
                             bfm[jj][hi], bfm[jj][hi+2]);
                }
        }
    }

    int g = lane >> 2, tg = lane & 3;
    #pragma unroll
    for (int i = 0; i < 4; i++) {
        int t0 = m0 + wm + i*16 + g;
        int t1 = t0 + 8;
        #pragma unroll
        for (int j = 0; j < 4; j++) {
            int c0 = n0 + wn + j*8 + tg*2;
            rope_write(t0, c0, acc[i][j][0], acc[i][j][1], freqs);
            rope_write(t1, c0, acc[i][j][2], acc[i][j][3], freqs);
        }
    }
}

// ---------------- fused MoE w1/w3 GEMM + silu*mul (bf16 out) ---------------
// 2-STAGE double buffer (96KB smem -> 2 CTA/SM; was 3-stage/144KB/1 CTA).
// Pattern: wait(c) -> barrier -> issue(c+1) into other stage (prior reads of
// that stage ordered by this barrier) -> compute(c) overlapping the load.
__global__ __launch_bounds__(256) void gemm_w13(
    const bf16* __restrict__ A, const bf16* __restrict__ B1,
    const bf16* __restrict__ B3)
{
    extern __shared__ char smem[];
    int e = blockIdx.z;
    int M = g_cnt[e];
    if ((int)blockIdx.y * 128 >= M) return;
    const int* sl = g_slot + e * SEQ;
    B1 += (size_t)e * NI * DM;
    B3 += (size_t)e * NI * DM;

    int m0 = blockIdx.y * 128, n0 = blockIdx.x * 128;
    int tid = threadIdx.x, warp = tid >> 5, lane = tid & 31;
    int wm = (warp >> 2) * 64, wn = (warp & 3) * 32;
    uint32_t sbase = (uint32_t)__cvta_generic_to_shared(smem);
    uint32_t aoff[2], b1off[2], b3off[2];
    #pragma unroll
    for (int s = 0; s < 2; s++) {
        aoff[s]  = sbase + s*GSTG;
        b1off[s] = sbase + 2*GSTG + s*GSTG;
        b3off[s] = sbase + 4*GSTG + s*GSTG;
    }

    int lrow = tid >> 1;
    int lsg  = (tid & 1) * 4;
    const bf16* Arow; int szA = 16;
    {
        int gm = m0 + lrow;
        if (gm < M) Arow = A + (size_t)(sl[gm] >> 1) * DM;
        else { Arow = A; szA = 0; }
    }
    const bf16* B1row = B1 + (size_t)(n0 + lrow) * DM;
    const bf16* B3row = B3 + (size_t)(n0 + lrow) * DM;
    uint32_t dsw = (uint32_t)lrow * 128u;
    int rxor = lrow & 7;

    float ac1[4][4][4], ac3[4][4][4];
    #pragma unroll
    for (int i = 0; i < 4; i++)
        #pragma unroll
        for (int j = 0; j < 4; j++)
            #pragma unroll
            for (int q = 0; q < 4; q++) { ac1[i][j][q] = 0.f; ac3[i][j][q] = 0.f; }

    const int CC = DM / 64;
    auto loadChunk = [&](int c) {
        int s = c & 1;
        const char* pa  = (const char*)(Arow  + c*64);
        const char* pb1 = (const char*)(B1row + c*64);
        const char* pb3 = (const char*)(B3row + c*64);
        #pragma unroll
        for (int i = 0; i < 4; i++) {
            int seg = lsg + i;
            uint32_t o = dsw + (uint32_t)((seg ^ rxor) * 16);
            cpa(aoff[s]  + o, pa  + seg*16, szA);
            cpa(b1off[s] + o, pb1 + seg*16, 16);
            cpa(b3off[s] + o, pb3 + seg*16, 16);
        }
        asm volatile("cp.async.commit_group;" ::: "memory");
    };
    loadChunk(0);

    int lt = lane >> 3, rl = lane & 7;
    int th = (lt & 1) * 8;
    int ts = lane >> 4;

    for (int c = 0; c < CC; c++) {
        asm volatile("cp.async.wait_group 0;" ::: "memory");
        __syncthreads();
        if (c + 1 < CC) loadChunk(c + 1);

        uint32_t Ab = aoff[c & 1], B1b = b1off[c & 1], B3b = b3off[c & 1];
        #pragma unroll
        for (int kk = 0; kk < 4; kk++) {
            uint32_t af[4][4], f1[2][4], f3[2][4];
            #pragma unroll
            for (int i = 0; i < 4; i++) {
                int row = wm + i*16 + th + rl;
                int seg = 2*kk + ts;
                ldsm4(af[i], Ab + row*128 + ((seg ^ (row & 7)) << 4));
            }
            #pragma unroll
            for (int j = 0; j < 2; j++) {
                int nr = wn + j*16 + th + rl;
                int seg = 2*kk + ts;
                ldsm4(f1[j], B1b + nr*128 + ((seg ^ (nr & 7)) << 4));
                ldsm4(f3[j], B3b + nr*128 + ((seg ^ (nr & 7)) << 4));
            }
            #pragma unroll
            for (int i = 0; i < 4; i++)
                #pragma unroll
                for (int jn = 0; jn < 4; jn++) {
                    int jj = jn >> 1, hi = jn & 1;
                    mma_bf16(ac1[i][jn], af[i][0], af[i][1], af[i][2], af[i][3],
                             f1[jj][hi], f1[jj][hi+2]);
                    mma_bf16(ac3[i][jn], af[i][0], af[i][1], af[i][2], af[i][3],
                             f3[jj][hi], f3[jj][hi+2]);
                }
        }
    }

    int g = lane >> 2, tg = lane & 3;
    #pragma unroll
    for (int i = 0; i < 4; i++) {
        int r0 = m0 + wm + i*16 + g;
        int r1 = r0 + 8;
        bool v0 = r0 < M, v1 = r1 < M;
        int row0 = v0 ? sl[r0] : 0;
        int row1 = v1 ? sl[r1] : 0;
        #pragma unroll
        for (int j = 0; j < 4; j++) {
            int c0 = n0 + wn + j*8 + tg*2;
            if (v0) {
                float a0 = ac1[i][j][0], a1 = ac1[i][j][1];
                float u0 = a0 / (1.f + __expf(-a0)) * ac3[i][j][0];
                float u1 = a1 / (1.f + __expf(-a1)) * ac3[i][j][1];
                *(__nv_bfloat162*)(g_gb + (size_t)row0*NI + c0) = __floats2bfloat162_rn(u0, u1);
            }
            if (v1) {
                float a0 = ac1[i][j][2], a1 = ac1[i][j][3];
                float u0 = a0 / (1.f + __expf(-a0)) * ac3[i][j][2];
                float u1 = a1 / (1.f + __expf(-a1)) * ac3[i][j][3];
                *(__nv_bfloat162*)(g_gb + (size_t)row1*NI + c0) = __floats2bfloat162_rn(u0, u1);
            }
        }
    }
}

// ---------------- attention v6: uniform-chunk split flash -------------------
#define ASTR 68
#define VSTR 72
__global__ __launch_bounds__(128) void attn6_kernel()
{
    __shared__ float Ks[64*ASTR];
    __shared__ bf16  Vt[64*VSTR];

    int qt = blockIdx.x, h = blockIdx.y, z = blockIdx.z;
    int kvh = h >> 2;
    int tid = threadIdx.x, warp = tid >> 5, lane = tid & 31;
    int g = lane >> 2, tg = lane & 3;
    int wq = warp * 16;
    int q0 = qt * 64;

    int n = qt + 1;
    int lo = z * CHUNK;
    int hi = min(n, lo + CHUNK);

    float oc[8][4];
    #pragma unroll
    for (int j = 0; j < 8; j++)
        #pragma unroll
        for (int q = 0; q < 4; q++) oc[j][q] = 0.f;
    float mrow[2] = {-1e30f, -1e30f};
    float lrow[2] = {0.f, 0.f};

    if (lo < hi) {
        for (int i = tid; i < 64*16; i += 128) {
            int row = i >> 4, c4 = (i & 15) * 4;
            *(float4*)&Ks[row*ASTR + c4] =
                *(const float4*)(g_q + ((size_t)h*SEQ + q0 + row)*HDIM + c4);
        }
        __syncthreads();
        uint32_t aq[8][4];
        #pragma unroll
        for (int kk = 0; kk < 8; kk++) {
            aq[kk][0] = __float_as_uint(Ks[(wq+g)*ASTR + kk*8 + tg]);
            aq[kk][1] = __float_as_uint(Ks[(wq+g+8)*ASTR + kk*8 + tg]);
            aq[kk][2] = __float_as_uint(Ks[(wq+g)*ASTR + kk*8 + tg + 4]);
            aq[kk][3] = __float_as_uint(Ks[(wq+g+8)*ASTR + kk*8 + tg + 4]);
        }
        __syncthreads();

        for (int kt = lo; kt < hi; kt++) {
            for (int i = tid; i < 1024; i += 128) {
                int row = i >> 4, c4 = (i & 15) * 4;
                *(float4*)&Ks[row*ASTR + c4] =
                    *(const float4*)(g_k + ((size_t)kvh*SEQ + kt*64 + row)*HDIM + c4);
            }
            for (int i = tid; i < 512; i += 128) {
                int row = i >> 3, seg = i & 7;
                *(uint4*)&Vt[row*VSTR + seg*8] =
                    *(const uint4*)(g_vt + ((size_t)(kvh*HDIM + row))*SEQ + kt*64 + seg*8);
            }
            __syncthreads();

            float sc[8][4];
            #pragma unroll
            for (int j = 0; j < 8; j++)
                #pragma unroll
                for (int q = 0; q < 4; q++) sc[j][q] = 0.f;
            #pragma unroll
            for (int kk = 0; kk < 8; kk++) {
                #pragma unroll
                for (int j = 0; j < 8; j++) {
                    uint32_t b0 = __float_as_uint(Ks[(j*8+g)*ASTR + kk*8 + tg]);
                    uint32_t b1 = __float_as_uint(Ks[(j*8+g)*ASTR + kk*8 + tg + 4]);
                    mma_tf32(sc[j], aq[kk][0], aq[kk][1], aq[kk][2], aq[kk][3], b0, b1);
                }
            }

            if (kt == qt) {
                int r0g = q0 + wq + g, r1g = r0g + 8;
                #pragma unroll
                for (int j = 0; j < 8; j++) {
                    int c0 = kt*64 + j*8 + tg*2;
                    if (c0     > r0g) sc[j][0] = -1e30f;
                    if (c0 + 1 > r0g) sc[j][1] = -1e30f;
                    if (c0     > r1g) sc[j][2] = -1e30f;
                    if (c0 + 1 > r1g) sc[j][3] = -1e30f;
                }
            }

            float mx0 = -1e30f, mx1 = -1e30f;
            #pragma unroll
            for (int j = 0; j < 8; j++) {
                mx0 = fmaxf(mx0, fmaxf(sc[j][0], sc[j][1]));
                mx1 = fmaxf(mx1, fmaxf(sc[j][2], sc[j][3]));
            }
            mx0 = fmaxf(mx0, __shfl_xor_sync(0xffffffffu, mx0, 1));
            mx0 = fmaxf(mx0, __shfl_xor_sync(0xffffffffu, mx0, 2));
            mx1 = fmaxf(mx1, __shfl_xor_sync(0xffffffffu, mx1, 1));
            mx1 = fmaxf(mx1, __shfl_xor_sync(0xffffffffu, mx1, 2));
            float mn0 = fmaxf(mrow[0], mx0), mn1 = fmaxf(mrow[1], mx1);
            float s0 = __expf(mrow[0] - mn0), s1 = __expf(mrow[1] - mn1);
            float ls0 = 0.f, ls1 = 0.f;
            #pragma unroll
            for (int j = 0; j < 8; j++) {
                sc[j][0] = __expf(sc[j][0] - mn0);
                sc[j][1] = __expf(sc[j][1] - mn0);
                sc[j][2] = __expf(sc[j][2] - mn1);
                sc[j][3] = __expf(sc[j][3] - mn1);
                ls0 += sc[j][0] + sc[j][1];
                ls1 += sc[j][2] + sc[j][3];
            }
            ls0 += __shfl_xor_sync(0xffffffffu, ls0, 1);
            ls0 += __shfl_xor_sync(0xffffffffu, ls0, 2);
            ls1 += __shfl_xor_sync(0xffffffffu, ls1, 1);
            ls1 += __shfl_xor_sync(0xffffffffu, ls1, 2);
            lrow[0] = lrow[0]*s0 + ls0;
            lrow[1] = lrow[1]*s1 + ls1;
            mrow[0] = mn0; mrow[1] = mn1;
            #pragma unroll
            for (int j = 0; j < 8; j++) {
                oc[j][0] *= s0; oc[j][1] *= s0;
                oc[j][2] *= s1; oc[j][3] *= s1;
            }

            uint32_t pa[4][4];
            #pragma unroll
            for (int kk = 0; kk < 4; kk++) {
                pa[kk][0] = packbf(sc[2*kk][0],   sc[2*kk][1]);
                pa[kk][1] = packbf(sc[2*kk][2],   sc[2*kk][3]);
                pa[kk][2] = packbf(sc[2*kk+1][0], sc[2*kk+1][1]);
                pa[kk][3] = packbf(sc[2*kk+1][2], sc[2*kk+1][3]);
            }
            #pragma unroll
            for (int kk = 0; kk < 4; kk++) {
                #pragma unroll
                for (int j = 0; j < 8; j++) {
                    uint32_t b0 = *(const uint32_t*)&Vt[(j*8+g)*VSTR + kk*16 + tg*2];
                    uint32_t b1 = *(const uint32_t*)&Vt[(j*8+g)*VSTR + kk*16 + tg*2 + 8];
                    mma_bf16(oc[j], pa[kk][0], pa[kk][1], pa[kk][2], pa[kk][3], b0, b1);
                }
            }
            __syncthreads();
        }
    }

    size_t pb = (size_t)z * NH * SEQ;
    int r0 = q0 + wq + g, r1 = r0 + 8;
    size_t hr0 = (size_t)h*SEQ + r0, hr1 = (size_t)h*SEQ + r1;
    #pragma unroll
    for (int j = 0; j < 8; j++) {
        int c0 = j*8 + tg*2;
        float2 v0; v0.x = oc[j][0]; v0.y = oc[j][1];
        float2 v1; v1.x = oc[j][2]; v1.y = oc[j][3];
        *(float2*)&g_po[(pb + hr0)*HDIM + c0] = v0;
        *(float2*)&g_po[(pb + hr1)*HDIM + c0] = v1;
    }
    if (tg == 0) {
        g_pm[pb + hr0] = mrow[0];
        g_pm[pb + hr1] = mrow[1];
        g_pl[pb + hr0] = lrow[0];
        g_pl[pb + hr1] = lrow[1];
    }
}

// ---------------- split reduce: merge NSPLIT partials -> y_bf ---------------
__global__ void attn_reduce_kernel()
{
    int i = blockIdx.x * blockDim.x + threadIdx.x;
    if (i >= NH*SEQ*(HDIM/2)) return;
    int hrow = i >> 5;
    int c2 = (i & 31) * 2;
    int h = hrow / SEQ, row = hrow % SEQ;
    float M = -1e30f;
    float ms[NSPLIT], ls[NSPLIT];
    #pragma unroll
    for (int s = 0; s < NSPLIT; s++) {
        ms[s] = g_pm[s*NH*SEQ + hrow];
        ls[s] = g_pl[s*NH*SEQ + hrow];
        M = fmaxf(M, ms[s]);
    }
    float den = 0.f, vx = 0.f, vy = 0.f;
    #pragma unroll
    for (int s = 0; s < NSPLIT; s++) {
        float w = __expf(ms[s] - M);
        den += ls[s] * w;
        float2 o = *(const float2*)&g_po[((size_t)s*NH*SEQ + hrow)*HDIM + c2];
        vx += o.x * w;
        vy += o.y * w;
    }
    float inv = 1.f / den;
    *(__nv_bfloat162*)(g_y_bf + (size_t)row*DM + h*HDIM + c2) =
        __floats2bfloat162_rn(vx*inv, vy*inv);
}

// ---------------- gating ----------------------------------------------------
__global__ __launch_bounds__(256) void gating_kernel(const float* __restrict__ gw)
{
    int t = blockIdx.x;
    int tid = threadIdx.x;
    int e = tid >> 5, lane = tid & 31;
    float s = 0.f;
    const float* hr = g_hf + (size_t)t*DM;
    const float* wr = gw + (size_t)e*DM;
    for (int d = lane; d < DM; d += 32) s += hr[d]*wr[d];
    #pragma unroll
    for (int ofs = 16; ofs > 0; ofs >>= 1) s += __shfl_down_sync(0xffffffffu, s, ofs);
    __shared__ float lg[NE];
    if (lane == 0) lg[e] = s;
    __syncthreads();
    if (tid == 0) {
        float mx = lg[0];
        #pragma unroll
        for (int i = 1; i < NE; i++) mx = fmaxf(mx, lg[i]);
        float p[NE]; float den = 0.f;
        #pragma unroll
        for (int i = 0; i < NE; i++) { p[i] = expf(lg[i]-mx); den += p[i]; }
        #pragma unroll
        for (int i = 0; i < NE; i++) p[i] /= den;
        int i1 = 0;
        #pragma unroll
        for (int i = 1; i < NE; i++) if (p[i] > p[i1]) i1 = i;
        int i2 = (i1 == 0) ? 1 : 0;
        #pragma unroll
        for (int i = 0; i < NE; i++) if (i != i1 && p[i] > p[i2]) i2 = i;
        float w1 = p[i1], w2 = p[i2];
        float sw2 = w1 + w2;
        w1 /= sw2; w2 /= sw2;
        int pos1 = atomicAdd(&g_cnt[i1], 1);
        g_slot[i1*SEQ + pos1] = 2*t;
        g_wslot[2*t] = w1;
        int pos2 = atomicAdd(&g_cnt[i2], 1);
        g_slot[i2*SEQ + pos2] = 2*t + 1;
        g_wslot[2*t+1] = w2;
    }
}

// ---------------- final combine ---------------------------------------------
__global__ __launch_bounds__(256) void combine_kernel(float* __restrict__ out)
{
    int t = blockIdx.x;
    int tid = threadIdx.x;
    float w0 = g_wslot[2*t], w1 = g_wslot[2*t+1];
    float4 hv = ((const float4*)(g_h + (size_t)t*DM))[tid];
    float4 a = ((const float4*)(g_os + (size_t)(2*t)*DM))[tid];
    float4 b = ((const float4*)(g_os + (size_t)(2*t+1)*DM))[tid];
    float4 o;
    o.x = hv.x + w0*a.x + w1*b.x;
    o.y = hv.y + w0*a.y + w1*b.y;
    o.z = hv.z + w0*a.z + w1*b.z;
    o.w = hv.w + w0*a.w + w1*b.w;
    ((float4*)(out + (size_t)t*DM))[tid] = o;
}

// ---------------- host launch ----------------------------------------------
#define GEMM_SMEM (6*GSTG)
#define W13_SMEM  (6*GSTG)

extern "C" void kernel_launch(void* const* d_in, const int* in_sizes, int n_in,
                              void* d_out, int out_size)
{
    const float* x      = (const float*)d_in[0];
    const float* wqkv   = (const float*)d_in[1];
    const float* wo     = (const float*)d_in[2];
    const float* gate_w = (const float*)d_in[3];
    const float* w1     = (const float*)d_in[4];
    const float* w2     = (const float*)d_in[5];
    const float* w3     = (const float*)d_in[6];
    const float* anw    = (const float*)d_in[7];
    const float* fnw    = (const float*)d_in[8];
    const float* freqs  = (const float*)d_in[9];
    float* out = (float*)d_out;

    bf16 *p_wqkv_bf, *p_wo_bf, *p_w1_bf, *p_w3_bf, *p_w2_bf;
    bf16 *p_hn_bf, *p_hf_bf, *p_y_bf, *p_gb;
    float *p_h, *p_hf, *p_os;
    int *p_cnt;
    cudaGetSymbolAddress((void**)&p_wqkv_bf, g_wqkv_bf);
    cudaGetSymbolAddress((void**)&p_wo_bf,   g_wo_bf);
    cudaGetSymbolAddress((void**)&p_w1_bf,   g_w1_bf);
    cudaGetSymbolAddress((void**)&p_w3_bf,   g_w3_bf);
    cudaGetSymbolAddress((void**)&p_w2_bf,   g_w2_bf);
    cudaGetSymbolAddress((void**)&p_hn_bf,   g_hn_bf);
    cudaGetSymbolAddress((void**)&p_hf_bf,   g_hf_bf);
    cudaGetSymbolAddress((void**)&p_y_bf,    g_y_bf);
    cudaGetSymbolAddress((void**)&p_gb,      g_gb);
    cudaGetSymbolAddress((void**)&p_h,       g_h);
    cudaGetSymbolAddress((void**)&p_hf,      g_hf);
    cudaGetSymbolAddress((void**)&p_os,      g_os);
    cudaGetSymbolAddress((void**)&p_cnt,     g_cnt);

    static cudaStream_t s2 = nullptr;
    static cudaEvent_t ev0 = nullptr, ev1 = nullptr;
    static bool attr_set = false;
    if (!attr_set) {
        cudaFuncSetAttribute(gemm_bf<false>,
            cudaFuncAttributeMaxDynamicSharedMemorySize, GEMM_SMEM);
        cudaFuncSetAttribute(gemm_bf<true>,
            cudaFuncAttributeMaxDynamicSharedMemorySize, GEMM_SMEM);
        cudaFuncSetAttribute(gemm_qkv,
            cudaFuncAttributeMaxDynamicSharedMemorySize, GEMM_SMEM);
        cudaFuncSetAttribute(gemm_w13,
            cudaFuncAttributeMaxDynamicSharedMemorySize, W13_SMEM);
        cudaStreamCreateWithFlags(&s2, cudaStreamNonBlocking);
        cudaEventCreateWithFlags(&ev0, cudaEventDisableTiming);
        cudaEventCreateWithFlags(&ev1, cudaEventDisableTiming);
        attr_set = true;
    }

    // (1) wqkv convert (main)
    {
        int n4 = QKVN*DM/4;
        f2bf_kernel<<<(n4+255)/256, 256>>>((const float4*)wqkv, (uint2*)p_wqkv_bf, n4);
    }
    // (2,3) fork first two big MoE converts on side stream
    cudaEventRecord(ev0, 0);
    cudaStreamWaitEvent(s2, ev0, 0);
    {
        int n4 = (int)((size_t)NE*NI*DM/4);
        f2bf_kernel<<<(n4+255)/256, 256, 0, s2>>>((const float4*)w1, (uint2*)p_w1_bf, n4);
        f2bf_kernel<<<(n4+255)/256, 256, 0, s2>>>((const float4*)w3, (uint2*)p_w3_bf, n4);
    }
    // (4) attn rmsnorm
    rmsnorm_kernel<<<SEQ, 256>>>(x, anw, p_hn_bf, nullptr);
    // (5) qkv GEMM + fused RoPE
    gemm_qkv<<<dim3(QKVN/128, SEQ/128), 256, GEMM_SMEM>>>(p_hn_bf, p_wqkv_bf, freqs);
    // (6) attention v6
    attn6_kernel<<<dim3(SEQ/64, NH, NSPLIT), 128>>>();
    // (7+) rest
    {
        int n4 = (int)((size_t)NE*NI*DM/4);
        f2bf_kernel<<<(n4+255)/256, 256, 0, s2>>>((const float4*)w2, (uint2*)p_w2_bf, n4);
    }
    cudaEventRecord(ev1, s2);
    {
        int n4 = DM*DM/4;
        f2bf_kernel<<<(n4+255)/256, 256>>>((const float4*)wo, (uint2*)p_wo_bf, n4);
    }
    attn_reduce_kernel<<<(NH*SEQ*(HDIM/2) + 255)/256, 256>>>();
    gemm_bf<false><<<dim3(DM/128, SEQ/128), 256, GEMM_SMEM>>>(
        p_y_bf, p_wo_bf, x, p_h, SEQ, DM, DM, 0);
    rmsnorm_kernel<<<SEQ, 256>>>(p_h, fnw, p_hf_bf, p_hf);
    cudaMemsetAsync(p_cnt, 0, NE*sizeof(int), 0);
    gating_kernel<<<SEQ, 256>>>(gate_w);

    cudaStreamWaitEvent(0, ev1, 0);
    gemm_w13<<<dim3(NI/128, SEQ/128, NE), 256, W13_SMEM>>>(
        p_hf_bf, p_w1_bf, p_w3_bf);
    gemm_bf<true><<<dim3(DM/128, SEQ/128, NE), 256, GEMM_SMEM>>>(
        p_gb, p_w2_bf, nullptr, p_os, 0, DM, NI, 0);
    combine_kernel<<<SEQ, 256>>>(out);
}

// round 14
// speedup vs baseline: 1.2161x; 1.0046x over previous
#include <cuda_runtime.h>
#include <cuda_bf16.h>
#include <math.h>
#include <stdint.h>

#define SEQ 2048
#define DM 1024
#define NH 16
#define NKV 4
#define HDIM 64
#define NE 8
#define NI 3584
#define QKVN 1536
#define NSLOTS (2*SEQ)
#define NSPLIT 8
#define CHUNK 4

typedef __nv_bfloat16 bf16;

// ---------------- scratch (device globals; no allocations) ----------------
__device__ bf16  g_wqkv_bf[QKVN*DM];
__device__ bf16  g_wo_bf[DM*DM];
__device__ bf16  g_w1_bf[(size_t)NE*NI*DM];
__device__ bf16  g_w3_bf[(size_t)NE*NI*DM];
__device__ bf16  g_w2_bf[(size_t)NE*DM*NI];
__device__ bf16  g_hn_bf[SEQ*DM];
__device__ float g_q[NH*SEQ*HDIM];      // tf32-rounded, pre-scaled 0.125
__device__ float g_k[NKV*SEQ*HDIM];     // tf32-rounded
__device__ bf16  g_vt[NKV*HDIM*SEQ];    // bf16, transposed [kvh][d][t]
__device__ float g_po[(size_t)NSPLIT*NH*SEQ*HDIM];
__device__ float g_pm[NSPLIT*NH*SEQ];
__device__ float g_pl[NSPLIT*NH*SEQ];
__device__ bf16  g_y_bf[SEQ*DM];
__device__ float g_h[SEQ*DM];
__device__ bf16  g_hf_bf[SEQ*DM];
__device__ int   g_cnt[NE];
__device__ int   g_slot[NE*SEQ];
__device__ float g_wslot[NSLOTS];
__device__ bf16  g_gb[(size_t)NSLOTS*NI];
__device__ float g_os[(size_t)NSLOTS*DM];

// ---------------- helpers ---------------------------------------------------
__device__ __forceinline__ uint32_t f2tf32(float f) {
    uint32_t r;
    asm("cvt.rna.tf32.f32 %0, %1;" : "=r"(r) : "f"(f));
    return r;
}
__device__ __forceinline__ void mma_tf32(float c[4],
    uint32_t a0, uint32_t a1, uint32_t a2, uint32_t a3,
    uint32_t b0, uint32_t b1)
{
    asm volatile(
        "mma.sync.aligned.m16n8k8.row.col.f32.tf32.tf32.f32 "
        "{%0,%1,%2,%3}, {%4,%5,%6,%7}, {%8,%9}, {%0,%1,%2,%3};"
        : "+f"(c[0]), "+f"(c[1]), "+f"(c[2]), "+f"(c[3])
        : "r"(a0), "r"(a1), "r"(a2), "r"(a3), "r"(b0), "r"(b1));
}
__device__ __forceinline__ void mma_bf16(float c[4],
    uint32_t a0, uint32_t a1, uint32_t a2, uint32_t a3,
    uint32_t b0, uint32_t b1)
{
    asm volatile(
        "mma.sync.aligned.m16n8k16.row.col.f32.bf16.bf16.f32 "
        "{%0,%1,%2,%3}, {%4,%5,%6,%7}, {%8,%9}, {%0,%1,%2,%3};"
        : "+f"(c[0]), "+f"(c[1]), "+f"(c[2]), "+f"(c[3])
        : "r"(a0), "r"(a1), "r"(a2), "r"(a3), "r"(b0), "r"(b1));
}
__device__ __forceinline__ void ldsm4(uint32_t r[4], uint32_t addr) {
    asm volatile("ldmatrix.sync.aligned.m8n8.x4.shared.b16 {%0,%1,%2,%3}, [%4];"
                 : "=r"(r[0]), "=r"(r[1]), "=r"(r[2]), "=r"(r[3]) : "r"(addr));
}
__device__ __forceinline__ void cpa(uint32_t dst, const void* src, int sz) {
    asm volatile("cp.async.cg.shared.global [%0], [%1], 16, %2;"
                 :: "r"(dst), "l"(src), "r"(sz));
}
__device__ __forceinline__ uint32_t packbf(float a, float b) {
    __nv_bfloat162 p = __floats2bfloat162_rn(a, b);
    return *(uint32_t*)&p;
}

// ---------------- fp32 -> bf16 convert --------------------------------------
__global__ void f2bf_kernel(const float4* __restrict__ s, uint2* __restrict__ d, int n4)
{
    int i = blockIdx.x * blockDim.x + threadIdx.x;
    if (i >= n4) return;
    float4 v = s[i];
    __nv_bfloat162 lo = __floats2bfloat162_rn(v.x, v.y);
    __nv_bfloat162 hi = __floats2bfloat162_rn(v.z, v.w);
    uint2 o;
    o.x = *(uint32_t*)&lo;
    o.y = *(uint32_t*)&hi;
    d[i] = o;
}

// ---------------- rmsnorm (bf16 out) ----------------------------------------
__global__ __launch_bounds__(256) void rmsnorm_kernel(
    const float* __restrict__ x, const float* __restrict__ w,
    bf16* __restrict__ obf)
{
    int row = blockIdx.x;
    int tid = threadIdx.x;
    const float4* xr = (const float4*)(x + (size_t)row*DM);
    float4 v = xr[tid];
    float ss = v.x*v.x + v.y*v.y + v.z*v.z + v.w*v.w;
    __shared__ float red[8];
    #pragma unroll
    for (int ofs = 16; ofs > 0; ofs >>= 1) ss += __shfl_down_sync(0xffffffffu, ss, ofs);
    if ((tid & 31) == 0) red[tid >> 5] = ss;
    __syncthreads();
    __shared__ float sr;
    if (tid == 0) {
        float t = 0.f;
        #pragma unroll
        for (int i = 0; i < 8; i++) t += red[i];
        sr = rsqrtf(t / (float)DM + 1e-5f);
    }
    __syncthreads();
    float r = sr;
    float4 wv = ((const float4*)w)[tid];
    float4 o;
    o.x = v.x*r*wv.x; o.y = v.y*r*wv.y; o.z = v.z*r*wv.z; o.w = v.w*r*wv.w;
    __nv_bfloat162 lo = __floats2bfloat162_rn(o.x, o.y);
    __nv_bfloat162 hi = __floats2bfloat162_rn(o.z, o.w);
    uint2 ob; ob.x = *(uint32_t*)&lo; ob.y = *(uint32_t*)&hi;
    *(uint2*)(obf + (size_t)row*DM + tid*4) = ob;
}

// ---------------- fused ffn rmsnorm + gating --------------------------------
// rmsnorm row -> bf16 out; gate logits computed from the same fp32 values
// in-register; thread 0 does softmax + top-2 + slot scatter.
__global__ __launch_bounds__(256) void rmsnorm_gate_kernel(
    const float* __restrict__ x, const float* __restrict__ w,
    const float* __restrict__ gw, bf16* __restrict__ obf)
{
    int row = blockIdx.x;
    int tid = threadIdx.x;
    const float4* xr = (const float4*)(x + (size_t)row*DM);
    float4 v = xr[tid];
    float ss = v.x*v.x + v.y*v.y + v.z*v.z + v.w*v.w;
    __shared__ float red[8];
    #pragma unroll
    for (int ofs = 16; ofs > 0; ofs >>= 1) ss += __shfl_down_sync(0xffffffffu, ss, ofs);
    if ((tid & 31) == 0) red[tid >> 5] = ss;
    __syncthreads();
    __shared__ float sr;
    if (tid == 0) {
        float t = 0.f;
        #pragma unroll
        for (int i = 0; i < 8; i++) t += red[i];
        sr = rsqrtf(t / (float)DM + 1e-5f);
    }
    __syncthreads();
    float r = sr;
    float4 wv = ((const float4*)w)[tid];
    float4 o;
    o.x = v.x*r*wv.x; o.y = v.y*r*wv.y; o.z = v.z*r*wv.z; o.w = v.w*r*wv.w;
    __nv_bfloat162 lo = __floats2bfloat162_rn(o.x, o.y);
    __nv_bfloat162 hi = __floats2bfloat162_rn(o.z, o.w);
    uint2 ob; ob.x = *(uint32_t*)&lo; ob.y = *(uint32_t*)&hi;
    *(uint2*)(obf + (size_t)row*DM + tid*4) = ob;

    // gate logits from the in-register fp32 row
    float d[NE];
    #pragma unroll
    for (int e = 0; e < NE; e++) {
        float4 gv = ((const float4*)(gw + (size_t)e*DM))[tid];
        d[e] = o.x*gv.x + o.y*gv.y + o.z*gv.z + o.w*gv.w;
    }
    #pragma unroll
    for (int e = 0; e < NE; e++) {
        #pragma unroll
        for (int ofs = 16; ofs > 0; ofs >>= 1)
            d[e] += __shfl_down_sync(0xffffffffu, d[e], ofs);
    }
    __shared__ float red2[8][NE];
    if ((tid & 31) == 0) {
        #pragma unroll
        for (int e = 0; e < NE; e++) red2[tid >> 5][e] = d[e];
    }
    __syncthreads();
    if (tid == 0) {
        float lg[NE];
        #pragma unroll
        for (int e = 0; e < NE; e++) {
            float t = 0.f;
            #pragma unroll
            for (int wpi = 0; wpi < 8; wpi++) t += red2[wpi][e];
            lg[e] = t;
        }
        float mx = lg[0];
        #pragma unroll
        for (int i = 1; i < NE; i++) mx = fmaxf(mx, lg[i]);
        float p[NE]; float den = 0.f;
        #pragma unroll
        for (int i = 0; i < NE; i++) { p[i] = expf(lg[i]-mx); den += p[i]; }
        #pragma unroll
        for (int i = 0; i < NE; i++) p[i] /= den;
        int i1 = 0;
        #pragma unroll
        for (int i = 1; i < NE; i++) if (p[i] > p[i1]) i1 = i;
        int i2 = (i1 == 0) ? 1 : 0;
        #pragma unroll
        for (int i = 0; i < NE; i++) if (i != i1 && p[i] > p[i2]) i2 = i;
        float w1 = p[i1], w2 = p[i2];
        float sw2 = w1 + w2;
        w1 /= sw2; w2 /= sw2;
        int pos1 = atomicAdd(&g_cnt[i1], 1);
        g_slot[i1*SEQ + pos1] = 2*row;
        g_wslot[2*row] = w1;
        int pos2 = atomicAdd(&g_cnt[i2], 1);
        g_slot[i2*SEQ + pos2] = 2*row + 1;
        g_wslot[2*row+1] = w2;
    }
}

// ---------------- bf16 HMMA GEMM: C[M,N] = A @ B^T (+resid) ----------------
// 3-stage cp.async, single barrier per K-chunk. 96KB smem -> 2 CTA/SM.
#define GSTG 16384
template<bool GATHER>
__global__ __launch_bounds__(256) void gemm_bf(
    const bf16* __restrict__ A, const bf16* __restrict__ B,
    const float* __restrict__ resid, float* __restrict__ C,
    int M, int N, int K, int shiftA)
{
    extern __shared__ char smem[];
    const int* sl = nullptr;
    if (GATHER) {
        int e = blockIdx.z;
        M = g_cnt[e];
        if ((int)blockIdx.y * 128 >= M) return;
        sl = g_slot + e * SEQ;
        B += (size_t)e * N * K;
    }
    int m0 = blockIdx.y * 128, n0 = blockIdx.x * 128;
    int tid = threadIdx.x, warp = tid >> 5, lane = tid & 31;
    int wm = (warp >> 2) * 64, wn = (warp & 3) * 32;
    uint32_t sbase = (uint32_t)__cvta_generic_to_shared(smem);
    uint32_t aoff[3], boff[3];
    #pragma unroll
    for (int s = 0; s < 3; s++) {
        aoff[s] = sbase + s*GSTG;
        boff[s] = sbase + 3*GSTG + s*GSTG;
    }

    int lrow = tid >> 1;
    int lsg  = (tid & 1) * 4;
    const bf16* Arow; int szA = 16;
    if (GATHER) {
        int gm = m0 + lrow;
        if (gm < M) Arow = A + (size_t)(sl[gm] >> shiftA) * K;
        else { Arow = A; szA = 0; }
    } else {
        Arow = A + (size_t)(m0 + lrow) * K;
    }
    const bf16* Brow = B + (size_t)(n0 + lrow) * K;
    uint32_t dsw = (uint32_t)lrow * 128u;
    int rxor = lrow & 7;

    float acc[4][4][4];
    #pragma unroll
    for (int i = 0; i < 4; i++)
        #pragma unroll
        for (int j = 0; j < 4; j++)
            #pragma unroll
            for (int q = 0; q < 4; q++) acc[i][j][q] = 0.f;

    int CC = K / 64;
    auto loadChunk = [&](int c) {
        int s = c % 3;
        const char* pa = (const char*)(Arow + c*64);
        const char* pb = (const char*)(Brow + c*64);
        #pragma unroll
        for (int i = 0; i < 4; i++) {
            int seg = lsg + i;
            uint32_t o = dsw + (uint32_t)((seg ^ rxor) * 16);
            cpa(aoff[s] + o, pa + seg*16, szA);
            cpa(boff[s] + o, pb + seg*16, 16);
        }
        asm volatile("cp.async.commit_group;" ::: "memory");
    };
    loadChunk(0);
    if (CC > 1) loadChunk(1);

    int lt = lane >> 3;
    int rl = lane & 7;
    int th = (lt & 1) * 8;
    int ts = lane >> 4;

    for (int c = 0; c < CC; c++) {
        if (c + 1 < CC) asm volatile("cp.async.wait_group 1;" ::: "memory");
        else            asm volatile("cp.async.wait_group 0;" ::: "memory");
        __syncthreads();
        if (c + 2 < CC) loadChunk(c + 2);

        uint32_t Ab = aoff[c % 3], Bb = boff[c % 3];
        #pragma unroll
        for (int kk = 0; kk < 4; kk++) {
            uint32_t af[4][4], bfm[2][4];
            #pragma unroll
            for (int i = 0; i < 4; i++) {
                int row = wm + i*16 + th + rl;
                int seg = 2*kk + ts;
                ldsm4(af[i], Ab + row*128 + ((seg ^ (row & 7)) << 4));
            }
            #pragma unroll
            for (int j = 0; j < 2; j++) {
                int nr = wn + j*16 + th + rl;
                int seg = 2*kk + ts;
                ldsm4(bfm[j], Bb + nr*128 + ((seg ^ (nr & 7)) << 4));
            }
            #pragma unroll
            for (int i = 0; i < 4; i++)
                #pragma unroll
                for (int jn = 0; jn < 4; jn++) {
                    int jj = jn >> 1, hi = jn & 1;
                    mma_bf16(acc[i][jn], af[i][0], af[i][1], af[i][2], af[i][3],
                             bfm[jj][hi], bfm[jj][hi+2]);
                }
        }
    }

    int g = lane >> 2, tg = lane & 3;
    #pragma unroll
    for (int i = 0; i < 4; i++) {
        int r0 = m0 + wm + i*16 + g;
        int r1 = r0 + 8;
        bool v0, v1;
        int row0, row1;
        if (GATHER) {
            v0 = r0 < M; v1 = r1 < M;
            row0 = v0 ? sl[r0] : 0;
            row1 = v1 ? sl[r1] : 0;
        } else {
            v0 = v1 = true; row0 = r0; row1 = r1;
        }
        #pragma unroll
        for (int j = 0; j < 4; j++) {
            int c0 = n0 + wn + j*8 + tg*2;
            if (v0) {
                float2 v; v.x = acc[i][j][0]; v.y = acc[i][j][1];
                if (resid) {
                    v.x += resid[(size_t)row0*N + c0];
                    v.y += resid[(size_t)row0*N + c0 + 1];
                }
                *(float2*)(C + (size_t)row0*N + c0) = v;
            }
            if (v1) {
                float2 v; v.x = acc[i][j][2]; v.y = acc[i][j][3];
                if (resid) {
                    v.x += resid[(size_t)row1*N + c0];
                    v.y += resid[(size_t)row1*N + c0 + 1];
                }
                *(float2*)(C + (size_t)row1*N + c0) = v;
            }
        }
    }
}

// ---------------- QKV GEMM with fused RoPE/split epilogue -------------------
__device__ __forceinline__ void rope_write(
    int t, int c0, float vx, float vy, const float* __restrict__ freqs)
{
    if (c0 < DM) {
        int h = c0 >> 6, d = c0 & 63, p = d >> 1;
        float cs = freqs[((size_t)t*32 + p)*2 + 0];
        float sn = freqs[((size_t)t*32 + p)*2 + 1];
        float2 o;
        o.x = __uint_as_float(f2tf32((vx*cs - vy*sn) * 0.125f));
        o.y = __uint_as_float(f2tf32((vy*cs + vx*sn) * 0.125f));
        *(float2*)(g_q + ((size_t)h*SEQ + t)*HDIM + d) = o;
    } else if (c0 < DM + NKV*HDIM) {
        int c = c0 - DM;
        int kh = c >> 6, d = c & 63, p = d >> 1;
        float cs = freqs[((size_t)t*32 + p)*2 + 0];
        float sn = freqs[((size_t)t*32 + p)*2 + 1];
        float2 o;
        o.x = __uint_as_float(f2tf32(vx*cs - vy*sn));
        o.y = __uint_as_float(f2tf32(vy*cs + vx*sn));
        *(float2*)(g_k + ((size_t)kh*SEQ + t)*HDIM + d) = o;
    } else {
        int c = c0 - DM - NKV*HDIM;
        int vh = c >> 6, d = c & 63;
        g_vt[((size_t)(vh*HDIM + d  ))*SEQ + t] = __float2bfloat16(vx);
        g_vt[((size_t)(vh*HDIM + d+1))*SEQ + t] = __float2bfloat16(vy);
    }
}

__global__ __launch_bounds__(256) void gemm_qkv(
    const bf16* __restrict__ A, const bf16* __restrict__ B,
    const float* __restrict__ freqs)
{
    extern __shared__ char smem[];
    const int K = DM;
    int m0 = blockIdx.y * 128, n0 = blockIdx.x * 128;
    int tid = threadIdx.x, warp = tid >> 5, lane = tid & 31;
    int wm = (warp >> 2) * 64, wn = (warp & 3) * 32;
    uint32_t sbase = (uint32_t)__cvta_generic_to_shared(smem);
    uint32_t aoff[3], boff[3];
    #pragma unroll
    for (int s = 0; s < 3; s++) {
        aoff[s] = sbase + s*GSTG;
        boff[s] = sbase + 3*GSTG + s*GSTG;
    }

    int lrow = tid >> 1;
    int lsg  = (tid & 1) * 4;
    const bf16* Arow = A + (size_t)(m0 + lrow) * K;
    const bf16* Brow = B + (size_t)(n0 + lrow) * K;
    uint32_t dsw = (uint32_t)lrow * 128u;
    int rxor = lrow & 7;

    float acc[4][4][4];
    #pragma unroll
    for (int i = 0; i < 4; i++)
        #pragma unroll
        for (int j = 0; j < 4; j++)
            #pragma unroll
            for (int q = 0; q < 4; q++) acc[i][j][q] = 0.f;

    const int CC = K / 64;
    auto loadChunk = [&](int c) {
        int s = c % 3;
        const char* pa = (const char*)(Arow + c*64);
        const char* pb = (const char*)(Brow + c*64);
        #pragma unroll
        for (int i = 0; i < 4; i++) {
            int seg = lsg + i;
            uint32_t o = dsw + (uint32_t)((seg ^ rxor) * 16);
            cpa(aoff[s] + o, pa + seg*16, 16);
            cpa(boff[s] + o, pb + seg*16, 16);
        }
        asm volatile("cp.async.commit_group;" ::: "memory");
    };
    loadChunk(0);
    loadChunk(1);

    int lt = lane >> 3;
    int rl = lane & 7;
    int th = (lt & 1) * 8;
    int ts = lane >> 4;

    for (int c = 0; c < CC; c++) {
        if (c + 1 < CC) asm volatile("cp.async.wait_group 1;" ::: "memory");
        else            asm volatile("cp.async.wait_group 0;" ::: "memory");
        __syncthreads();
        if (c + 2 < CC) loadChunk(c + 2);

        uint32_t Ab = aoff[c % 3], Bb = boff[c % 3];
        #pragma unroll
        for (int kk = 0; kk < 4; kk++) {
            uint32_t af[4][4], bfm[2][4];
            #pragma unroll
            for (int i = 0; i < 4; i++) {
                int row = wm + i*16 + th + rl;
                int seg = 2*kk + ts;
                ldsm4(af[i], Ab + row*128 + ((seg ^ (row & 7)) << 4));
            }
            #pragma unroll
            for (int j = 0; j < 2; j++) {
                int nr = wn + j*16 + th + rl;
                int seg = 2*kk + ts;
                ldsm4(bfm[j], Bb + nr*128 + ((seg ^ (nr & 7)) << 4));
            }
            #pragma unroll
            for (int i = 0; i < 4; i++)
                #pragma unroll
                for (int jn = 0; jn < 4; jn++) {
                    int jj = jn >> 1, hi = jn & 1;
                    mma_bf16(acc[i][jn], af[i][0], af[i][1], af[i][2], af[i][3],
                             bfm[jj][hi], bfm[jj][hi+2]);
                }
        }
    }

    int g = lane >> 2, tg = lane & 3;
    #pragma unroll
    for (int i = 0; i < 4; i++) {
        int t0 = m0 + wm + i*16 + g;
        int t1 = t0 + 8;
        #pragma unroll
        for (int j = 0; j < 4; j++) {
            int c0 = n0 + wn + j*8 + tg*2;
            rope_write(t0, c0, acc[i][j][0], acc[i][j][1], freqs);
            rope_write(t1, c0, acc[i][j][2], acc[i][j][3], freqs);
        }
    }
}

// ---------------- fused MoE w1/w3 GEMM + silu*mul (bf16 out) ---------------
// 2-stage double buffer (96KB smem -> 2 CTA/SM).
__global__ __launch_bounds__(256) void gemm_w13(
    const bf16* __restrict__ A, const bf16* __restrict__ B1,
    const bf16* __restrict__ B3)
{
    extern __shared__ char smem[];
    int e = blockIdx.z;
    int M = g_cnt[e];
    if ((int)blockIdx.y * 128 >= M) return;
    const int* sl = g_slot + e * SEQ;
    B1 += (size_t)e * NI * DM;
    B3 += (size_t)e * NI * DM;

    int m0 = blockIdx.y * 128, n0 = blockIdx.x * 128;
    int tid = threadIdx.x, warp = tid >> 5, lane = tid & 31;
    int wm = (warp >> 2) * 64, wn = (warp & 3) * 32;
    uint32_t sbase = (uint32_t)__cvta_generic_to_shared(smem);
    uint32_t aoff[2], b1off[2], b3off[2];
    #pragma unroll
    for (int s = 0; s < 2; s++) {
        aoff[s]  = sbase + s*GSTG;
        b1off[s] = sbase + 2*GSTG + s*GSTG;
        b3off[s] = sbase + 4*GSTG + s*GSTG;
    }

    int lrow = tid >> 1;
    int lsg  = (tid & 1) * 4;
    const bf16* Arow; int szA = 16;
    {
        int gm = m0 + lrow;
        if (gm < M) Arow = A + (size_t)(sl[gm] >> 1) * DM;
        else { Arow = A; szA = 0; }
    }
    const bf16* B1row = B1 + (size_t)(n0 + lrow) * DM;
    const bf16* B3row = B3 + (size_t)(n0 + lrow) * DM;
    uint32_t dsw = (uint32_t)lrow * 128u;
    int rxor = lrow & 7;

    float ac1[4][4][4], ac3[4][4][4];
    #pragma unroll
    for (int i = 0; i < 4; i++)
        #pragma unroll
        for (int j = 0; j < 4; j++)
            #pragma unroll
            for (int q = 0; q < 4; q++) { ac1[i][j][q] = 0.f; ac3[i][j][q] = 0.f; }

    const int CC = DM / 64;
    auto loadChunk = [&](int c) {
        int s = c & 1;
        const char* pa  = (const char*)(Arow  + c*64);
        const char* pb1 = (const char*)(B1row + c*64);
        const char* pb3 = (const char*)(B3row + c*64);
        #pragma unroll
        for (int i = 0; i < 4; i++) {
            int seg = lsg + i;
            uint32_t o = dsw + (uint32_t)((seg ^ rxor) * 16);
            cpa(aoff[s]  + o, pa  + seg*16, szA);
            cpa(b1off[s] + o, pb1 + seg*16, 16);
            cpa(b3off[s] + o, pb3 + seg*16, 16);
        }
        asm volatile("cp.async.commit_group;" ::: "memory");
    };
    loadChunk(0);

    int lt = lane >> 3, rl = lane & 7;
    int th = (lt & 1) * 8;
    int ts = lane >> 4;

    for (int c = 0; c < CC; c++) {
        asm volatile("cp.async.wait_group 0;" ::: "memory");
        __syncthreads();
        if (c + 1 < CC) loadChunk(c + 1);

        uint32_t Ab = aoff[c & 1], B1b = b1off[c & 1], B3b = b3off[c & 1];
        #pragma unroll
        for (int kk = 0; kk < 4; kk++) {
            uint32_t af[4][4], f1[2][4], f3[2][4];
            #pragma unroll
            for (int i = 0; i < 4; i++) {
                int row = wm + i*16 + th + rl;
                int seg = 2*kk + ts;
                ldsm4(af[i], Ab + row*128 + ((seg ^ (row & 7)) << 4));
            }
            #pragma unroll
            for (int j = 0; j < 2; j++) {
                int nr = wn + j*16 + th + rl;
                int seg = 2*kk + ts;
                ldsm4(f1[j], B1b + nr*128 + ((seg ^ (nr & 7)) << 4));
                ldsm4(f3[j], B3b + nr*128 + ((seg ^ (nr & 7)) << 4));
            }
            #pragma unroll
            for (int i = 0; i < 4; i++)
                #pragma unroll
                for (int jn = 0; jn < 4; jn++) {
                    int jj = jn >> 1, hi = jn & 1;
                    mma_bf16(ac1[i][jn], af[i][0], af[i][1], af[i][2], af[i][3],
                             f1[jj][hi], f1[jj][hi+2]);
                    mma_bf16(ac3[i][jn], af[i][0], af[i][1], af[i][2], af[i][3],
                             f3[jj][hi], f3[jj][hi+2]);
                }
        }
    }

    int g = lane >> 2, tg = lane & 3;
    #pragma unroll
    for (int i = 0; i < 4; i++) {
        int r0 = m0 + wm + i*16 + g;
        int r1 = r0 + 8;
        bool v0 = r0 < M, v1 = r1 < M;
        int row0 = v0 ? sl[r0] : 0;
        int row1 = v1 ? sl[r1] : 0;
        #pragma unroll
        for (int j = 0; j < 4; j++) {
            int c0 = n0 + wn + j*8 + tg*2;
            if (v0) {
                float a0 = ac1[i][j][0], a1 = ac1[i][j][1];
                float u0 = a0 / (1.f + __expf(-a0)) * ac3[i][j][0];
                float u1 = a1 / (1.f + __expf(-a1)) * ac3[i][j][1];
                *(__nv_bfloat162*)(g_gb + (size_t)row0*NI + c0) = __floats2bfloat162_rn(u0, u1);
            }
            if (v1) {
                float a0 = ac1[i][j][2], a1 = ac1[i][j][3];
                float u0 = a0 / (1.f + __expf(-a0)) * ac3[i][j][2];
                float u1 = a1 / (1.f + __expf(-a1)) * ac3[i][j][3];
                *(__nv_bfloat162*)(g_gb + (size_t)row1*NI + c0) = __floats2bfloat162_rn(u0, u1);
            }
        }
    }
}

// ---------------- attention v6: uniform-chunk split flash -------------------
#define ASTR 68
#define VSTR 72
__global__ __launch_bounds__(128) void attn6_kernel()
{
    __shared__ float Ks[64*ASTR];
    __shared__ bf16  Vt[64*VSTR];

    int qt = blockIdx.x, h = blockIdx.y, z = blockIdx.z;
    int kvh = h >> 2;
    int tid = threadIdx.x, warp = tid >> 5, lane = tid & 31;
    int g = lane >> 2, tg = lane & 3;
    int wq = warp * 16;
    int q0 = qt * 64;

    int n = qt + 1;
    int lo = z * CHUNK;
    int hi = min(n, lo + CHUNK);

    float oc[8][4];
    #pragma unroll
    for (int j = 0; j < 8; j++)
        #pragma unroll
        for (int q = 0; q < 4; q++) oc[j][q] = 0.f;
    float mrow[2] = {-1e30f, -1e30f};
    float lrow[2] = {0.f, 0.f};

    if (lo < hi) {
        for (int i = tid; i < 64*16; i += 128) {
            int row = i >> 4, c4 = (i & 15) * 4;
            *(float4*)&Ks[row*ASTR + c4] =
                *(const float4*)(g_q + ((size_t)h*SEQ + q0 + row)*HDIM + c4);
        }
        __syncthreads();
        uint32_t aq[8][4];
        #pragma unroll
        for (int kk = 0; kk < 8; kk++) {
            aq[kk][0] = __float_as_uint(Ks[(wq+g)*ASTR + kk*8 + tg]);
            aq[kk][1] = __float_as_uint(Ks[(wq+g+8)*ASTR + kk*8 + tg]);
            aq[kk][2] = __float_as_uint(Ks[(wq+g)*ASTR + kk*8 + tg + 4]);
            aq[kk][3] = __float_as_uint(Ks[(wq+g+8)*ASTR + kk*8 + tg + 4]);
        }
        __syncthreads();

        for (int kt = lo; kt < hi; kt++) {
            for (int i = tid; i < 1024; i += 128) {
                int row = i >> 4, c4 = (i & 15) * 4;
                *(float4*)&Ks[row*ASTR + c4] =
                    *(const float4*)(g_k + ((size_t)kvh*SEQ + kt*64 + row)*HDIM + c4);
            }
            for (int i = tid; i < 512; i += 128) {
                int row = i >> 3, seg = i & 7;
                *(uint4*)&Vt[row*VSTR + seg*8] =
                    *(const uint4*)(g_vt + ((size_t)(kvh*HDIM + row))*SEQ + kt*64 + seg*8);
            }
            __syncthreads();

            float sc[8][4];
            #pragma unroll
            for (int j = 0; j < 8; j++)
                #pragma unroll
                for (int q = 0; q < 4; q++) sc[j][q] = 0.f;
            #pragma unroll
            for (int kk = 0; kk < 8; kk++) {
                #pragma unroll
                for (int j = 0; j < 8; j++) {
                    uint32_t b0 = __float_as_uint(Ks[(j*8+g)*ASTR + kk*8 + tg]);
                    uint32_t b1 = __float_as_uint(Ks[(j*8+g)*ASTR + kk*8 + tg + 4]);
                    mma_tf32(sc[j], aq[kk][0], aq[kk][1], aq[kk][2], aq[kk][3], b0, b1);
                }
            }

            if (kt == qt) {
                int r0g = q0 + wq + g, r1g = r0g + 8;
                #pragma unroll
                for (int j = 0; j < 8; j++) {
                    int c0 = kt*64 + j*8 + tg*2;
                    if (c0     > r0g) sc[j][0] = -1e30f;
                    if (c0 + 1 > r0g) sc[j][1] = -1e30f;
                    if (c0     > r1g) sc[j][2] = -1e30f;
                    if (c0 + 1 > r1g) sc[j][3] = -1e30f;
                }
            }

            float mx0 = -1e30f, mx1 = -1e30f;
            #pragma unroll
            for (int j = 0; j < 8; j++) {
                mx0 = fmaxf(mx0, fmaxf(sc[j][0], sc[j][1]));
                mx1 = fmaxf(mx1, fmaxf(sc[j][2], sc[j][3]));
            }
            mx0 = fmaxf(mx0, __shfl_xor_sync(0xffffffffu, mx0, 1));
            mx0 = fmaxf(mx0, __shfl_xor_sync(0xffffffffu, mx0, 2));
            mx1 = fmaxf(mx1, __shfl_xor_sync(0xffffffffu, mx1, 1));
            mx1 = fmaxf(mx1, __shfl_xor_sync(0xffffffffu, mx1, 2));
            float mn0 = fmaxf(mrow[0], mx0), mn1 = fmaxf(mrow[1], mx1);
            float s0 = __expf(mrow[0] - mn0), s1 = __expf(mrow[1] - mn1);
            float ls0 = 0.f, ls1 = 0.f;
            #pragma unroll
            for (int j = 0; j < 8; j++) {
                sc[j][0] = __expf(sc[j][0] - mn0);
                sc[j][1] = __expf(sc[j][1] - mn0);
                sc[j][2] = __expf(sc[j][2] - mn1);
                sc[j][3] = __expf(sc[j][3] - mn1);
                ls0 += sc[j][0] + sc[j][1];
                ls1 += sc[j][2] + sc[j][3];
            }
            ls0 += __shfl_xor_sync(0xffffffffu, ls0, 1);
            ls0 += __shfl_xor_sync(0xffffffffu, ls0, 2);
            ls1 += __shfl_xor_sync(0xffffffffu, ls1, 1);
            ls1 += __shfl_xor_sync(0xffffffffu, ls1, 2);
            lrow[0] = lrow[0]*s0 + ls0;
            lrow[1] = lrow[1]*s1 + ls1;
            mrow[0] = mn0; mrow[1] = mn1;
            #pragma unroll
            for (int j = 0; j < 8; j++) {
                oc[j][0] *= s0; oc[j][1] *= s0;
                oc[j][2] *= s1; oc[j][3] *= s1;
            }

            uint32_t pa[4][4];
            #pragma unroll
            for (int kk = 0; kk < 4; kk++) {
                pa[kk][0] = packbf(sc[2*kk][0],   sc[2*kk][1]);
                pa[kk][1] = packbf(sc[2*kk][2],   sc[2*kk][3]);
                pa[kk][2] = packbf(sc[2*kk+1][0], sc[2*kk+1][1]);
                pa[kk][3] = packbf(sc[2*kk+1][2], sc[2*kk+1][3]);
            }
            #pragma unroll
            for (int kk = 0; kk < 4; kk++) {
                #pragma unroll
                for (int j = 0; j < 8; j++) {
                    uint32_t b0 = *(const uint32_t*)&Vt[(j*8+g)*VSTR + kk*16 + tg*2];
                    uint32_t b1 = *(const uint32_t*)&Vt[(j*8+g)*VSTR + kk*16 + tg*2 + 8];
                    mma_bf16(oc[j], pa[kk][0], pa[kk][1], pa[kk][2], pa[kk][3], b0, b1);
                }
            }
            __syncthreads();
        }
    }

    size_t pb = (size_t)z * NH * SEQ;
    int r0 = q0 + wq + g, r1 = r0 + 8;
    size_t hr0 = (size_t)h*SEQ + r0, hr1 = (size_t)h*SEQ + r1;
    #pragma unroll
    for (int j = 0; j < 8; j++) {
        int c0 = j*8 + tg*2;
        float2 v0; v0.x = oc[j][0]; v0.y = oc[j][1];
        float2 v1; v1.x = oc[j][2]; v1.y = oc[j][3];
        *(float2*)&g_po[(pb + hr0)*HDIM + c0] = v0;
        *(float2*)&g_po[(pb + hr1)*HDIM + c0] = v1;
    }
    if (tg == 0) {
        g_pm[pb + hr0] = mrow[0];
        g_pm[pb + hr1] = mrow[1];
        g_pl[pb + hr0] = lrow[0];
        g_pl[pb + hr1] = lrow[1];
    }
}

// ---------------- split reduce: merge NSPLIT partials -> y_bf ---------------
__global__ void attn_reduce_kernel()
{
    int i = blockIdx.x * blockDim.x + threadIdx.x;
    if (i >= NH*SEQ*(HDIM/2)) return;
    int hrow = i >> 5;
    int c2 = (i & 31) * 2;
    int h = hrow / SEQ, row = hrow % SEQ;
    float M = -1e30f;
    float ms[NSPLIT], ls[NSPLIT];
    #pragma unroll
    for (int s = 0; s < NSPLIT; s++) {
        ms[s] = g_pm[s*NH*SEQ + hrow];
        ls[s] = g_pl[s*NH*SEQ + hrow];
        M = fmaxf(M, ms[s]);
    }
    float den = 0.f, vx = 0.f, vy = 0.f;
    #pragma unroll
    for (int s = 0; s < NSPLIT; s++) {
        float w = __expf(ms[s] - M);
        den += ls[s] * w;
        float2 o = *(const float2*)&g_po[((size_t)s*NH*SEQ + hrow)*HDIM + c2];
        vx += o.x * w;
        vy += o.y * w;
    }
    float inv = 1.f / den;
    *(__nv_bfloat162*)(g_y_bf + (size_t)row*DM + h*HDIM + c2) =
        __floats2bfloat162_rn(vx*inv, vy*inv);
}

// ---------------- final combine ---------------------------------------------
__global__ __launch_bounds__(256) void combine_kernel(float* __restrict__ out)
{
    int t = blockIdx.x;
    int tid = threadIdx.x;
    float w0 = g_wslot[2*t], w1 = g_wslot[2*t+1];
    float4 hv = ((const float4*)(g_h + (size_t)t*DM))[tid];
    float4 a = ((const float4*)(g_os + (size_t)(2*t)*DM))[tid];
    float4 b = ((const float4*)(g_os + (size_t)(2*t+1)*DM))[tid];
    float4 o;
    o.x = hv.x + w0*a.x + w1*b.x;
    o.y = hv.y + w0*a.y + w1*b.y;
    o.z = hv.z + w0*a.z + w1*b.z;
    o.w = hv.w + w0*a.w + w1*b.w;
    ((float4*)(out + (size_t)t*DM))[tid] = o;
}

// ---------------- host launch ----------------------------------------------
#define GEMM_SMEM (6*GSTG)
#define W13_SMEM  (6*GSTG)

extern "C" void kernel_launch(void* const* d_in, const int* in_sizes, int n_in,
                              void* d_out, int out_size)
{
    const float* x      = (const float*)d_in[0];
    const float* wqkv   = (const float*)d_in[1];
    const float* wo     = (const float*)d_in[2];
    const float* gate_w = (const float*)d_in[3];
    const float* w1     = (const float*)d_in[4];
    const float* w2     = (const float*)d_in[5];
    const float* w3     = (const float*)d_in[6];
    const float* anw    = (const float*)d_in[7];
    const float* fnw    = (const float*)d_in[8];
    const float* freqs  = (const float*)d_in[9];
    float* out = (float*)d_out;

    bf16 *p_wqkv_bf, *p_wo_bf, *p_w1_bf, *p_w3_bf, *p_w2_bf;
    bf16 *p_hn_bf, *p_hf_bf, *p_y_bf, *p_gb;
    float *p_h, *p_os;
    int *p_cnt;
    cudaGetSymbolAddress((void**)&p_wqkv_bf, g_wqkv_bf);
    cudaGetSymbolAddress((void**)&p_wo_bf,   g_wo_bf);
    cudaGetSymbolAddress((void**)&p_w1_bf,   g_w1_bf);
    cudaGetSymbolAddress((void**)&p_w3_bf,   g_w3_bf);
    cudaGetSymbolAddress((void**)&p_w2_bf,   g_w2_bf);
    cudaGetSymbolAddress((void**)&p_hn_bf,   g_hn_bf);
    cudaGetSymbolAddress((void**)&p_hf_bf,   g_hf_bf);
    cudaGetSymbolAddress((void**)&p_y_bf,    g_y_bf);
    cudaGetSymbolAddress((void**)&p_gb,      g_gb);
    cudaGetSymbolAddress((void**)&p_h,       g_h);
    cudaGetSymbolAddress((void**)&p_os,      g_os);
    cudaGetSymbolAddress((void**)&p_cnt,     g_cnt);

    static cudaStream_t s2 = nullptr;
    static cudaEvent_t ev0 = nullptr, ev1 = nullptr;
    static bool attr_set = false;
    if (!attr_set) {
        cudaFuncSetAttribute(gemm_bf<false>,
            cudaFuncAttributeMaxDynamicSharedMemorySize, GEMM_SMEM);
        cudaFuncSetAttribute(gemm_bf<true>,
            cudaFuncAttributeMaxDynamicSharedMemorySize, GEMM_SMEM);
        cudaFuncSetAttribute(gemm_qkv,
            cudaFuncAttributeMaxDynamicSharedMemorySize, GEMM_SMEM);
        cudaFuncSetAttribute(gemm_w13,
            cudaFuncAttributeMaxDynamicSharedMemorySize, W13_SMEM);
        cudaStreamCreateWithFlags(&s2, cudaStreamNonBlocking);
        cudaEventCreateWithFlags(&ev0, cudaEventDisableTiming);
        cudaEventCreateWithFlags(&ev1, cudaEventDisableTiming);
        attr_set = true;
    }

    // (1) wqkv convert (main)
    {
        int n4 = QKVN*DM/4;
        f2bf_kernel<<<(n4+255)/256, 256>>>((const float4*)wqkv, (uint2*)p_wqkv_bf, n4);
    }
    // (2,3) fork first two big MoE converts on side stream
    cudaEventRecord(ev0, 0);
    cudaStreamWaitEvent(s2, ev0, 0);
    {
        int n4 = (int)((size_t)NE*NI*DM/4);
        f2bf_kernel<<<(n4+255)/256, 256, 0, s2>>>((const float4*)w1, (uint2*)p_w1_bf, n4);
        f2bf_kernel<<<(n4+255)/256, 256, 0, s2>>>((const float4*)w3, (uint2*)p_w3_bf, n4);
    }
    // (4) attn rmsnorm
    rmsnorm_kernel<<<SEQ, 256>>>(x, anw, p_hn_bf);
    // (5) qkv GEMM + fused RoPE
    gemm_qkv<<<dim3(QKVN/128, SEQ/128), 256, GEMM_SMEM>>>(p_hn_bf, p_wqkv_bf, freqs);
    // (6) attention v6
    attn6_kernel<<<dim3(SEQ/64, NH, NSPLIT), 128>>>();
    // (7+) rest
    {
        int n4 = (int)((size_t)NE*NI*DM/4);
        f2bf_kernel<<<(n4+255)/256, 256, 0, s2>>>((const float4*)w2, (uint2*)p_w2_bf, n4);
    }
    cudaEventRecord(ev1, s2);
    {
        int n4 = DM*DM/4;
        f2bf_kernel<<<(n4+255)/256, 256>>>((const float4*)wo, (uint2*)p_wo_bf, n4);
    }
    attn_reduce_kernel<<<(NH*SEQ*(HDIM/2) + 255)/256, 256>>>();
    gemm_bf<false><<<dim3(DM/128, SEQ/128), 256, GEMM_SMEM>>>(
        p_y_bf, p_wo_bf, x, p_h, SEQ, DM, DM, 0);
    // fused ffn rmsnorm + gating (cnt cleared first)
    cudaMemsetAsync(p_cnt, 0, NE*sizeof(int), 0);
    rmsnorm_gate_kernel<<<SEQ, 256>>>(p_h, fnw, gate_w, p_hf_bf);

    cudaStreamWaitEvent(0, ev1, 0);
    gemm_w13<<<dim3(NI/128, SEQ/128, NE), 256, W13_SMEM>>>(
        p_hf_bf, p_w1_bf, p_w3_bf);
    gemm_bf<true><<<dim3(DM/128, SEQ/128, NE), 256, GEMM_SMEM>>>(
        p_gb, p_w2_bf, nullptr, p_os, 0, DM, NI, 0);
    combine_kernel<<<SEQ, 256>>>(out);
}

// round 15
// speedup vs baseline: 1.2416x; 1.0210x over previous
#include <cuda_runtime.h>
#include <cuda_bf16.h>
#include <math.h>
#include <stdint.h>

#define SEQ 2048
#define DM 1024
#define NH 16
#define NKV 4
#define HDIM 64
#define NE 8
#define NI 3584
#define QKVN 1536
#define NSLOTS (2*SEQ)
#define NSPLIT 8
#define CHUNK 4

typedef __nv_bfloat16 bf16;

// ---------------- scratch (device globals; no allocations) ----------------
__device__ bf16  g_wqkv_bf[QKVN*DM];
__device__ bf16  g_wo_bf[DM*DM];
__device__ bf16  g_w1_bf[(size_t)NE*NI*DM];
__device__ bf16  g_w3_bf[(size_t)NE*NI*DM];
__device__ bf16  g_w2_bf[(size_t)NE*DM*NI];
__device__ bf16  g_hn_bf[SEQ*DM];
__device__ float g_q[NH*SEQ*HDIM];      // tf32-rounded, pre-scaled 0.125
__device__ float g_k[NKV*SEQ*HDIM];     // tf32-rounded
__device__ bf16  g_vt[NKV*HDIM*SEQ];    // bf16, transposed [kvh][d][t]
__device__ float g_po[(size_t)NSPLIT*NH*SEQ*HDIM];
__device__ float g_pm[NSPLIT*NH*SEQ];
__device__ float g_pl[NSPLIT*NH*SEQ];
__device__ bf16  g_y_bf[SEQ*DM];
__device__ float g_h[SEQ*DM];
__device__ bf16  g_hf_bf[SEQ*DM];
__device__ int   g_cnt[NE];
__device__ int   g_slot[NE*SEQ];
__device__ float g_wslot[NSLOTS];
__device__ bf16  g_gb[(size_t)NSLOTS*NI];
__device__ float g_os[(size_t)NSLOTS*DM];

// ---------------- helpers ---------------------------------------------------
__device__ __forceinline__ uint32_t f2tf32(float f) {
    uint32_t r;
    asm("cvt.rna.tf32.f32 %0, %1;" : "=r"(r) : "f"(f));
    return r;
}
__device__ __forceinline__ void mma_tf32(float c[4],
    uint32_t a0, uint32_t a1, uint32_t a2, uint32_t a3,
    uint32_t b0, uint32_t b1)
{
    asm volatile(
        "mma.sync.aligned.m16n8k8.row.col.f32.tf32.tf32.f32 "
        "{%0,%1,%2,%3}, {%4,%5,%6,%7}, {%8,%9}, {%0,%1,%2,%3};"
        : "+f"(c[0]), "+f"(c[1]), "+f"(c[2]), "+f"(c[3])
        : "r"(a0), "r"(a1), "r"(a2), "r"(a3), "r"(b0), "r"(b1));
}
__device__ __forceinline__ void mma_bf16(float c[4],
    uint32_t a0, uint32_t a1, uint32_t a2, uint32_t a3,
    uint32_t b0, uint32_t b1)
{
    asm volatile(
        "mma.sync.aligned.m16n8k16.row.col.f32.bf16.bf16.f32 "
        "{%0,%1,%2,%3}, {%4,%5,%6,%7}, {%8,%9}, {%0,%1,%2,%3};"
        : "+f"(c[0]), "+f"(c[1]), "+f"(c[2]), "+f"(c[3])
        : "r"(a0), "r"(a1), "r"(a2), "r"(a3), "r"(b0), "r"(b1));
}
__device__ __forceinline__ void ldsm4(uint32_t r[4], uint32_t addr) {
    asm volatile("ldmatrix.sync.aligned.m8n8.x4.shared.b16 {%0,%1,%2,%3}, [%4];"
                 : "=r"(r[0]), "=r"(r[1]), "=r"(r[2]), "=r"(r[3]) : "r"(addr));
}
__device__ __forceinline__ void cpa(uint32_t dst, const void* src, int sz) {
    asm volatile("cp.async.cg.shared.global [%0], [%1], 16, %2;"
                 :: "r"(dst), "l"(src), "r"(sz));
}
__device__ __forceinline__ uint32_t packbf(float a, float b) {
    __nv_bfloat162 p = __floats2bfloat162_rn(a, b);
    return *(uint32_t*)&p;
}

// ---------------- fp32 -> bf16 convert --------------------------------------
__global__ void f2bf_kernel(const float4* __restrict__ s, uint2* __restrict__ d, int n4)
{
    int i = blockIdx.x * blockDim.x + threadIdx.x;
    if (i >= n4) return;
    float4 v = s[i];
    __nv_bfloat162 lo = __floats2bfloat162_rn(v.x, v.y);
    __nv_bfloat162 hi = __floats2bfloat162_rn(v.z, v.w);
    uint2 o;
    o.x = *(uint32_t*)&lo;
    o.y = *(uint32_t*)&hi;
    d[i] = o;
}

// ---------------- rmsnorm (bf16 out) ----------------------------------------
__global__ __launch_bounds__(256) void rmsnorm_kernel(
    const float* __restrict__ x, const float* __restrict__ w,
    bf16* __restrict__ obf)
{
    int row = blockIdx.x;
    int tid = threadIdx.x;
    const float4* xr = (const float4*)(x + (size_t)row*DM);
    float4 v = xr[tid];
    float ss = v.x*v.x + v.y*v.y + v.z*v.z + v.w*v.w;
    __shared__ float red[8];
    #pragma unroll
    for (int ofs = 16; ofs > 0; ofs >>= 1) ss += __shfl_down_sync(0xffffffffu, ss, ofs);
    if ((tid & 31) == 0) red[tid >> 5] = ss;
    __syncthreads();
    __shared__ float sr;
    if (tid == 0) {
        float t = 0.f;
        #pragma unroll
        for (int i = 0; i < 8; i++) t += red[i];
        sr = rsqrtf(t / (float)DM + 1e-5f);
    }
    __syncthreads();
    float r = sr;
    float4 wv = ((const float4*)w)[tid];
    float4 o;
    o.x = v.x*r*wv.x; o.y = v.y*r*wv.y; o.z = v.z*r*wv.z; o.w = v.w*r*wv.w;
    __nv_bfloat162 lo = __floats2bfloat162_rn(o.x, o.y);
    __nv_bfloat162 hi = __floats2bfloat162_rn(o.z, o.w);
    uint2 ob; ob.x = *(uint32_t*)&lo; ob.y = *(uint32_t*)&hi;
    *(uint2*)(obf + (size_t)row*DM + tid*4) = ob;
}

// ---------------- fused ffn rmsnorm + gating --------------------------------
__global__ __launch_bounds__(256) void rmsnorm_gate_kernel(
    const float* __restrict__ x, const float* __restrict__ w,
    const float* __restrict__ gw, bf16* __restrict__ obf)
{
    int row = blockIdx.x;
    int tid = threadIdx.x;
    const float4* xr = (const float4*)(x + (size_t)row*DM);
    float4 v = xr[tid];
    float ss = v.x*v.x + v.y*v.y + v.z*v.z + v.w*v.w;
    __shared__ float red[8];
    #pragma unroll
    for (int ofs = 16; ofs > 0; ofs >>= 1) ss += __shfl_down_sync(0xffffffffu, ss, ofs);
    if ((tid & 31) == 0) red[tid >> 5] = ss;
    __syncthreads();
    __shared__ float sr;
    if (tid == 0) {
        float t = 0.f;
        #pragma unroll
        for (int i = 0; i < 8; i++) t += red[i];
        sr = rsqrtf(t / (float)DM + 1e-5f);
    }
    __syncthreads();
    float r = sr;
    float4 wv = ((const float4*)w)[tid];
    float4 o;
    o.x = v.x*r*wv.x; o.y = v.y*r*wv.y; o.z = v.z*r*wv.z; o.w = v.w*r*wv.w;
    __nv_bfloat162 lo = __floats2bfloat162_rn(o.x, o.y);
    __nv_bfloat162 hi = __floats2bfloat162_rn(o.z, o.w);
    uint2 ob; ob.x = *(uint32_t*)&lo; ob.y = *(uint32_t*)&hi;
    *(uint2*)(obf + (size_t)row*DM + tid*4) = ob;

    float d[NE];
    #pragma unroll
    for (int e = 0; e < NE; e++) {
        float4 gv = ((const float4*)(gw + (size_t)e*DM))[tid];
        d[e] = o.x*gv.x + o.y*gv.y + o.z*gv.z + o.w*gv.w;
    }
    #pragma unroll
    for (int e = 0; e < NE; e++) {
        #pragma unroll
        for (int ofs = 16; ofs > 0; ofs >>= 1)
            d[e] += __shfl_down_sync(0xffffffffu, d[e], ofs);
    }
    __shared__ float red2[8][NE];
    if ((tid & 31) == 0) {
        #pragma unroll
        for (int e = 0; e < NE; e++) red2[tid >> 5][e] = d[e];
    }
    __syncthreads();
    if (tid == 0) {
        float lg[NE];
        #pragma unroll
        for (int e = 0; e < NE; e++) {
            float t = 0.f;
            #pragma unroll
            for (int wpi = 0; wpi < 8; wpi++) t += red2[wpi][e];
            lg[e] = t;
        }
        float mx = lg[0];
        #pragma unroll
        for (int i = 1; i < NE; i++) mx = fmaxf(mx, lg[i]);
        float p[NE]; float den = 0.f;
        #pragma unroll
        for (int i = 0; i < NE; i++) { p[i] = expf(lg[i]-mx); den += p[i]; }
        #pragma unroll
        for (int i = 0; i < NE; i++) p[i] /= den;
        int i1 = 0;
        #pragma unroll
        for (int i = 1; i < NE; i++) if (p[i] > p[i1]) i1 = i;
        int i2 = (i1 == 0) ? 1 : 0;
        #pragma unroll
        for (int i = 0; i < NE; i++) if (i != i1 && p[i] > p[i2]) i2 = i;
        float w1 = p[i1], w2 = p[i2];
        float sw2 = w1 + w2;
        w1 /= sw2; w2 /= sw2;
        int pos1 = atomicAdd(&g_cnt[i1], 1);
        g_slot[i1*SEQ + pos1] = 2*row;
        g_wslot[2*row] = w1;
        int pos2 = atomicAdd(&g_cnt[i2], 1);
        g_slot[i2*SEQ + pos2] = 2*row + 1;
        g_wslot[2*row+1] = w2;
    }
}

// ---------------- bf16 HMMA GEMM: C[M,N] = A @ B^T (+resid) ----------------
#define GSTG 16384
template<bool GATHER>
__global__ __launch_bounds__(256) void gemm_bf(
    const bf16* __restrict__ A, const bf16* __restrict__ B,
    const float* __restrict__ resid, float* __restrict__ C,
    int M, int N, int K, int shiftA)
{
    extern __shared__ char smem[];
    const int* sl = nullptr;
    if (GATHER) {
        int e = blockIdx.z;
        M = g_cnt[e];
        if ((int)blockIdx.y * 128 >= M) return;
        sl = g_slot + e * SEQ;
        B += (size_t)e * N * K;
    }
    int m0 = blockIdx.y * 128, n0 = blockIdx.x * 128;
    int tid = threadIdx.x, warp = tid >> 5, lane = tid & 31;
    int wm = (warp >> 2) * 64, wn = (warp & 3) * 32;
    uint32_t sbase = (uint32_t)__cvta_generic_to_shared(smem);
    uint32_t aoff[3], boff[3];
    #pragma unroll
    for (int s = 0; s < 3; s++) {
        aoff[s] = sbase + s*GSTG;
        boff[s] = sbase + 3*GSTG + s*GSTG;
    }

    int lrow = tid >> 1;
    int lsg  = (tid & 1) * 4;
    const bf16* Arow; int szA = 16;
    if (GATHER) {
        int gm = m0 + lrow;
        if (gm < M) Arow = A + (size_t)(sl[gm] >> shiftA) * K;
        else { Arow = A; szA = 0; }
    } else {
        Arow = A + (size_t)(m0 + lrow) * K;
    }
    const bf16* Brow = B + (size_t)(n0 + lrow) * K;
    uint32_t dsw = (uint32_t)lrow * 128u;
    int rxor = lrow & 7;

    float acc[4][4][4];
    #pragma unroll
    for (int i = 0; i < 4; i++)
        #pragma unroll
        for (int j = 0; j < 4; j++)
            #pragma unroll
            for (int q = 0; q < 4; q++) acc[i][j][q] = 0.f;

    int CC = K / 64;
    auto loadChunk = [&](int c) {
        int s = c % 3;
        const char* pa = (const char*)(Arow + c*64);
        const char* pb = (const char*)(Brow + c*64);
        #pragma unroll
        for (int i = 0; i < 4; i++) {
            int seg = lsg + i;
            uint32_t o = dsw + (uint32_t)((seg ^ rxor) * 16);
            cpa(aoff[s] + o, pa + seg*16, szA);
            cpa(boff[s] + o, pb + seg*16, 16);
        }
        asm volatile("cp.async.commit_group;" ::: "memory");
    };
    loadChunk(0);
    if (CC > 1) loadChunk(1);

    int lt = lane >> 3;
    int rl = lane & 7;
    int th = (lt & 1) * 8;
    int ts = lane >> 4;

    for (int c = 0; c < CC; c++) {
        if (c + 1 < CC) asm volatile("cp.async.wait_group 1;" ::: "memory");
        else            asm volatile("cp.async.wait_group 0;" ::: "memory");
        __syncthreads();
        if (c + 2 < CC) loadChunk(c + 2);

        uint32_t Ab = aoff[c % 3], Bb = boff[c % 3];
        #pragma unroll
        for (int kk = 0; kk < 4; kk++) {
            uint32_t af[4][4], bfm[2][4];
            #pragma unroll
            for (int i = 0; i < 4; i++) {
                int row = wm + i*16 + th + rl;
                int seg = 2*kk + ts;
                ldsm4(af[i], Ab + row*128 + ((seg ^ (row & 7)) << 4));
            }
            #pragma unroll
            for (int j = 0; j < 2; j++) {
                int nr = wn + j*16 + th + rl;
                int seg = 2*kk + ts;
                ldsm4(bfm[j], Bb + nr*128 + ((seg ^ (nr & 7)) << 4));
            }
            #pragma unroll
            for (int i = 0; i < 4; i++)
                #pragma unroll
                for (int jn = 0; jn < 4; jn++) {
                    int jj = jn >> 1, hi = jn & 1;
                    mma_bf16(acc[i][jn], af[i][0], af[i][1], af[i][2], af[i][3],
                             bfm[jj][hi], bfm[jj][hi+2]);
                }
        }
    }

    int g = lane >> 2, tg = lane & 3;
    #pragma unroll
    for (int i = 0; i < 4; i++) {
        int r0 = m0 + wm + i*16 + g;
        int r1 = r0 + 8;
        bool v0, v1;
        int row0, row1;
        if (GATHER) {
            v0 = r0 < M; v1 = r1 < M;
            row0 = v0 ? sl[r0] : 0;
            row1 = v1 ? sl[r1] : 0;
        } else {
            v0 = v1 = true; row0 = r0; row1 = r1;
        }
        #pragma unroll
        for (int j = 0; j < 4; j++) {
            int c0 = n0 + wn + j*8 + tg*2;
            if (v0) {
                float2 v; v.x = acc[i][j][0]; v.y = acc[i][j][1];
                if (resid) {
                    v.x += resid[(size_t)row0*N + c0];
                    v.y += resid[(size_t)row0*N + c0 + 1];
                }
                *(float2*)(C + (size_t)row0*N + c0) = v;
            }
            if (v1) {
                float2 v; v.x = acc[i][j][2]; v.y = acc[i][j][3];
                if (resid) {
                    v.x += resid[(size_t)row1*N + c0];
                    v.y += resid[(size_t)row1*N + c0 + 1];
                }
                *(float2*)(C + (size_t)row1*N + c0) = v;
            }
        }
    }
}

// ---------------- QKV GEMM with fused RoPE/split epilogue -------------------
__device__ __forceinline__ void rope_write(
    int t, int c0, float vx, float vy, const float* __restrict__ freqs)
{
    if (c0 < DM) {
        int h = c0 >> 6, d = c0 & 63, p = d >> 1;
        float cs = freqs[((size_t)t*32 + p)*2 + 0];
        float sn = freqs[((size_t)t*32 + p)*2 + 1];
        float2 o;
        o.x = __uint_as_float(f2tf32((vx*cs - vy*sn) * 0.125f));
        o.y = __uint_as_float(f2tf32((vy*cs + vx*sn) * 0.125f));
        *(float2*)(g_q + ((size_t)h*SEQ + t)*HDIM + d) = o;
    } else if (c0 < DM + NKV*HDIM) {
        int c = c0 - DM;
        int kh = c >> 6, d = c & 63, p = d >> 1;
        float cs = freqs[((size_t)t*32 + p)*2 + 0];
        float sn = freqs[((size_t)t*32 + p)*2 + 1];
        float2 o;
        o.x = __uint_as_float(f2tf32(vx*cs - vy*sn));
        o.y = __uint_as_float(f2tf32(vy*cs + vx*sn));
        *(float2*)(g_k + ((size_t)kh*SEQ + t)*HDIM + d) = o;
    } else {
        int c = c0 - DM - NKV*HDIM;
        int vh = c >> 6, d = c & 63;
        g_vt[((size_t)(vh*HDIM + d  ))*SEQ + t] = __float2bfloat16(vx);
        g_vt[((size_t)(vh*HDIM + d+1))*SEQ + t] = __float2bfloat16(vy);
    }
}

__global__ __launch_bounds__(256) void gemm_qkv(
    const bf16* __restrict__ A, const bf16* __restrict__ B,
    const float* __restrict__ freqs)
{
    extern __shared__ char smem[];
    const int K = DM;
    int m0 = blockIdx.y * 128, n0 = blockIdx.x * 128;
    int tid = threadIdx.x, warp = tid >> 5, lane = tid & 31;
    int wm = (warp >> 2) * 64, wn = (warp & 3) * 32;
    uint32_t sbase = (uint32_t)__cvta_generic_to_shared(smem);
    uint32_t aoff[3], boff[3];
    #pragma unroll
    for (int s = 0; s < 3; s++) {
        aoff[s] = sbase + s*GSTG;
        boff[s] = sbase + 3*GSTG + s*GSTG;
    }

    int lrow = tid >> 1;
    int lsg  = (tid & 1) * 4;
    const bf16* Arow = A + (size_t)(m0 + lrow) * K;
    const bf16* Brow = B + (size_t)(n0 + lrow) * K;
    uint32_t dsw = (uint32_t)lrow * 128u;
    int rxor = lrow & 7;

    float acc[4][4][4];
    #pragma unroll
    for (int i = 0; i < 4; i++)
        #pragma unroll
        for (int j = 0; j < 4; j++)
            #pragma unroll
            for (int q = 0; q < 4; q++) acc[i][j][q] = 0.f;

    const int CC = K / 64;
    auto loadChunk = [&](int c) {
        int s = c % 3;
        const char* pa = (const char*)(Arow + c*64);
        const char* pb = (const char*)(Brow + c*64);
        #pragma unroll
        for (int i = 0; i < 4; i++) {
            int seg = lsg + i;
            uint32_t o = dsw + (uint32_t)((seg ^ rxor) * 16);
            cpa(aoff[s] + o, pa + seg*16, 16);
            cpa(boff[s] + o, pb + seg*16, 16);
        }
        asm volatile("cp.async.commit_group;" ::: "memory");
    };
    loadChunk(0);
    loadChunk(1);

    int lt = lane >> 3;
    int rl = lane & 7;
    int th = (lt & 1) * 8;
    int ts = lane >> 4;

    for (int c = 0; c < CC; c++) {
        if (c + 1 < CC) asm volatile("cp.async.wait_group 1;" ::: "memory");
        else            asm volatile("cp.async.wait_group 0;" ::: "memory");
        __syncthreads();
        if (c + 2 < CC) loadChunk(c + 2);

        uint32_t Ab = aoff[c % 3], Bb = boff[c % 3];
        #pragma unroll
        for (int kk = 0; kk < 4; kk++) {
            uint32_t af[4][4], bfm[2][4];
            #pragma unroll
            for (int i = 0; i < 4; i++) {
                int row = wm + i*16 + th + rl;
                int seg = 2*kk + ts;
                ldsm4(af[i], Ab + row*128 + ((seg ^ (row & 7)) << 4));
            }
            #pragma unroll
            for (int j = 0; j < 2; j++) {
                int nr = wn + j*16 + th + rl;
                int seg = 2*kk + ts;
                ldsm4(bfm[j], Bb + nr*128 + ((seg ^ (nr & 7)) << 4));
            }
            #pragma unroll
            for (int i = 0; i < 4; i++)
                #pragma unroll
                for (int jn = 0; jn < 4; jn++) {
                    int jj = jn >> 1, hi = jn & 1;
                    mma_bf16(acc[i][jn], af[i][0], af[i][1], af[i][2], af[i][3],
                             bfm[jj][hi], bfm[jj][hi+2]);
                }
        }
    }

    int g = lane >> 2, tg = lane & 3;
    #pragma unroll
    for (int i = 0; i < 4; i++) {
        int t0 = m0 + wm + i*16 + g;
        int t1 = t0 + 8;
        #pragma unroll
        for (int j = 0; j < 4; j++) {
            int c0 = n0 + wn + j*8 + tg*2;
            rope_write(t0, c0, acc[i][j][0], acc[i][j][1], freqs);
            rope_write(t1, c0, acc[i][j][2], acc[i][j][3], freqs);
        }
    }
}

// ---------------- fused MoE w1/w3 GEMM + silu*mul (bf16 out) ---------------
__global__ __launch_bounds__(256) void gemm_w13(
    const bf16* __restrict__ A, const bf16* __restrict__ B1,
    const bf16* __restrict__ B3)
{
    extern __shared__ char smem[];
    int e = blockIdx.z;
    int M = g_cnt[e];
    if ((int)blockIdx.y * 128 >= M) return;
    const int* sl = g_slot + e * SEQ;
    B1 += (size_t)e * NI * DM;
    B3 += (size_t)e * NI * DM;

    int m0 = blockIdx.y * 128, n0 = blockIdx.x * 128;
    int tid = threadIdx.x, warp = tid >> 5, lane = tid & 31;
    int wm = (warp >> 2) * 64, wn = (warp & 3) * 32;
    uint32_t sbase = (uint32_t)__cvta_generic_to_shared(smem);
    uint32_t aoff[2], b1off[2], b3off[2];
    #pragma unroll
    for (int s = 0; s < 2; s++) {
        aoff[s]  = sbase + s*GSTG;
        b1off[s] = sbase + 2*GSTG + s*GSTG;
        b3off[s] = sbase + 4*GSTG + s*GSTG;
    }

    int lrow = tid >> 1;
    int lsg  = (tid & 1) * 4;
    const bf16* Arow; int szA = 16;
    {
        int gm = m0 + lrow;
        if (gm < M) Arow = A + (size_t)(sl[gm] >> 1) * DM;
        else { Arow = A; szA = 0; }
    }
    const bf16* B1row = B1 + (size_t)(n0 + lrow) * DM;
    const bf16* B3row = B3 + (size_t)(n0 + lrow) * DM;
    uint32_t dsw = (uint32_t)lrow * 128u;
    int rxor = lrow & 7;

    float ac1[4][4][4], ac3[4][4][4];
    #pragma unroll
    for (int i = 0; i < 4; i++)
        #pragma unroll
        for (int j = 0; j < 4; j++)
            #pragma unroll
            for (int q = 0; q < 4; q++) { ac1[i][j][q] = 0.f; ac3[i][j][q] = 0.f; }

    const int CC = DM / 64;
    auto loadChunk = [&](int c) {
        int s = c & 1;
        const char* pa  = (const char*)(Arow  + c*64);
        const char* pb1 = (const char*)(B1row + c*64);
        const char* pb3 = (const char*)(B3row + c*64);
        #pragma unroll
        for (int i = 0; i < 4; i++) {
            int seg = lsg + i;
            uint32_t o = dsw + (uint32_t)((seg ^ rxor) * 16);
            cpa(aoff[s]  + o, pa  + seg*16, szA);
            cpa(b1off[s] + o, pb1 + seg*16, 16);
            cpa(b3off[s] + o, pb3 + seg*16, 16);
        }
        asm volatile("cp.async.commit_group;" ::: "memory");
    };
    loadChunk(0);

    int lt = lane >> 3, rl = lane & 7;
    int th = (lt & 1) * 8;
    int ts = lane >> 4;

    for (int c = 0; c < CC; c++) {
        asm volatile("cp.async.wait_group 0;" ::: "memory");
        __syncthreads();
        if (c + 1 < CC) loadChunk(c + 1);

        uint32_t Ab = aoff[c & 1], B1b = b1off[c & 1], B3b = b3off[c & 1];
        #pragma unroll
        for (int kk = 0; kk < 4; kk++) {
            uint32_t af[4][4], f1[2][4], f3[2][4];
            #pragma unroll
            for (int i = 0; i < 4; i++) {
                int row = wm + i*16 + th + rl;
                int seg = 2*kk + ts;
                ldsm4(af[i], Ab + row*128 + ((seg ^ (row & 7)) << 4));
            }
            #pragma unroll
            for (int j = 0; j < 2; j++) {
                int nr = wn + j*16 + th + rl;
                int seg = 2*kk + ts;
                ldsm4(f1[j], B1b + nr*128 + ((seg ^ (nr & 7)) << 4));
                ldsm4(f3[j], B3b + nr*128 + ((seg ^ (nr & 7)) << 4));
            }
            #pragma unroll
            for (int i = 0; i < 4; i++)
                #pragma unroll
                for (int jn = 0; jn < 4; jn++) {
                    int jj = jn >> 1, hi = jn & 1;
                    mma_bf16(ac1[i][jn], af[i][0], af[i][1], af[i][2], af[i][3],
                             f1[jj][hi], f1[jj][hi+2]);
                    mma_bf16(ac3[i][jn], af[i][0], af[i][1], af[i][2], af[i][3],
                             f3[jj][hi], f3[jj][hi+2]);
                }
        }
    }

    int g = lane >> 2, tg = lane & 3;
    #pragma unroll
    for (int i = 0; i < 4; i++) {
        int r0 = m0 + wm + i*16 + g;
        int r1 = r0 + 8;
        bool v0 = r0 < M, v1 = r1 < M;
        int row0 = v0 ? sl[r0] : 0;
        int row1 = v1 ? sl[r1] : 0;
        #pragma unroll
        for (int j = 0; j < 4; j++) {
            int c0 = n0 + wn + j*8 + tg*2;
            if (v0) {
                float a0 = ac1[i][j][0], a1 = ac1[i][j][1];
                float u0 = a0 / (1.f + __expf(-a0)) * ac3[i][j][0];
                float u1 = a1 / (1.f + __expf(-a1)) * ac3[i][j][1];
                *(__nv_bfloat162*)(g_gb + (size_t)row0*NI + c0) = __floats2bfloat162_rn(u0, u1);
            }
            if (v1) {
                float a0 = ac1[i][j][2], a1 = ac1[i][j][3];
                float u0 = a0 / (1.f + __expf(-a0)) * ac3[i][j][2];
                float u1 = a1 / (1.f + __expf(-a1)) * ac3[i][j][3];
                *(__nv_bfloat162*)(g_gb + (size_t)row1*NI + c0) = __floats2bfloat162_rn(u0, u1);
            }
        }
    }
}

// ---------------- attention v7: uniform-chunk split flash -------------------
// Empty chunks (lo>=hi) exit WITHOUT writing partials; reduce folds only
// the nch = ceil((qt+1)/CHUNK) live chunks per row (bit-identical merge).
#define ASTR 68
#define VSTR 72
__global__ __launch_bounds__(128) void attn6_kernel()
{
    __shared__ float Ks[64*ASTR];
    __shared__ bf16  Vt[64*VSTR];

    int qt = blockIdx.x, h = blockIdx.y, z = blockIdx.z;
    int kvh = h >> 2;
    int tid = threadIdx.x, warp = tid >> 5, lane = tid & 31;
    int g = lane >> 2, tg = lane & 3;
    int wq = warp * 16;
    int q0 = qt * 64;

    int n = qt + 1;
    int lo = z * CHUNK;
    int hi = min(n, lo + CHUNK);
    if (lo >= hi) return;   // empty chunk: no partial writes

    float oc[8][4];
    #pragma unroll
    for (int j = 0; j < 8; j++)
        #pragma unroll
        for (int q = 0; q < 4; q++) oc[j][q] = 0.f;
    float mrow[2] = {-1e30f, -1e30f};
    float lrow[2] = {0.f, 0.f};

    for (int i = tid; i < 64*16; i += 128) {
        int row = i >> 4, c4 = (i & 15) * 4;
        *(float4*)&Ks[row*ASTR + c4] =
            *(const float4*)(g_q + ((size_t)h*SEQ + q0 + row)*HDIM + c4);
    }
    __syncthreads();
    uint32_t aq[8][4];
    #pragma unroll
    for (int kk = 0; kk < 8; kk++) {
        aq[kk][0] = __float_as_uint(Ks[(wq+g)*ASTR + kk*8 + tg]);
        aq[kk][1] = __float_as_uint(Ks[(wq+g+8)*ASTR + kk*8 + tg]);
        aq[kk][2] = __float_as_uint(Ks[(wq+g)*ASTR + kk*8 + tg + 4]);
        aq[kk][3] = __float_as_uint(Ks[(wq+g+8)*ASTR + kk*8 + tg + 4]);
    }
    __syncthreads();

    for (int kt = lo; kt < hi; kt++) {
        for (int i = tid; i < 1024; i += 128) {
            int row = i >> 4, c4 = (i & 15) * 4;
            *(float4*)&Ks[row*ASTR + c4] =
                *(const float4*)(g_k + ((size_t)kvh*SEQ + kt*64 + row)*HDIM + c4);
        }
        for (int i = tid; i < 512; i += 128) {
            int row = i >> 3, seg = i & 7;
            *(uint4*)&Vt[row*VSTR + seg*8] =
                *(const uint4*)(g_vt + ((size_t)(kvh*HDIM + row))*SEQ + kt*64 + seg*8);
        }
        __syncthreads();

        float sc[8][4];
        #pragma unroll
        for (int j = 0; j < 8; j++)
            #pragma unroll
            for (int q = 0; q < 4; q++) sc[j][q] = 0.f;
        #pragma unroll
        for (int kk = 0; kk < 8; kk++) {
            #pragma unroll
            for (int j = 0; j < 8; j++) {
                uint32_t b0 = __float_as_uint(Ks[(j*8+g)*ASTR + kk*8 + tg]);
                uint32_t b1 = __float_as_uint(Ks[(j*8+g)*ASTR + kk*8 + tg + 4]);
                mma_tf32(sc[j], aq[kk][0], aq[kk][1], aq[kk][2], aq[kk][3], b0, b1);
            }
        }

        if (kt == qt) {
            int r0g = q0 + wq + g, r1g = r0g + 8;
            #pragma unroll
            for (int j = 0; j < 8; j++) {
                int c0 = kt*64 + j*8 + tg*2;
                if (c0     > r0g) sc[j][0] = -1e30f;
                if (c0 + 1 > r0g) sc[j][1] = -1e30f;
                if (c0     > r1g) sc[j][2] = -1e30f;
                if (c0 + 1 > r1g) sc[j][3] = -1e30f;
            }
        }

        float mx0 = -1e30f, mx1 = -1e30f;
        #pragma unroll
        for (int j = 0; j < 8; j++) {
            mx0 = fmaxf(mx0, fmaxf(sc[j][0], sc[j][1]));
            mx1 = fmaxf(mx1, fmaxf(sc[j][2], sc[j][3]));
        }
        mx0 = fmaxf(mx0, __shfl_xor_sync(0xffffffffu, mx0, 1));
        mx0 = fmaxf(mx0, __shfl_xor_sync(0xffffffffu, mx0, 2));
        mx1 = fmaxf(mx1, __shfl_xor_sync(0xffffffffu, mx1, 1));
        mx1 = fmaxf(mx1, __shfl_xor_sync(0xffffffffu, mx1, 2));
        float mn0 = fmaxf(mrow[0], mx0), mn1 = fmaxf(mrow[1], mx1);
        float s0 = __expf(mrow[0] - mn0), s1 = __expf(mrow[1] - mn1);
        float ls0 = 0.f, ls1 = 0.f;
        #pragma unroll
        for (int j = 0; j < 8; j++) {
            sc[j][0] = __expf(sc[j][0] - mn0);
            sc[j][1] = __expf(sc[j][1] - mn0);
            sc[j][2] = __expf(sc[j][2] - mn1);
            sc[j][3] = __expf(sc[j][3] - mn1);
            ls0 += sc[j][0] + sc[j][1];
            ls1 += sc[j][2] + sc[j][3];
        }
        ls0 += __shfl_xor_sync(0xffffffffu, ls0, 1);
        ls0 += __shfl_xor_sync(0xffffffffu, ls0, 2);
        ls1 += __shfl_xor_sync(0xffffffffu, ls1, 1);
        ls1 += __shfl_xor_sync(0xffffffffu, ls1, 2);
        lrow[0] = lrow[0]*s0 + ls0;
        lrow[1] = lrow[1]*s1 + ls1;
        mrow[0] = mn0; mrow[1] = mn1;
        #pragma unroll
        for (int j = 0; j < 8; j++) {
            oc[j][0] *= s0; oc[j][1] *= s0;
            oc[j][2] *= s1; oc[j][3] *= s1;
        }

        uint32_t pa[4][4];
        #pragma unroll
        for (int kk = 0; kk < 4; kk++) {
            pa[kk][0] = packbf(sc[2*kk][0],   sc[2*kk][1]);
            pa[kk][1] = packbf(sc[2*kk][2],   sc[2*kk][3]);
            pa[kk][2] = packbf(sc[2*kk+1][0], sc[2*kk+1][1]);
            pa[kk][3] = packbf(sc[2*kk+1][2], sc[2*kk+1][3]);
        }
        #pragma unroll
        for (int kk = 0; kk < 4; kk++) {
            #pragma unroll
            for (int j = 0; j < 8; j++) {
                uint32_t b0 = *(const uint32_t*)&Vt[(j*8+g)*VSTR + kk*16 + tg*2];
                uint32_t b1 = *(const uint32_t*)&Vt[(j*8+g)*VSTR + kk*16 + tg*2 + 8];
                mma_bf16(oc[j], pa[kk][0], pa[kk][1], pa[kk][2], pa[kk][3], b0, b1);
            }
        }
        __syncthreads();
    }

    size_t pb = (size_t)z * NH * SEQ;
    int r0 = q0 + wq + g, r1 = r0 + 8;
    size_t hr0 = (size_t)h*SEQ + r0, hr1 = (size_t)h*SEQ + r1;
    #pragma unroll
    for (int j = 0; j < 8; j++) {
        int c0 = j*8 + tg*2;
        float2 v0; v0.x = oc[j][0]; v0.y = oc[j][1];
        float2 v1; v1.x = oc[j][2]; v1.y = oc[j][3];
        *(float2*)&g_po[(pb + hr0)*HDIM + c0] = v0;
        *(float2*)&g_po[(pb + hr1)*HDIM + c0] = v1;
    }
    if (tg == 0) {
        g_pm[pb + hr0] = mrow[0];
        g_pm[pb + hr1] = mrow[1];
        g_pl[pb + hr0] = lrow[0];
        g_pl[pb + hr1] = lrow[1];
    }
}

// ---------------- split reduce: fold only live chunks -> y_bf ---------------
__global__ void attn_reduce_kernel()
{
    int i = blockIdx.x * blockDim.x + threadIdx.x;
    if (i >= NH*SEQ*(HDIM/2)) return;
    int hrow = i >> 5;
    int c2 = (i & 31) * 2;
    int h = hrow / SEQ, row = hrow % SEQ;
    int qt = row >> 6;
    int nch = (qt + 1 + CHUNK - 1) / CHUNK;   // live chunks for this row
    float M = -1e30f;
    float ms[NSPLIT], ls[NSPLIT];
    for (int s = 0; s < nch; s++) {
        ms[s] = g_pm[s*NH*SEQ + hrow];
        ls[s] = g_pl[s*NH*SEQ + hrow];
        M = fmaxf(M, ms[s]);
    }
    float den = 0.f, vx = 0.f, vy = 0.f;
    for (int s = 0; s < nch; s++) {
        float w = __expf(ms[s] - M);
        den += ls[s] * w;
        float2 o = *(const float2*)&g_po[((size_t)s*NH*SEQ + hrow)*HDIM + c2];
        vx += o.x * w;
        vy += o.y * w;
    }
    float inv = 1.f / den;
    *(__nv_bfloat162*)(g_y_bf + (size_t)row*DM + h*HDIM + c2) =
        __floats2bfloat162_rn(vx*inv, vy*inv);
}

// ---------------- final combine ---------------------------------------------
__global__ __launch_bounds__(256) void combine_kernel(float* __restrict__ out)
{
    int t = blockIdx.x;
    int tid = threadIdx.x;
    float w0 = g_wslot[2*t], w1 = g_wslot[2*t+1];
    float4 hv = ((const float4*)(g_h + (size_t)t*DM))[tid];
    float4 a = ((const float4*)(g_os + (size_t)(2*t)*DM))[tid];
    float4 b = ((const float4*)(g_os + (size_t)(2*t+1)*DM))[tid];
    float4 o;
    o.x = hv.x + w0*a.x + w1*b.x;
    o.y = hv.y + w0*a.y + w1*b.y;
    o.z = hv.z + w0*a.z + w1*b.z;
    o.w = hv.w + w0*a.w + w1*b.w;
    ((float4*)(out + (size_t)t*DM))[tid] = o;
}

// ---------------- host launch ----------------------------------------------
#define GEMM_SMEM (6*GSTG)
#define W13_SMEM  (6*GSTG)

extern "C" void kernel_launch(void* const* d_in, const int* in_sizes, int n_in,
                              void* d_out, int out_size)
{
    const float* x      = (const float*)d_in[0];
    const float* wqkv   = (const float*)d_in[1];
    const float* wo     = (const float*)d_in[2];
    const float* gate_w = (const float*)d_in[3];
    const float* w1     = (const float*)d_in[4];
    const float* w2     = (const float*)d_in[5];
    const float* w3     = (const float*)d_in[6];
    const float* anw    = (const float*)d_in[7];
    const float* fnw    = (const float*)d_in[8];
    const float* freqs  = (const float*)d_in[9];
    float* out = (float*)d_out;

    bf16 *p_wqkv_bf, *p_wo_bf, *p_w1_bf, *p_w3_bf, *p_w2_bf;
    bf16 *p_hn_bf, *p_hf_bf, *p_y_bf, *p_gb;
    float *p_h, *p_os;
    int *p_cnt;
    cudaGetSymbolAddress((void**)&p_wqkv_bf, g_wqkv_bf);
    cudaGetSymbolAddress((void**)&p_wo_bf,   g_wo_bf);
    cudaGetSymbolAddress((void**)&p_w1_bf,   g_w1_bf);
    cudaGetSymbolAddress((void**)&p_w3_bf,   g_w3_bf);
    cudaGetSymbolAddress((void**)&p_w2_bf,   g_w2_bf);
    cudaGetSymbolAddress((void**)&p_hn_bf,   g_hn_bf);
    cudaGetSymbolAddress((void**)&p_hf_bf,   g_hf_bf);
    cudaGetSymbolAddress((void**)&p_y_bf,    g_y_bf);
    cudaGetSymbolAddress((void**)&p_gb,      g_gb);
    cudaGetSymbolAddress((void**)&p_h,       g_h);
    cudaGetSymbolAddress((void**)&p_os,      g_os);
    cudaGetSymbolAddress((void**)&p_cnt,     g_cnt);

    static cudaStream_t s2 = nullptr;
    static cudaEvent_t ev0 = nullptr, ev1 = nullptr;
    static bool attr_set = false;
    if (!attr_set) {
        cudaFuncSetAttribute(gemm_bf<false>,
            cudaFuncAttributeMaxDynamicSharedMemorySize, GEMM_SMEM);
        cudaFuncSetAttribute(gemm_bf<true>,
            cudaFuncAttributeMaxDynamicSharedMemorySize, GEMM_SMEM);
        cudaFuncSetAttribute(gemm_qkv,
            cudaFuncAttributeMaxDynamicSharedMemorySize, GEMM_SMEM);
        cudaFuncSetAttribute(gemm_w13,
            cudaFuncAttributeMaxDynamicSharedMemorySize, W13_SMEM);
        cudaStreamCreateWithFlags(&s2, cudaStreamNonBlocking);
        cudaEventCreateWithFlags(&ev0, cudaEventDisableTiming);
        cudaEventCreateWithFlags(&ev1, cudaEventDisableTiming);
        attr_set = true;
    }

    // (1) wqkv convert (main)
    {
        int n4 = QKVN*DM/4;
        f2bf_kernel<<<(n4+255)/256, 256>>>((const float4*)wqkv, (uint2*)p_wqkv_bf, n4);
    }
    // (2,3) fork first two big MoE converts on side stream
    cudaEventRecord(ev0, 0);
    cudaStreamWaitEvent(s2, ev0, 0);
    {
        int n4 = (int)((size_t)NE*NI*DM/4);
        f2bf_kernel<<<(n4+255)/256, 256, 0, s2>>>((const float4*)w1, (uint2*)p_w1_bf, n4);
        f2bf_kernel<<<(n4+255)/256, 256, 0, s2>>>((const float4*)w3, (uint2*)p_w3_bf, n4);
    }
    // (4) attn rmsnorm
    rmsnorm_kernel<<<SEQ, 256>>>(x, anw, p_hn_bf);
    // (5) qkv GEMM + fused RoPE
    gemm_qkv<<<dim3(QKVN/128, SEQ/128), 256, GEMM_SMEM>>>(p_hn_bf, p_wqkv_bf, freqs);
    // (6) attention v7 (live chunks only)
    attn6_kernel<<<dim3(SEQ/64, NH, NSPLIT), 128>>>();
    // (7+) rest
    {
        int n4 = (int)((size_t)NE*NI*DM/4);
        f2bf_kernel<<<(n4+255)/256, 256, 0, s2>>>((const float4*)w2, (uint2*)p_w2_bf, n4);
    }
    cudaEventRecord(ev1, s2);
    {
        int n4 = DM*DM/4;
        f2bf_kernel<<<(n4+255)/256, 256>>>((const float4*)wo, (uint2*)p_wo_bf, n4);
    }
    attn_reduce_kernel<<<(NH*SEQ*(HDIM/2) + 255)/256, 256>>>();
    gemm_bf<false><<<dim3(DM/128, SEQ/128), 256, GEMM_SMEM>>>(
        p_y_bf, p_wo_bf, x, p_h, SEQ, DM, DM, 0);
    // fused ffn rmsnorm + gating (cnt cleared first)
    cudaMemsetAsync(p_cnt, 0, NE*sizeof(int), 0);
    rmsnorm_gate_kernel<<<SEQ, 256>>>(p_h, fnw, gate_w, p_hf_bf);

    cudaStreamWaitEvent(0, ev1, 0);
    gemm_w13<<<dim3(NI/128, SEQ/128, NE), 256, W13_SMEM>>>(
        p_hf_bf, p_w1_bf, p_w3_bf);
    gemm_bf<true><<<dim3(DM/128, SEQ/128, NE), 256, GEMM_SMEM>>>(
        p_gb, p_w2_bf, nullptr, p_os, 0, DM, NI, 0);
    combine_kernel<<<SEQ, 256>>>(out);
}